// round 2
// baseline (speedup 1.0000x reference)
#include <cuda_runtime.h>
#include <math.h>

#define LQ      1024
#define BATCH   2
#define DMODEL  1024
#define NH      16
#define DHD     64
#define MEMLEN  1024
#define TT      2048            // T = L + M
#define NG      (BATCH*NH)      // 32 batched heads
#define SCALE_F 0.125f          // 1/sqrt(64)
#define NEGBIG  -1e30f

// ---------------- scratch (device globals; no allocation allowed) -------------
__device__ float g_q [NG*LQ*DHD];                    //  8 MB  [b][h][i][d]
__device__ float g_k [NG*TT*DHD];                    // 16 MB  [b][h][t][d]
__device__ float g_v [NG*TT*DHD];                    // 16 MB
__device__ float g_r [NG*TT*DHD];                    // 16 MB
__device__ float g_s [(size_t)NG*LQ*TT];             // 256 MB scores -> probs
__device__ float g_bd[(size_t)NG*LQ*TT];             // 256 MB BD (pre-shift)
__device__ float g_av[LQ*BATCH*NH*DHD];              //  8 MB  [(i*B+b)][h*64+d]
__device__ float g_h [LQ*BATCH*DMODEL];              //  8 MB  pre-LN residual

// ---------------- reductions ----------------
__device__ __forceinline__ float warpSum(float v){
    #pragma unroll
    for (int o=16;o>0;o>>=1) v += __shfl_xor_sync(0xffffffffu, v, o);
    return v;
}
__device__ __forceinline__ float blockSum(float v){
    __shared__ float sm[32];
    int lane = threadIdx.x & 31, w = threadIdx.x >> 5;
    v = warpSum(v);
    if (lane==0) sm[w] = v;
    __syncthreads();
    float r = (threadIdx.x < 8) ? sm[threadIdx.x] : 0.f;
    if (w==0){
        #pragma unroll
        for (int o=4;o>0;o>>=1) r += __shfl_xor_sync(0xffffffffu, r, o);
        if (lane==0) sm[0]=r;
    }
    __syncthreads();
    r = sm[0];
    __syncthreads();
    return r;
}
__device__ __forceinline__ float blockMax(float v){
    __shared__ float sm[32];
    int lane = threadIdx.x & 31, w = threadIdx.x >> 5;
    #pragma unroll
    for (int o=16;o>0;o>>=1) v = fmaxf(v, __shfl_xor_sync(0xffffffffu, v, o));
    if (lane==0) sm[w] = v;
    __syncthreads();
    float r = (threadIdx.x < 8) ? sm[threadIdx.x] : -3.4e38f;
    if (w==0){
        #pragma unroll
        for (int o=4;o>0;o>>=1) r = fmaxf(r, __shfl_xor_sync(0xffffffffu, r, o));
        if (lane==0) sm[0]=r;
    }
    __syncthreads();
    r = sm[0];
    __syncthreads();
    return r;
}

// ---------------- projection GEMM: C[rows, N] = A[rows,1024] @ W[1024,N] ------
// MODE 0: A=x (row=i*B+b), N=1024 -> g_q[b][h][i][d]
// MODE 1: A=concat(memory,x) (row=t*B+b), N=2048 -> g_k / g_v
// MODE 2: A=pos_emb, N=1024 -> g_r
// MODE 3: A=g_av (row=i*B+b), W=Wo, N=1024 -> g_h = x + A@Wo
template<int MODE, int N>
__global__ __launch_bounds__(256) void proj_gemm(const float* __restrict__ A0,
                                                 const float* __restrict__ A1,
                                                 const float* __restrict__ W)
{
    constexpr int BM=128, BN=128, BK=8;
    const int m0 = blockIdx.y * BM;
    const int n0 = blockIdx.x * BN;
    __shared__ float As[BK][BM];
    __shared__ float Ws[BK][BN];
    const int tid = threadIdx.x;
    const int a_r = tid >> 1;            // 0..127
    const int a_c = (tid & 1) * 4;       // 0 / 4
    const int w_r = tid >> 5;            // 0..7
    const int w_c = (tid & 31) * 4;
    const int tx = tid & 15, ty = tid >> 4;

    float acc[8][8];
    #pragma unroll
    for (int m=0;m<8;m++)
        #pragma unroll
        for (int n=0;n<8;n++) acc[m][n]=0.f;

    const int grow = m0 + a_r;
    const float* arow;
    if (MODE==1) arow = (grow < MEMLEN*BATCH) ? (A0 + (size_t)grow*DMODEL)
                                              : (A1 + (size_t)(grow - MEMLEN*BATCH)*DMODEL);
    else if (MODE==3) arow = g_av + (size_t)grow*DMODEL;
    else              arow = A0 + (size_t)grow*DMODEL;

    for (int k0=0;k0<DMODEL;k0+=BK){
        float4 av = *(const float4*)(arow + k0 + a_c);
        As[a_c+0][a_r]=av.x; As[a_c+1][a_r]=av.y; As[a_c+2][a_r]=av.z; As[a_c+3][a_r]=av.w;
        float4 wv = *(const float4*)(W + (size_t)(k0+w_r)*N + n0 + w_c);
        *(float4*)&Ws[w_r][w_c] = wv;
        __syncthreads();
        #pragma unroll
        for (int kk=0;kk<BK;kk++){
            float4 a0v = *(const float4*)&As[kk][ty*8];
            float4 a1v = *(const float4*)&As[kk][ty*8+4];
            float4 b0v = *(const float4*)&Ws[kk][tx*8];
            float4 b1v = *(const float4*)&Ws[kk][tx*8+4];
            float a[8] = {a0v.x,a0v.y,a0v.z,a0v.w,a1v.x,a1v.y,a1v.z,a1v.w};
            float b[8] = {b0v.x,b0v.y,b0v.z,b0v.w,b1v.x,b1v.y,b1v.z,b1v.w};
            #pragma unroll
            for (int m=0;m<8;m++)
                #pragma unroll
                for (int n=0;n<8;n++)
                    acc[m][n] = fmaf(a[m], b[n], acc[m][n]);
        }
        __syncthreads();
    }

    #pragma unroll
    for (int m=0;m<8;m++){
        const int row = m0 + ty*8 + m;
        #pragma unroll
        for (int n=0;n<8;n++){
            const int col = n0 + tx*8 + n;
            const float val = acc[m][n];
            if (MODE==0){
                int i = row / BATCH, b = row % BATCH;
                int h = col >> 6, d = col & 63;
                g_q[(((size_t)(b*NH+h)*LQ + i)<<6) + d] = val;
            } else if (MODE==1){
                int t = row / BATCH, b = row % BATCH;
                int c = col; float* dst = g_k;
                if (c >= NH*DHD){ dst = g_v; c -= NH*DHD; }
                int h = c >> 6, d = c & 63;
                dst[(((size_t)(b*NH+h)*TT + t)<<6) + d] = val;
            } else if (MODE==2){
                int t = row / BATCH, b = row % BATCH;
                int h = col >> 6, d = col & 63;
                g_r[(((size_t)(b*NH+h)*TT + t)<<6) + d] = val;
            } else {
                g_h[(size_t)row*DMODEL + col] = val + A1[(size_t)row*DMODEL + col];
            }
        }
    }
}

// ---------------- batched scores GEMM: S[g,i,j] = (q[g,i]+bias[h]) . K[g,j] ---
// WHICH 0: K=g_k -> g_s (AC term);  WHICH 1: K=g_r -> g_bd (BD term, pre-shift)
template<int WHICH>
__global__ __launch_bounds__(256) void scores_gemm(const float* __restrict__ bias)
{
    const float* Kk = WHICH ? g_r : g_k;
    float*       S  = WHICH ? g_bd : g_s;
    const int g  = blockIdx.z;
    const int h  = g % NH;
    const int i0 = blockIdx.y * 64;
    const int j0 = blockIdx.x * 64;
    __shared__ float Qs[64][65];
    __shared__ float Ks[64][65];
    const int tid = threadIdx.x;
    {
        const int r  = tid >> 2;
        const int c0 = (tid & 3) * 16;
        const float* qp = g_q + (((size_t)g*LQ + i0 + r) << 6) + c0;
        const float* bp = bias + (h << 6) + c0;
        const float* kp = Kk + (((size_t)g*TT + j0 + r) << 6) + c0;
        #pragma unroll
        for (int q4=0;q4<4;q4++){
            float4 qv = *(const float4*)(qp + q4*4);
            float4 bv = *(const float4*)(bp + q4*4);
            Qs[r][c0+q4*4+0]=qv.x+bv.x; Qs[r][c0+q4*4+1]=qv.y+bv.y;
            Qs[r][c0+q4*4+2]=qv.z+bv.z; Qs[r][c0+q4*4+3]=qv.w+bv.w;
            float4 kv = *(const float4*)(kp + q4*4);
            Ks[r][c0+q4*4+0]=kv.x; Ks[r][c0+q4*4+1]=kv.y;
            Ks[r][c0+q4*4+2]=kv.z; Ks[r][c0+q4*4+3]=kv.w;
        }
    }
    __syncthreads();
    const int tx = tid & 15, ty = tid >> 4;
    float acc[4][4];
    #pragma unroll
    for (int m=0;m<4;m++)
        #pragma unroll
        for (int n=0;n<4;n++) acc[m][n]=0.f;
    #pragma unroll
    for (int d=0; d<64; d++){
        float a[4], b[4];
        #pragma unroll
        for (int m=0;m<4;m++) a[m]=Qs[ty*4+m][d];
        #pragma unroll
        for (int n=0;n<4;n++) b[n]=Ks[tx*4+n][d];
        #pragma unroll
        for (int m=0;m<4;m++)
            #pragma unroll
            for (int n=0;n<4;n++)
                acc[m][n] = fmaf(a[m], b[n], acc[m][n]);
    }
    #pragma unroll
    for (int m=0;m<4;m++){
        float* srow = S + ((size_t)g*LQ + i0 + ty*4 + m)*TT + j0 + tx*4;
        #pragma unroll
        for (int n=0;n<4;n++) srow[n] = acc[m][n];
    }
}

// ---------------- softmax: in-place over g_s rows, reading shifted BD --------
__global__ __launch_bounds__(256) void softmax_kernel()
{
    const int idx = blockIdx.x;            // g*L + i
    const int i   = idx & (LQ-1);
    float* srow = g_s + (size_t)idx*TT;
    const float* bdrow = g_bd + (size_t)idx*TT;
    const int jmax = i + MEMLEN;
    const int tid = threadIdx.x;
    float vals[8];
    float mx = -3.4e38f;
    #pragma unroll
    for (int q=0;q<8;q++){
        int j = q*256 + tid;
        if (j <= jmax){
            float vv = (srow[j] + bdrow[j - i + LQ - 1]) * SCALE_F;
            vals[q] = vv;
            mx = fmaxf(mx, vv);
        } else vals[q] = NEGBIG;
    }
    mx = blockMax(mx);
    float s = 0.f;
    #pragma unroll
    for (int q=0;q<8;q++){
        float e = (vals[q] > -1e29f) ? __expf(vals[q]-mx) : 0.f;
        vals[q] = e; s += e;
    }
    s = blockSum(s);
    const float inv = 1.f / s;
    #pragma unroll
    for (int q=0;q<8;q++) srow[q*256 + tid] = vals[q] * inv;
}

// ---------------- attn_matrix = mean over (b,h) of probs ---------------------
__global__ __launch_bounds__(256) void attnmat_kernel(float* __restrict__ out)
{
    const size_t idx = (size_t)blockIdx.x*256 + threadIdx.x;   // over L*T
    float s = 0.f;
    #pragma unroll
    for (int g=0; g<NG; g++) s += g_s[(size_t)g*LQ*TT + idx];
    out[idx] = s * (1.f/NG);
}

// ---------------- PV: av[g,i,:] = P[g,i,:] @ V[g,:,:] ------------------------
__global__ __launch_bounds__(256) void pv_gemm()
{
    const int g  = blockIdx.y;
    const int i0 = blockIdx.x * 128;
    const int b  = g / NH, h = g % NH;
    __shared__ float Ps[32][132];
    __shared__ float Vs[32][68];
    const int tid = threadIdx.x;
    const int tx = tid & 15, ty = tid >> 4;
    float acc[8][4];
    #pragma unroll
    for (int m=0;m<8;m++)
        #pragma unroll
        for (int n=0;n<4;n++) acc[m][n]=0.f;
    const float* prow  = g_s + ((size_t)g*LQ + i0)*TT;
    const float* vbase = g_v + (((size_t)g*TT) << 6);
    for (int k0=0;k0<TT;k0+=32){
        {
            const int r  = tid >> 3;          // 0..31
            const int c0 = (tid & 7)*4;       // 0..28
            #pragma unroll
            for (int rr=0;rr<4;rr++){
                const int row = r + rr*32;
                float4 pv = *(const float4*)(prow + (size_t)row*TT + k0 + c0);
                Ps[c0+0][row]=pv.x; Ps[c0+1][row]=pv.y; Ps[c0+2][row]=pv.z; Ps[c0+3][row]=pv.w;
            }
            const int vr  = tid >> 4;         // 0..15
            const int vc0 = (tid & 15)*4;
            #pragma unroll
            for (int rr=0;rr<2;rr++){
                float4 vv = *(const float4*)(vbase + (size_t)(k0+vr+rr*16)*DHD + vc0);
                *(float4*)&Vs[vr+rr*16][vc0] = vv;
            }
        }
        __syncthreads();
        #pragma unroll
        for (int kk=0;kk<32;kk++){
            float a[8], bb[4];
            #pragma unroll
            for (int m=0;m<8;m++) a[m]=Ps[kk][ty*8+m];
            #pragma unroll
            for (int n=0;n<4;n++) bb[n]=Vs[kk][tx*4+n];
            #pragma unroll
            for (int m=0;m<8;m++)
                #pragma unroll
                for (int n=0;n<4;n++)
                    acc[m][n] = fmaf(a[m], bb[n], acc[m][n]);
        }
        __syncthreads();
    }
    #pragma unroll
    for (int m=0;m<8;m++){
        const int i = i0 + ty*8 + m;
        float* dst = g_av + ((size_t)(i*BATCH + b))*DMODEL + (h<<6) + tx*4;
        #pragma unroll
        for (int n=0;n<4;n++) dst[n] = acc[m][n];
    }
}

// ---------------- layernorm over D, writes output ----------------------------
__global__ __launch_bounds__(256) void ln_kernel(const float* __restrict__ gamma,
                                                 const float* __restrict__ beta,
                                                 float* __restrict__ out)
{
    const int row = blockIdx.x;
    const float* hr = g_h + (size_t)row*DMODEL;
    const int c = threadIdx.x * 4;
    float4 v = *(const float4*)(hr + c);
    float s = v.x+v.y+v.z+v.w;
    s = blockSum(s);
    const float mu = s * (1.f/DMODEL);
    float dx = v.x-mu, dy = v.y-mu, dz = v.z-mu, dw = v.w-mu;
    float sq = dx*dx+dy*dy+dz*dz+dw*dw;
    sq = blockSum(sq);
    const float inv = rsqrtf(sq*(1.f/DMODEL) + 1e-5f);
    float4 gm = *(const float4*)(gamma + c);
    float4 bt = *(const float4*)(beta + c);
    float4 o;
    o.x = dx*inv*gm.x + bt.x;
    o.y = dy*inv*gm.y + bt.y;
    o.z = dz*inv*gm.z + bt.z;
    o.w = dw*inv*gm.w + bt.w;
    *(float4*)(out + (size_t)row*DMODEL + c) = o;
}

// ---------------- launch ------------------------------------------------------
extern "C" void kernel_launch(void* const* d_in, const int* in_sizes, int n_in,
                              void* d_out, int out_size)
{
    const float* x        = (const float*)d_in[0];
    const float* pos_emb  = (const float*)d_in[1];
    const float* memory   = (const float*)d_in[2];
    const float* ubias    = (const float*)d_in[3];
    const float* vbias    = (const float*)d_in[4];
    // d_in[5] = mask (recomputed analytically)
    const float* Wq       = (const float*)d_in[6];
    const float* Wkv      = (const float*)d_in[7];
    const float* Wrel     = (const float*)d_in[8];
    const float* Wo       = (const float*)d_in[9];
    const float* gamma    = (const float*)d_in[10];
    const float* beta     = (const float*)d_in[11];
    float* out    = (float*)d_out;                     // [L,B,D]
    float* out_am = out + (size_t)LQ*BATCH*DMODEL;     // [L,T]

    proj_gemm<0,1024><<<dim3( 8,16), 256>>>(x,      nullptr, Wq);
    proj_gemm<1,2048><<<dim3(16,32), 256>>>(memory, x,       Wkv);
    proj_gemm<2,1024><<<dim3( 8,32), 256>>>(pos_emb,nullptr, Wrel);

    scores_gemm<0><<<dim3(TT/64, LQ/64, NG), 256>>>(ubias);   // AC -> g_s
    scores_gemm<1><<<dim3(TT/64, LQ/64, NG), 256>>>(vbias);   // BD -> g_bd

    softmax_kernel<<<NG*LQ, 256>>>();
    attnmat_kernel<<<(LQ*TT)/256, 256>>>(out_am);

    pv_gemm<<<dim3(LQ/128, NG), 256>>>();

    proj_gemm<3,1024><<<dim3(8,16), 256>>>(nullptr, x, Wo);   // g_h = x + av@Wo
    ln_kernel<<<LQ*BATCH, 256>>>(gamma, beta, out);
}

// round 3
// speedup vs baseline: 1.2111x; 1.2111x over previous
#include <cuda_runtime.h>
#include <math.h>

#define LQ      1024
#define BATCH   2
#define DMODEL  1024
#define NH      16
#define DHD     64
#define MEMLEN  1024
#define TT      2048            // T = L + M
#define NG      (BATCH*NH)      // 32 batched heads
#define SCALE_F 0.125f          // 1/sqrt(64)
#define NEGBIG  -1e30f

// ---------------- scratch (device globals; no allocation allowed) -------------
__device__ float g_q [NG*LQ*DHD];                    //  8 MB  [b][h][i][d]
__device__ float g_k [NG*TT*DHD];                    // 16 MB  [b][h][t][d]
__device__ float g_v [NG*TT*DHD];                    // 16 MB
__device__ float g_r [NG*TT*DHD];                    // 16 MB
__device__ float g_s [(size_t)NG*LQ*TT];             // 256 MB scores -> probs
__device__ float g_av[LQ*BATCH*NH*DHD];              //  8 MB  [(i*B+b)][h*64+d]
__device__ float g_h [LQ*BATCH*DMODEL];              //  8 MB  pre-LN residual

// ---------------- reductions ----------------
__device__ __forceinline__ float warpSum(float v){
    #pragma unroll
    for (int o=16;o>0;o>>=1) v += __shfl_xor_sync(0xffffffffu, v, o);
    return v;
}
__device__ __forceinline__ float blockSum(float v){
    __shared__ float sm[32];
    int lane = threadIdx.x & 31, w = threadIdx.x >> 5;
    v = warpSum(v);
    if (lane==0) sm[w] = v;
    __syncthreads();
    float r = (threadIdx.x < 8) ? sm[threadIdx.x] : 0.f;
    if (w==0){
        #pragma unroll
        for (int o=4;o>0;o>>=1) r += __shfl_xor_sync(0xffffffffu, r, o);
        if (lane==0) sm[0]=r;
    }
    __syncthreads();
    r = sm[0];
    __syncthreads();
    return r;
}
__device__ __forceinline__ float blockMax(float v){
    __shared__ float sm[32];
    int lane = threadIdx.x & 31, w = threadIdx.x >> 5;
    #pragma unroll
    for (int o=16;o>0;o>>=1) v = fmaxf(v, __shfl_xor_sync(0xffffffffu, v, o));
    if (lane==0) sm[w] = v;
    __syncthreads();
    float r = (threadIdx.x < 8) ? sm[threadIdx.x] : -3.4e38f;
    if (w==0){
        #pragma unroll
        for (int o=4;o>0;o>>=1) r = fmaxf(r, __shfl_xor_sync(0xffffffffu, r, o));
        if (lane==0) sm[0]=r;
    }
    __syncthreads();
    r = sm[0];
    __syncthreads();
    return r;
}

// ---------------- combined QKVR projection GEMM ------------------------------
// One launch covering:
//  seg0 (128 tiles): q = x@Wq            (M=2048, N=1024) -> g_q
//  seg1 (512 tiles): kv = concat@Wkv     (M=4096, N=2048) -> g_k/g_v
//  seg2 (256 tiles): r = pos_emb@Wrel    (M=4096, N=1024) -> g_r
__global__ __launch_bounds__(256) void qkvr_gemm(const float* __restrict__ x,
                                                 const float* __restrict__ memory,
                                                 const float* __restrict__ pos_emb,
                                                 const float* __restrict__ Wq,
                                                 const float* __restrict__ Wkv,
                                                 const float* __restrict__ Wrel)
{
    constexpr int BK=8;
    int bid = blockIdx.x;
    int mode, m0, n0, N;
    const float* W;
    if (bid < 128)      { mode=0; m0=(bid>>3)<<7;  n0=(bid&7)<<7;  N=1024; W=Wq;  }
    else if (bid < 640) { int t=bid-128; mode=1; m0=(t>>4)<<7; n0=(t&15)<<7; N=2048; W=Wkv; }
    else                { int t=bid-640; mode=2; m0=(t>>3)<<7; n0=(t&7)<<7;  N=1024; W=Wrel;}

    __shared__ float As[BK][128];
    __shared__ float Ws[BK][128];
    const int tid = threadIdx.x;
    const int a_r = tid >> 1;
    const int a_c = (tid & 1) * 4;
    const int w_r = tid >> 5;
    const int w_c = (tid & 31) * 4;
    const int tx = tid & 15, ty = tid >> 4;

    float acc[8][8];
    #pragma unroll
    for (int m=0;m<8;m++)
        #pragma unroll
        for (int n=0;n<8;n++) acc[m][n]=0.f;

    const int grow = m0 + a_r;
    const float* arow;
    if (mode==0)      arow = x + (size_t)grow*DMODEL;
    else if (mode==1) arow = (grow < MEMLEN*BATCH) ? (memory + (size_t)grow*DMODEL)
                                                   : (x + (size_t)(grow - MEMLEN*BATCH)*DMODEL);
    else              arow = pos_emb + (size_t)grow*DMODEL;

    for (int k0=0;k0<DMODEL;k0+=BK){
        float4 av = *(const float4*)(arow + k0 + a_c);
        As[a_c+0][a_r]=av.x; As[a_c+1][a_r]=av.y; As[a_c+2][a_r]=av.z; As[a_c+3][a_r]=av.w;
        float4 wv = *(const float4*)(W + (size_t)(k0+w_r)*N + n0 + w_c);
        *(float4*)&Ws[w_r][w_c] = wv;
        __syncthreads();
        #pragma unroll
        for (int kk=0;kk<BK;kk++){
            float4 a0v = *(const float4*)&As[kk][ty*8];
            float4 a1v = *(const float4*)&As[kk][ty*8+4];
            float4 b0v = *(const float4*)&Ws[kk][tx*8];
            float4 b1v = *(const float4*)&Ws[kk][tx*8+4];
            float a[8] = {a0v.x,a0v.y,a0v.z,a0v.w,a1v.x,a1v.y,a1v.z,a1v.w};
            float b[8] = {b0v.x,b0v.y,b0v.z,b0v.w,b1v.x,b1v.y,b1v.z,b1v.w};
            #pragma unroll
            for (int m=0;m<8;m++)
                #pragma unroll
                for (int n=0;n<8;n++)
                    acc[m][n] = fmaf(a[m], b[n], acc[m][n]);
        }
        __syncthreads();
    }

    #pragma unroll
    for (int m=0;m<8;m++){
        const int row = m0 + ty*8 + m;
        #pragma unroll
        for (int n=0;n<8;n++){
            const int col = n0 + tx*8 + n;
            const float val = acc[m][n];
            if (mode==0){
                int i = row >> 1, b = row & 1;
                int h = col >> 6, d = col & 63;
                g_q[(((size_t)(b*NH+h)*LQ + i)<<6) + d] = val;
            } else if (mode==1){
                int t = row >> 1, b = row & 1;
                int c = col; float* dst = g_k;
                if (c >= NH*DHD){ dst = g_v; c -= NH*DHD; }
                int h = c >> 6, d = c & 63;
                dst[(((size_t)(b*NH+h)*TT + t)<<6) + d] = val;
            } else {
                int t = row >> 1, b = row & 1;
                int h = col >> 6, d = col & 63;
                g_r[(((size_t)(b*NH+h)*TT + t)<<6) + d] = val;
            }
        }
    }
}

// ---------------- fused scores: S = ((q+u)K^T + shifted (q+v)R^T) * scale ----
// 128x128 tiles, 512 threads, per-thread 4x8. BD via Toeplitz r-band in SMEM:
// score[i,j] uses r[j-i+1023]; per thread all (m,n) read a 12-value window.
__global__ __launch_bounds__(512) void scores_fused(const float* __restrict__ ubias,
                                                    const float* __restrict__ vbias)
{
    const int g  = blockIdx.z;
    const int h  = g % NH;
    const int i0 = blockIdx.y << 7;
    const int j0 = blockIdx.x << 7;
    const int delta = j0 - i0;
    if (delta > 1151) return;                  // fully masked tile

    __shared__ float Qs[16][128];
    __shared__ float Ks[16][128];
    __shared__ float Rs[16][256];
    __shared__ float Ub[16], Vb[16];

    const int tid = threadIdx.x;
    const int tx = tid & 15;                   // n: 8 cols
    const int ty = tid >> 4;                   // m: 4 rows (0..31)
    const int rbase_g = delta + 896;           // global r row at band offset 0

    float acc[4][8];
    #pragma unroll
    for (int m=0;m<4;m++)
        #pragma unroll
        for (int n=0;n<8;n++) acc[m][n]=0.f;

    // per-thread staging indices
    const int qk_r = tid & 127;
    const int qk_c = (tid >> 7) * 4;           // 0,4,8,12
    const int rs_lr = tid >> 1;                // 0..255
    const int rs_c  = (tid & 1) * 8;           // 0 / 8
    const int rs_gr = min(max(rbase_g + rs_lr, 0), TT-1);

    const float* qbase = g_q + (((size_t)g*LQ + i0 + qk_r) << 6);
    const float* kbase = g_k + (((size_t)g*TT + j0 + qk_r) << 6);
    const float* rrow  = g_r + (((size_t)g*TT + rs_gr) << 6);

    for (int d0=0; d0<64; d0+=16){
        {
            float4 qv = *(const float4*)(qbase + d0 + qk_c);
            Qs[qk_c+0][qk_r]=qv.x; Qs[qk_c+1][qk_r]=qv.y;
            Qs[qk_c+2][qk_r]=qv.z; Qs[qk_c+3][qk_r]=qv.w;
            float4 kv = *(const float4*)(kbase + d0 + qk_c);
            Ks[qk_c+0][qk_r]=kv.x; Ks[qk_c+1][qk_r]=kv.y;
            Ks[qk_c+2][qk_r]=kv.z; Ks[qk_c+3][qk_r]=kv.w;
            float4 r0 = *(const float4*)(rrow + d0 + rs_c);
            float4 r1 = *(const float4*)(rrow + d0 + rs_c + 4);
            Rs[rs_c+0][rs_lr]=r0.x; Rs[rs_c+1][rs_lr]=r0.y;
            Rs[rs_c+2][rs_lr]=r0.z; Rs[rs_c+3][rs_lr]=r0.w;
            Rs[rs_c+4][rs_lr]=r1.x; Rs[rs_c+5][rs_lr]=r1.y;
            Rs[rs_c+6][rs_lr]=r1.z; Rs[rs_c+7][rs_lr]=r1.w;
            if (tid < 16){
                Ub[tid] = ubias[(h<<6) + d0 + tid];
                Vb[tid] = vbias[(h<<6) + d0 + tid];
            }
        }
        __syncthreads();
        const int rb_base = tx*8 - ty*4 + 124;  // multiple of 4
        #pragma unroll
        for (int kk=0;kk<16;kk++){
            float4 qv = *(const float4*)&Qs[kk][ty*4];
            const float ub = Ub[kk], vb = Vb[kk];
            float au[4], avv[4];
            au[0]=qv.x+ub; au[1]=qv.y+ub; au[2]=qv.z+ub; au[3]=qv.w+ub;
            avv[0]=qv.x+vb; avv[1]=qv.y+vb; avv[2]=qv.z+vb; avv[3]=qv.w+vb;
            float4 b0 = *(const float4*)&Ks[kk][tx*8];
            float4 b1 = *(const float4*)&Ks[kk][tx*8+4];
            float b8[8] = {b0.x,b0.y,b0.z,b0.w,b1.x,b1.y,b1.z,b1.w};
            float4 r0 = *(const float4*)&Rs[kk][rb_base];
            float4 r1 = *(const float4*)&Rs[kk][rb_base+4];
            float4 r2 = *(const float4*)&Rs[kk][rb_base+8];
            float rb[12] = {r0.x,r0.y,r0.z,r0.w,r1.x,r1.y,r1.z,r1.w,r2.x,r2.y,r2.z,r2.w};
            #pragma unroll
            for (int m=0;m<4;m++)
                #pragma unroll
                for (int n=0;n<8;n++){
                    acc[m][n] = fmaf(au[m],  b8[n],        acc[m][n]);
                    acc[m][n] = fmaf(avv[m], rb[n-m+3],    acc[m][n]);
                }
        }
        __syncthreads();
    }

    #pragma unroll
    for (int m=0;m<4;m++){
        const int i = i0 + ty*4 + m;
        float* srow = g_s + ((size_t)g*LQ + i)*TT + j0 + tx*8;
        float4 o0, o1;
        o0.x=acc[m][0]*SCALE_F; o0.y=acc[m][1]*SCALE_F; o0.z=acc[m][2]*SCALE_F; o0.w=acc[m][3]*SCALE_F;
        o1.x=acc[m][4]*SCALE_F; o1.y=acc[m][5]*SCALE_F; o1.z=acc[m][6]*SCALE_F; o1.w=acc[m][7]*SCALE_F;
        *(float4*)srow = o0;
        *(float4*)(srow+4) = o1;
    }
}

// ---------------- softmax: in-place over g_s rows (scores pre-scaled) --------
__global__ __launch_bounds__(256) void softmax_kernel()
{
    const int idx = blockIdx.x;            // g*L + i
    const int i   = idx & (LQ-1);
    float* srow = g_s + (size_t)idx*TT;
    const int jmax = i + MEMLEN;
    const int tid = threadIdx.x;
    float vals[8];
    float mx = -3.4e38f;
    #pragma unroll
    for (int q=0;q<8;q++){
        int j = q*256 + tid;
        if (j <= jmax){
            float vv = srow[j];
            vals[q] = vv;
            mx = fmaxf(mx, vv);
        } else vals[q] = NEGBIG;
    }
    mx = blockMax(mx);
    float s = 0.f;
    #pragma unroll
    for (int q=0;q<8;q++){
        float e = (vals[q] > -1e29f) ? __expf(vals[q]-mx) : 0.f;
        vals[q] = e; s += e;
    }
    s = blockSum(s);
    const float inv = 1.f / s;
    #pragma unroll
    for (int q=0;q<8;q++) srow[q*256 + tid] = vals[q] * inv;
}

// ---------------- attn_matrix = mean over (b,h) of probs ---------------------
__global__ __launch_bounds__(256) void attnmat_kernel(float* __restrict__ out)
{
    const size_t idx = ((size_t)blockIdx.x*256 + threadIdx.x) * 4;   // over L*T
    float4 s = {0.f,0.f,0.f,0.f};
    #pragma unroll
    for (int g=0; g<NG; g++){
        float4 p = *(const float4*)(g_s + (size_t)g*LQ*TT + idx);
        s.x += p.x; s.y += p.y; s.z += p.z; s.w += p.w;
    }
    const float c = 1.f/NG;
    s.x*=c; s.y*=c; s.z*=c; s.w*=c;
    *(float4*)(out + idx) = s;
}

// ---------------- PV: av[g,i,:] = P[g,i,:] @ V[g,:,:] ------------------------
__global__ __launch_bounds__(256) void pv_gemm()
{
    const int g  = blockIdx.y;
    const int i0 = blockIdx.x * 128;
    const int b  = g / NH, h = g % NH;
    const int kmax = min(TT, i0 + 1152);       // beyond this, probs are 0
    __shared__ float Ps[32][132];
    __shared__ float Vs[32][68];
    const int tid = threadIdx.x;
    const int tx = tid & 15, ty = tid >> 4;
    float acc[8][4];
    #pragma unroll
    for (int m=0;m<8;m++)
        #pragma unroll
        for (int n=0;n<4;n++) acc[m][n]=0.f;
    const float* prow  = g_s + ((size_t)g*LQ + i0)*TT;
    const float* vbase = g_v + (((size_t)g*TT) << 6);
    for (int k0=0;k0<kmax;k0+=32){
        {
            const int r  = tid >> 3;          // 0..31
            const int c0 = (tid & 7)*4;       // 0..28
            #pragma unroll
            for (int rr=0;rr<4;rr++){
                const int row = r + rr*32;
                float4 pv = *(const float4*)(prow + (size_t)row*TT + k0 + c0);
                Ps[c0+0][row]=pv.x; Ps[c0+1][row]=pv.y; Ps[c0+2][row]=pv.z; Ps[c0+3][row]=pv.w;
            }
            const int vr  = tid >> 4;         // 0..15
            const int vc0 = (tid & 15)*4;
            #pragma unroll
            for (int rr=0;rr<2;rr++){
                float4 vv = *(const float4*)(vbase + (size_t)(k0+vr+rr*16)*DHD + vc0);
                *(float4*)&Vs[vr+rr*16][vc0] = vv;
            }
        }
        __syncthreads();
        #pragma unroll
        for (int kk=0;kk<32;kk++){
            float a[8], bb[4];
            #pragma unroll
            for (int m=0;m<8;m++) a[m]=Ps[kk][ty*8+m];
            #pragma unroll
            for (int n=0;n<4;n++) bb[n]=Vs[kk][tx*4+n];
            #pragma unroll
            for (int m=0;m<8;m++)
                #pragma unroll
                for (int n=0;n<4;n++)
                    acc[m][n] = fmaf(a[m], bb[n], acc[m][n]);
        }
        __syncthreads();
    }
    #pragma unroll
    for (int m=0;m<8;m++){
        const int i = i0 + ty*8 + m;
        float* dst = g_av + ((size_t)(i*BATCH + b))*DMODEL + (h<<6) + tx*4;
        #pragma unroll
        for (int n=0;n<4;n++) dst[n] = acc[m][n];
    }
}

// ---------------- Wo GEMM + residual: g_h = x + g_av @ Wo --------------------
// 128x64 tiles -> 256 CTAs (better SM fill than 128x128's 128 CTAs)
__global__ __launch_bounds__(256) void wo_gemm(const float* __restrict__ x,
                                               const float* __restrict__ Wo)
{
    constexpr int BK=8;
    const int m0 = blockIdx.y * 128;
    const int n0 = blockIdx.x * 64;
    __shared__ float As[BK][128];
    __shared__ float Ws[BK][64];
    const int tid = threadIdx.x;
    const int a_r = tid >> 1;
    const int a_c = (tid & 1) * 4;
    const int tx = tid & 15, ty = tid >> 4;

    float acc[8][4];
    #pragma unroll
    for (int m=0;m<8;m++)
        #pragma unroll
        for (int n=0;n<4;n++) acc[m][n]=0.f;

    const float* arow = g_av + (size_t)(m0 + a_r)*DMODEL;

    for (int k0=0;k0<DMODEL;k0+=BK){
        float4 av = *(const float4*)(arow + k0 + a_c);
        As[a_c+0][a_r]=av.x; As[a_c+1][a_r]=av.y; As[a_c+2][a_r]=av.z; As[a_c+3][a_r]=av.w;
        if (tid < 128){
            const int w_r = tid >> 4;
            const int w_c = (tid & 15) * 4;
            float4 wv = *(const float4*)(Wo + (size_t)(k0+w_r)*DMODEL + n0 + w_c);
            *(float4*)&Ws[w_r][w_c] = wv;
        }
        __syncthreads();
        #pragma unroll
        for (int kk=0;kk<BK;kk++){
            float4 a0v = *(const float4*)&As[kk][ty*8];
            float4 a1v = *(const float4*)&As[kk][ty*8+4];
            float4 b0v = *(const float4*)&Ws[kk][tx*4];
            float a[8] = {a0v.x,a0v.y,a0v.z,a0v.w,a1v.x,a1v.y,a1v.z,a1v.w};
            float bb[4] = {b0v.x,b0v.y,b0v.z,b0v.w};
            #pragma unroll
            for (int m=0;m<8;m++)
                #pragma unroll
                for (int n=0;n<4;n++)
                    acc[m][n] = fmaf(a[m], bb[n], acc[m][n]);
        }
        __syncthreads();
    }

    #pragma unroll
    for (int m=0;m<8;m++){
        const int row = m0 + ty*8 + m;
        const float* xr = x + (size_t)row*DMODEL + n0 + tx*4;
        float* hr = g_h + (size_t)row*DMODEL + n0 + tx*4;
        float4 xv = *(const float4*)xr;
        float4 o;
        o.x = acc[m][0] + xv.x;
        o.y = acc[m][1] + xv.y;
        o.z = acc[m][2] + xv.z;
        o.w = acc[m][3] + xv.w;
        *(float4*)hr = o;
    }
}

// ---------------- layernorm over D, writes output ----------------------------
__global__ __launch_bounds__(256) void ln_kernel(const float* __restrict__ gamma,
                                                 const float* __restrict__ beta,
                                                 float* __restrict__ out)
{
    const int row = blockIdx.x;
    const float* hr = g_h + (size_t)row*DMODEL;
    const int c = threadIdx.x * 4;
    float4 v = *(const float4*)(hr + c);
    float s = v.x+v.y+v.z+v.w;
    s = blockSum(s);
    const float mu = s * (1.f/DMODEL);
    float dx = v.x-mu, dy = v.y-mu, dz = v.z-mu, dw = v.w-mu;
    float sq = dx*dx+dy*dy+dz*dz+dw*dw;
    sq = blockSum(sq);
    const float inv = rsqrtf(sq*(1.f/DMODEL) + 1e-5f);
    float4 gm = *(const float4*)(gamma + c);
    float4 bt = *(const float4*)(beta + c);
    float4 o;
    o.x = dx*inv*gm.x + bt.x;
    o.y = dy*inv*gm.y + bt.y;
    o.z = dz*inv*gm.z + bt.z;
    o.w = dw*inv*gm.w + bt.w;
    *(float4*)(out + (size_t)row*DMODEL + c) = o;
}

// ---------------- launch ------------------------------------------------------
extern "C" void kernel_launch(void* const* d_in, const int* in_sizes, int n_in,
                              void* d_out, int out_size)
{
    const float* x        = (const float*)d_in[0];
    const float* pos_emb  = (const float*)d_in[1];
    const float* memory   = (const float*)d_in[2];
    const float* ubias    = (const float*)d_in[3];
    const float* vbias    = (const float*)d_in[4];
    // d_in[5] = mask (recomputed analytically)
    const float* Wq       = (const float*)d_in[6];
    const float* Wkv      = (const float*)d_in[7];
    const float* Wrel     = (const float*)d_in[8];
    const float* Wo       = (const float*)d_in[9];
    const float* gamma    = (const float*)d_in[10];
    const float* beta     = (const float*)d_in[11];
    float* out    = (float*)d_out;                     // [L,B,D]
    float* out_am = out + (size_t)LQ*BATCH*DMODEL;     // [L,T]

    qkvr_gemm<<<896, 256>>>(x, memory, pos_emb, Wq, Wkv, Wrel);

    scores_fused<<<dim3(TT/128, LQ/128, NG), 512>>>(ubias, vbias);

    softmax_kernel<<<NG*LQ, 256>>>();
    attnmat_kernel<<<(LQ*TT)/1024, 256>>>(out_am);

    pv_gemm<<<dim3(LQ/128, NG), 256>>>();

    wo_gemm<<<dim3(16,16), 256>>>(x, Wo);
    ln_kernel<<<LQ*BATCH, 256>>>(gamma, beta, out);
}

// round 4
// speedup vs baseline: 2.1515x; 1.7765x over previous
#include <cuda_runtime.h>
#include <math.h>

#define LQ      1024
#define BATCH   2
#define DMODEL  1024
#define NH      16
#define DHD     64
#define MEMLEN  1024
#define TT      2048
#define NG      (BATCH*NH)
#define SCALE_F 0.125f
#define NEGBIG  -1e30f

// ---------------- scratch ------------------------------------------------------
__device__ float g_q [NG*LQ*DHD];
__device__ float g_k [NG*TT*DHD];
__device__ float g_v [NG*TT*DHD];
__device__ float g_r [NG*TT*DHD];
__device__ float g_bd[(size_t)NG*LQ*TT];             // BD pre-shift [g][i][p]
__device__ float g_s [(size_t)NG*LQ*TT];             // scores -> probs
__device__ float g_av[LQ*BATCH*NH*DHD];
__device__ float g_h [LQ*BATCH*DMODEL];

// ---------------- tf32 mma helpers --------------------------------------------
__device__ __forceinline__ unsigned f2tf(float f){
    unsigned r; asm("cvt.rna.tf32.f32 %0, %1;" : "=r"(r) : "f"(f)); return r;
}
__device__ __forceinline__ void mma_tf32(float c[4],
                                         unsigned a0, unsigned a1, unsigned a2, unsigned a3,
                                         unsigned b0, unsigned b1){
    asm volatile("mma.sync.aligned.m16n8k8.row.col.f32.tf32.tf32.f32 "
        "{%0,%1,%2,%3}, {%4,%5,%6,%7}, {%8,%9}, {%0,%1,%2,%3};"
        : "+f"(c[0]), "+f"(c[1]), "+f"(c[2]), "+f"(c[3])
        : "r"(a0), "r"(a1), "r"(a2), "r"(a3), "r"(b0), "r"(b1));
}

// ---------------- reductions ----------------
__device__ __forceinline__ float blockSum(float v){
    __shared__ float sm[32];
    int lane = threadIdx.x & 31, w = threadIdx.x >> 5;
    #pragma unroll
    for (int o=16;o>0;o>>=1) v += __shfl_xor_sync(0xffffffffu, v, o);
    if (lane==0) sm[w] = v;
    __syncthreads();
    float r = (threadIdx.x < 8) ? sm[threadIdx.x] : 0.f;
    if (w==0){
        #pragma unroll
        for (int o=4;o>0;o>>=1) r += __shfl_xor_sync(0xffffffffu, r, o);
        if (lane==0) sm[0]=r;
    }
    __syncthreads();
    r = sm[0];
    __syncthreads();
    return r;
}
__device__ __forceinline__ float blockMax(float v){
    __shared__ float sm[32];
    int lane = threadIdx.x & 31, w = threadIdx.x >> 5;
    #pragma unroll
    for (int o=16;o>0;o>>=1) v = fmaxf(v, __shfl_xor_sync(0xffffffffu, v, o));
    if (lane==0) sm[w] = v;
    __syncthreads();
    float r = (threadIdx.x < 8) ? sm[threadIdx.x] : -3.4e38f;
    if (w==0){
        #pragma unroll
        for (int o=4;o>0;o>>=1) r = fmaxf(r, __shfl_xor_sync(0xffffffffu, r, o));
        if (lane==0) sm[0]=r;
    }
    __syncthreads();
    r = sm[0];
    __syncthreads();
    return r;
}

// ---------------- QKVR projection GEMM (tf32 MMA) -----------------------------
// seg0 (128): q = x@Wq -> g_q ; seg1 (512): concat@Wkv -> g_k/g_v ; seg2 (256): pos_emb@Wrel -> g_r
__global__ __launch_bounds__(256) void qkvr_mma(const float* __restrict__ x,
                                                const float* __restrict__ memory,
                                                const float* __restrict__ pos_emb,
                                                const float* __restrict__ Wq,
                                                const float* __restrict__ Wkv,
                                                const float* __restrict__ Wrel)
{
    int bid = blockIdx.x;
    int mode, m0, n0, N;
    const float* W;
    if (bid < 128)      { mode=0; m0=(bid>>3)<<7;  n0=(bid&7)<<7;  N=1024; W=Wq;  }
    else if (bid < 640) { int t=bid-128; mode=1; m0=(t>>4)<<7; n0=(t&15)<<7; N=2048; W=Wkv; }
    else                { int t=bid-640; mode=2; m0=(t>>3)<<7; n0=(t&7)<<7;  N=1024; W=Wrel;}

    __shared__ unsigned As[128][36];     // [m][k], pad 4 -> conflict-free frags
    __shared__ unsigned Bs[32][136];     // [k][n], pad 8 -> conflict-free frags

    const int tid = threadIdx.x;
    const int warp = tid >> 5, lane = tid & 31;
    const int gq = lane >> 2, tq = lane & 3;
    const int wm = (warp >> 2) * 64, wn = (warp & 3) * 32;

    const int a_r = tid >> 1;
    const int a_cb = (tid & 1) * 16;
    const int grow = m0 + a_r;
    const float* arow;
    if (mode==0)      arow = x + (size_t)grow*DMODEL;
    else if (mode==1) arow = (grow < MEMLEN*BATCH) ? memory + (size_t)grow*DMODEL
                                                   : x + (size_t)(grow - MEMLEN*BATCH)*DMODEL;
    else              arow = pos_emb + (size_t)grow*DMODEL;

    const int b_kr = tid >> 3;
    const int b_cb = (tid & 7) * 16;

    float acc[4][4][4];
    #pragma unroll
    for (int mi=0;mi<4;mi++)
        #pragma unroll
        for (int ni=0;ni<4;ni++)
            #pragma unroll
            for (int c=0;c<4;c++) acc[mi][ni][c]=0.f;

    for (int k0=0;k0<DMODEL;k0+=32){
        #pragma unroll
        for (int q=0;q<4;q++){
            float4 v = *(const float4*)(arow + k0 + a_cb + q*4);
            uint4 u = { f2tf(v.x), f2tf(v.y), f2tf(v.z), f2tf(v.w) };
            *(uint4*)&As[a_r][a_cb + q*4] = u;
        }
        const float* brow = W + (size_t)(k0 + b_kr)*N + n0 + b_cb;
        #pragma unroll
        for (int q=0;q<4;q++){
            float4 v = *(const float4*)(brow + q*4);
            uint4 u = { f2tf(v.x), f2tf(v.y), f2tf(v.z), f2tf(v.w) };
            *(uint4*)&Bs[b_kr][b_cb + q*4] = u;
        }
        __syncthreads();
        #pragma unroll
        for (int kk=0;kk<32;kk+=8){
            unsigned a[4][4], b[4][2];
            #pragma unroll
            for (int mi=0;mi<4;mi++){
                int m = wm + mi*16;
                a[mi][0] = As[m+gq  ][kk+tq  ];
                a[mi][1] = As[m+gq+8][kk+tq  ];
                a[mi][2] = As[m+gq  ][kk+tq+4];
                a[mi][3] = As[m+gq+8][kk+tq+4];
            }
            #pragma unroll
            for (int ni=0;ni<4;ni++){
                int n = wn + ni*8;
                b[ni][0] = Bs[kk+tq  ][n+gq];
                b[ni][1] = Bs[kk+tq+4][n+gq];
            }
            #pragma unroll
            for (int mi=0;mi<4;mi++)
                #pragma unroll
                for (int ni=0;ni<4;ni++)
                    mma_tf32(acc[mi][ni], a[mi][0],a[mi][1],a[mi][2],a[mi][3], b[ni][0],b[ni][1]);
        }
        __syncthreads();
    }

    #pragma unroll
    for (int mi=0;mi<4;mi++){
        #pragma unroll
        for (int rr=0;rr<2;rr++){
            const int row = m0 + wm + mi*16 + gq + rr*8;
            const int t   = row >> 1, bb = row & 1;
            #pragma unroll
            for (int ni=0;ni<4;ni++){
                const int col = n0 + wn + ni*8 + 2*tq;
                float2 val = { acc[mi][ni][rr*2+0], acc[mi][ni][rr*2+1] };
                if (mode==0){
                    int h = col >> 6, d = col & 63;
                    *(float2*)&g_q[(((size_t)(bb*NH+h)*LQ + t)<<6) + d] = val;
                } else if (mode==1){
                    int c = col; float* dst = g_k;
                    if (c >= NH*DHD){ dst = g_v; c -= NH*DHD; }
                    int h = c >> 6, d = c & 63;
                    *(float2*)&dst[(((size_t)(bb*NH+h)*TT + t)<<6) + d] = val;
                } else {
                    int h = col >> 6, d = col & 63;
                    *(float2*)&g_r[(((size_t)(bb*NH+h)*TT + t)<<6) + d] = val;
                }
            }
        }
    }
}

// ---------------- BD GEMM: g_bd[g][i][p] = (q_i + vbias_h) . r_p  (tf32 MMA) --
__global__ __launch_bounds__(256) void bd_mma(const float* __restrict__ vbias)
{
    const int gg = blockIdx.z, h = gg & (NH-1);
    const int i0 = blockIdx.y << 7;
    const int p0 = blockIdx.x << 7;
    if (i0 + p0 <= 768) return;                 // never read (p < 1023 - i for all elems)

    __shared__ unsigned As[128][36];            // (q+v) [i][k]
    __shared__ unsigned Rs[128][36];            // r     [p][k]

    const int tid = threadIdx.x;
    const int warp = tid >> 5, lane = tid & 31;
    const int gq = lane >> 2, tq = lane & 3;
    const int wm = (warp >> 2) * 64, wn = (warp & 3) * 32;

    float acc[4][4][4];
    #pragma unroll
    for (int mi=0;mi<4;mi++)
        #pragma unroll
        for (int ni=0;ni<4;ni++)
            #pragma unroll
            for (int c=0;c<4;c++) acc[mi][ni][c]=0.f;

    const int sr = tid >> 1;
    const int cb = (tid & 1) * 16;
    const float* qrow = g_q + (((size_t)gg*LQ + i0 + sr) << 6);
    const float* rrow = g_r + (((size_t)gg*TT + p0 + sr) << 6);
    const float* vb   = vbias + (h << 6);

    #pragma unroll
    for (int k0=0;k0<DHD;k0+=32){
        #pragma unroll
        for (int q=0;q<4;q++){
            int c = cb + q*4;
            float4 v  = *(const float4*)(qrow + k0 + c);
            float4 bv = *(const float4*)(vb   + k0 + c);
            uint4 u = { f2tf(v.x+bv.x), f2tf(v.y+bv.y), f2tf(v.z+bv.z), f2tf(v.w+bv.w) };
            *(uint4*)&As[sr][c] = u;
            float4 rv = *(const float4*)(rrow + k0 + c);
            uint4 ur = { f2tf(rv.x), f2tf(rv.y), f2tf(rv.z), f2tf(rv.w) };
            *(uint4*)&Rs[sr][c] = ur;
        }
        __syncthreads();
        #pragma unroll
        for (int kk=0;kk<32;kk+=8){
            unsigned a[4][4], b[4][2];
            #pragma unroll
            for (int mi=0;mi<4;mi++){
                int m = wm + mi*16;
                a[mi][0] = As[m+gq  ][kk+tq  ];
                a[mi][1] = As[m+gq+8][kk+tq  ];
                a[mi][2] = As[m+gq  ][kk+tq+4];
                a[mi][3] = As[m+gq+8][kk+tq+4];
            }
            #pragma unroll
            for (int ni=0;ni<4;ni++){
                int n = wn + ni*8;
                b[ni][0] = Rs[n+gq][kk+tq  ];
                b[ni][1] = Rs[n+gq][kk+tq+4];
            }
            #pragma unroll
            for (int mi=0;mi<4;mi++)
                #pragma unroll
                for (int ni=0;ni<4;ni++)
                    mma_tf32(acc[mi][ni], a[mi][0],a[mi][1],a[mi][2],a[mi][3], b[ni][0],b[ni][1]);
        }
        __syncthreads();
    }

    #pragma unroll
    for (int mi=0;mi<4;mi++)
        #pragma unroll
        for (int rr=0;rr<2;rr++){
            const int i = i0 + wm + mi*16 + gq + rr*8;
            float* row = g_bd + ((size_t)gg*LQ + i)*TT;
            #pragma unroll
            for (int ni=0;ni<4;ni++){
                const int p = p0 + wn + ni*8 + 2*tq;
                float2 val = { acc[mi][ni][rr*2+0], acc[mi][ni][rr*2+1] };
                *(float2*)&row[p] = val;
            }
        }
}

// ---------------- scores: g_s = ((q+u).K^T + shift(BD)) * scale  (tf32 MMA) ---
__global__ __launch_bounds__(256) void scores_mma(const float* __restrict__ ubias)
{
    const int gg = blockIdx.z, h = gg & (NH-1);
    const int i0 = blockIdx.y << 7;
    const int j0 = blockIdx.x << 7;
    if (j0 - i0 > 1151) return;                 // fully masked tile

    __shared__ unsigned As[128][36];            // (q+u) [i][k]
    __shared__ unsigned Ks[128][36];            // k     [j][k]

    const int tid = threadIdx.x;
    const int warp = tid >> 5, lane = tid & 31;
    const int gq = lane >> 2, tq = lane & 3;
    const int wm = (warp >> 2) * 64, wn = (warp & 3) * 32;

    float acc[4][4][4];
    #pragma unroll
    for (int mi=0;mi<4;mi++)
        #pragma unroll
        for (int ni=0;ni<4;ni++)
            #pragma unroll
            for (int c=0;c<4;c++) acc[mi][ni][c]=0.f;

    const int sr = tid >> 1;
    const int cb = (tid & 1) * 16;
    const float* qrow = g_q + (((size_t)gg*LQ + i0 + sr) << 6);
    const float* krow = g_k + (((size_t)gg*TT + j0 + sr) << 6);
    const float* ub   = ubias + (h << 6);

    #pragma unroll
    for (int k0=0;k0<DHD;k0+=32){
        #pragma unroll
        for (int q=0;q<4;q++){
            int c = cb + q*4;
            float4 v  = *(const float4*)(qrow + k0 + c);
            float4 bv = *(const float4*)(ub   + k0 + c);
            uint4 u = { f2tf(v.x+bv.x), f2tf(v.y+bv.y), f2tf(v.z+bv.z), f2tf(v.w+bv.w) };
            *(uint4*)&As[sr][c] = u;
            float4 kv = *(const float4*)(krow + k0 + c);
            uint4 uk = { f2tf(kv.x), f2tf(kv.y), f2tf(kv.z), f2tf(kv.w) };
            *(uint4*)&Ks[sr][c] = uk;
        }
        __syncthreads();
        #pragma unroll
        for (int kk=0;kk<32;kk+=8){
            unsigned a[4][4], b[4][2];
            #pragma unroll
            for (int mi=0;mi<4;mi++){
                int m = wm + mi*16;
                a[mi][0] = As[m+gq  ][kk+tq  ];
                a[mi][1] = As[m+gq+8][kk+tq  ];
                a[mi][2] = As[m+gq  ][kk+tq+4];
                a[mi][3] = As[m+gq+8][kk+tq+4];
            }
            #pragma unroll
            for (int ni=0;ni<4;ni++){
                int n = wn + ni*8;
                b[ni][0] = Ks[n+gq][kk+tq  ];
                b[ni][1] = Ks[n+gq][kk+tq+4];
            }
            #pragma unroll
            for (int mi=0;mi<4;mi++)
                #pragma unroll
                for (int ni=0;ni<4;ni++)
                    mma_tf32(acc[mi][ni], a[mi][0],a[mi][1],a[mi][2],a[mi][3], b[ni][0],b[ni][1]);
        }
        __syncthreads();
    }

    #pragma unroll
    for (int mi=0;mi<4;mi++)
        #pragma unroll
        for (int rr=0;rr<2;rr++){
            const int i = i0 + wm + mi*16 + gq + rr*8;
            const float* bdrow = g_bd + ((size_t)gg*LQ + i)*TT;
            float* srow = g_s + ((size_t)gg*LQ + i)*TT;
            #pragma unroll
            for (int ni=0;ni<4;ni++){
                const int j = j0 + wn + ni*8 + 2*tq;
                const int p = j - i + 1023;       // p > 2047 <=> masked; clamp is safe
                float b0 = bdrow[min(p,   2047)];
                float b1 = bdrow[min(p+1, 2047)];
                float2 val = { (acc[mi][ni][rr*2+0] + b0) * SCALE_F,
                               (acc[mi][ni][rr*2+1] + b1) * SCALE_F };
                *(float2*)&srow[j] = val;
            }
        }
}

// ---------------- softmax: in-place over g_s rows -----------------------------
__global__ __launch_bounds__(256) void softmax_kernel()
{
    const int idx = blockIdx.x;            // g*L + i
    const int i   = idx & (LQ-1);
    float* srow = g_s + (size_t)idx*TT;
    const int jmax = i + MEMLEN;
    const int tid = threadIdx.x;
    float vals[8];
    float mx = -3.4e38f;
    #pragma unroll
    for (int q=0;q<8;q++){
        int j = q*256 + tid;
        if (j <= jmax){
            float vv = srow[j];
            vals[q] = vv;
            mx = fmaxf(mx, vv);
        } else vals[q] = NEGBIG;
    }
    mx = blockMax(mx);
    float s = 0.f;
    #pragma unroll
    for (int q=0;q<8;q++){
        float e = (vals[q] > -1e29f) ? __expf(vals[q]-mx) : 0.f;
        vals[q] = e; s += e;
    }
    s = blockSum(s);
    const float inv = 1.f / s;
    #pragma unroll
    for (int q=0;q<8;q++) srow[q*256 + tid] = vals[q] * inv;
}

// ---------------- attn_matrix = mean over (b,h) of probs ----------------------
__global__ __launch_bounds__(256) void attnmat_kernel(float* __restrict__ out)
{
    const size_t idx = ((size_t)blockIdx.x*256 + threadIdx.x) * 4;
    float4 s = {0.f,0.f,0.f,0.f};
    #pragma unroll
    for (int g=0; g<NG; g++){
        float4 p = *(const float4*)(g_s + (size_t)g*LQ*TT + idx);
        s.x += p.x; s.y += p.y; s.z += p.z; s.w += p.w;
    }
    const float c = 1.f/NG;
    s.x*=c; s.y*=c; s.z*=c; s.w*=c;
    *(float4*)(out + idx) = s;
}

// ---------------- PV GEMM (tf32 MMA): av = P @ V ------------------------------
__global__ __launch_bounds__(256) void pv_mma()
{
    const int gg = blockIdx.y, b = gg >> 4, h = gg & (NH-1);
    const int i0 = blockIdx.x << 7;
    const int kmax = min(TT, i0 + 1152);

    __shared__ unsigned As[128][36];     // P chunk [i][k]
    __shared__ unsigned Vs[32][72];      // V chunk [k][d]

    const int tid = threadIdx.x;
    const int warp = tid >> 5, lane = tid & 31;
    const int gq = lane >> 2, tq = lane & 3;
    const int wm = (warp >> 1) * 32, wn = (warp & 1) * 32;

    float acc[2][4][4];
    #pragma unroll
    for (int mi=0;mi<2;mi++)
        #pragma unroll
        for (int ni=0;ni<4;ni++)
            #pragma unroll
            for (int c=0;c<4;c++) acc[mi][ni][c]=0.f;

    const int a_r = tid >> 1;
    const int a_cb = (tid & 1) * 16;
    const float* prow = g_s + ((size_t)gg*LQ + i0 + a_r)*TT + a_cb;
    const float* vtile = g_v + ((size_t)gg*TT << 6);
    const int v_jr = tid >> 3;
    const int v_db = (tid & 7) * 8;

    for (int k0=0;k0<kmax;k0+=32){
        #pragma unroll
        for (int q=0;q<4;q++){
            float4 v = *(const float4*)(prow + k0 + q*4);
            uint4 u = { f2tf(v.x), f2tf(v.y), f2tf(v.z), f2tf(v.w) };
            *(uint4*)&As[a_r][a_cb + q*4] = u;
        }
        const float* vr = vtile + (size_t)(k0 + v_jr)*DHD + v_db;
        #pragma unroll
        for (int q=0;q<2;q++){
            float4 v = *(const float4*)(vr + q*4);
            uint4 u = { f2tf(v.x), f2tf(v.y), f2tf(v.z), f2tf(v.w) };
            *(uint4*)&Vs[v_jr][v_db + q*4] = u;
        }
        __syncthreads();
        #pragma unroll
        for (int kk=0;kk<32;kk+=8){
            unsigned a[2][4], b[4][2];
            #pragma unroll
            for (int mi=0;mi<2;mi++){
                int m = wm + mi*16;
                a[mi][0] = As[m+gq  ][kk+tq  ];
                a[mi][1] = As[m+gq+8][kk+tq  ];
                a[mi][2] = As[m+gq  ][kk+tq+4];
                a[mi][3] = As[m+gq+8][kk+tq+4];
            }
            #pragma unroll
            for (int ni=0;ni<4;ni++){
                int n = wn + ni*8;
                b[ni][0] = Vs[kk+tq  ][n+gq];
                b[ni][1] = Vs[kk+tq+4][n+gq];
            }
            #pragma unroll
            for (int mi=0;mi<2;mi++)
                #pragma unroll
                for (int ni=0;ni<4;ni++)
                    mma_tf32(acc[mi][ni], a[mi][0],a[mi][1],a[mi][2],a[mi][3], b[ni][0],b[ni][1]);
        }
        __syncthreads();
    }

    #pragma unroll
    for (int mi=0;mi<2;mi++)
        #pragma unroll
        for (int rr=0;rr<2;rr++){
            const int i = i0 + wm + mi*16 + gq + rr*8;
            float* dst = g_av + (size_t)(i*BATCH + b)*DMODEL + (h<<6);
            #pragma unroll
            for (int ni=0;ni<4;ni++){
                const int d = wn + ni*8 + 2*tq;
                float2 val = { acc[mi][ni][rr*2+0], acc[mi][ni][rr*2+1] };
                *(float2*)&dst[d] = val;
            }
        }
}

// ---------------- Wo GEMM + residual (tf32 MMA): g_h = x + g_av @ Wo ----------
__global__ __launch_bounds__(256) void wo_mma(const float* __restrict__ x,
                                              const float* __restrict__ Wo)
{
    const int m0 = blockIdx.y << 7;
    const int n0 = blockIdx.x << 6;

    __shared__ unsigned As[128][36];
    __shared__ unsigned Bs[32][72];

    const int tid = threadIdx.x;
    const int warp = tid >> 5, lane = tid & 31;
    const int gq = lane >> 2, tq = lane & 3;
    const int wm = (warp >> 1) * 32, wn = (warp & 1) * 32;

    float acc[2][4][4];
    #pragma unroll
    for (int mi=0;mi<2;mi++)
        #pragma unroll
        for (int ni=0;ni<4;ni++)
            #pragma unroll
            for (int c=0;c<4;c++) acc[mi][ni][c]=0.f;

    const int a_r = tid >> 1;
    const int a_cb = (tid & 1) * 16;
    const float* arow = g_av + (size_t)(m0 + a_r)*DMODEL + a_cb;
    const int b_kr = tid >> 3;
    const int b_db = (tid & 7) * 8;

    for (int k0=0;k0<DMODEL;k0+=32){
        #pragma unroll
        for (int q=0;q<4;q++){
            float4 v = *(const float4*)(arow + k0 + q*4);
            uint4 u = { f2tf(v.x), f2tf(v.y), f2tf(v.z), f2tf(v.w) };
            *(uint4*)&As[a_r][a_cb + q*4] = u;
        }
        const float* brow = Wo + (size_t)(k0 + b_kr)*DMODEL + n0 + b_db;
        #pragma unroll
        for (int q=0;q<2;q++){
            float4 v = *(const float4*)(brow + q*4);
            uint4 u = { f2tf(v.x), f2tf(v.y), f2tf(v.z), f2tf(v.w) };
            *(uint4*)&Bs[b_kr][b_db + q*4] = u;
        }
        __syncthreads();
        #pragma unroll
        for (int kk=0;kk<32;kk+=8){
            unsigned a[2][4], b[4][2];
            #pragma unroll
            for (int mi=0;mi<2;mi++){
                int m = wm + mi*16;
                a[mi][0] = As[m+gq  ][kk+tq  ];
                a[mi][1] = As[m+gq+8][kk+tq  ];
                a[mi][2] = As[m+gq  ][kk+tq+4];
                a[mi][3] = As[m+gq+8][kk+tq+4];
            }
            #pragma unroll
            for (int ni=0;ni<4;ni++){
                int n = wn + ni*8;
                b[ni][0] = Bs[kk+tq  ][n+gq];
                b[ni][1] = Bs[kk+tq+4][n+gq];
            }
            #pragma unroll
            for (int mi=0;mi<2;mi++)
                #pragma unroll
                for (int ni=0;ni<4;ni++)
                    mma_tf32(acc[mi][ni], a[mi][0],a[mi][1],a[mi][2],a[mi][3], b[ni][0],b[ni][1]);
        }
        __syncthreads();
    }

    #pragma unroll
    for (int mi=0;mi<2;mi++)
        #pragma unroll
        for (int rr=0;rr<2;rr++){
            const int row = m0 + wm + mi*16 + gq + rr*8;
            #pragma unroll
            for (int ni=0;ni<4;ni++){
                const int col = n0 + wn + ni*8 + 2*tq;
                float2 xv = *(const float2*)&x[(size_t)row*DMODEL + col];
                float2 val = { acc[mi][ni][rr*2+0] + xv.x,
                               acc[mi][ni][rr*2+1] + xv.y };
                *(float2*)&g_h[(size_t)row*DMODEL + col] = val;
            }
        }
}

// ---------------- layernorm ----------------------------------------------------
__global__ __launch_bounds__(256) void ln_kernel(const float* __restrict__ gamma,
                                                 const float* __restrict__ beta,
                                                 float* __restrict__ out)
{
    const int row = blockIdx.x;
    const float* hr = g_h + (size_t)row*DMODEL;
    const int c = threadIdx.x * 4;
    float4 v = *(const float4*)(hr + c);
    float s = v.x+v.y+v.z+v.w;
    s = blockSum(s);
    const float mu = s * (1.f/DMODEL);
    float dx = v.x-mu, dy = v.y-mu, dz = v.z-mu, dw = v.w-mu;
    float sq = dx*dx+dy*dy+dz*dz+dw*dw;
    sq = blockSum(sq);
    const float inv = rsqrtf(sq*(1.f/DMODEL) + 1e-5f);
    float4 gm = *(const float4*)(gamma + c);
    float4 bt = *(const float4*)(beta + c);
    float4 o;
    o.x = dx*inv*gm.x + bt.x;
    o.y = dy*inv*gm.y + bt.y;
    o.z = dz*inv*gm.z + bt.z;
    o.w = dw*inv*gm.w + bt.w;
    *(float4*)(out + (size_t)row*DMODEL + c) = o;
}

// ---------------- launch --------------------------------------------------------
extern "C" void kernel_launch(void* const* d_in, const int* in_sizes, int n_in,
                              void* d_out, int out_size)
{
    const float* x        = (const float*)d_in[0];
    const float* pos_emb  = (const float*)d_in[1];
    const float* memory   = (const float*)d_in[2];
    const float* ubias    = (const float*)d_in[3];
    const float* vbias    = (const float*)d_in[4];
    const float* Wq       = (const float*)d_in[6];
    const float* Wkv      = (const float*)d_in[7];
    const float* Wrel     = (const float*)d_in[8];
    const float* Wo       = (const float*)d_in[9];
    const float* gamma    = (const float*)d_in[10];
    const float* beta     = (const float*)d_in[11];
    float* out    = (float*)d_out;
    float* out_am = out + (size_t)LQ*BATCH*DMODEL;

    qkvr_mma<<<896, 256>>>(x, memory, pos_emb, Wq, Wkv, Wrel);
    bd_mma<<<dim3(TT/128, LQ/128, NG), 256>>>(vbias);
    scores_mma<<<dim3(TT/128, LQ/128, NG), 256>>>(ubias);
    softmax_kernel<<<NG*LQ, 256>>>();
    attnmat_kernel<<<(LQ*TT)/1024, 256>>>(out_am);
    pv_mma<<<dim3(LQ/128, NG), 256>>>();
    wo_mma<<<dim3(16,16), 256>>>(x, Wo);
    ln_kernel<<<LQ*BATCH, 256>>>(gamma, beta, out);
}

// round 5
// speedup vs baseline: 2.3228x; 1.0796x over previous
#include <cuda_runtime.h>
#include <math.h>

#define LQ      1024
#define BATCH   2
#define DMODEL  1024
#define NH      16
#define DHD     64
#define MEMLEN  1024
#define TT      2048
#define NG      (BATCH*NH)
#define SCALE_F 0.125f
#define NEGBIG  -1e30f

// ---------------- scratch ------------------------------------------------------
__device__ float g_q [NG*LQ*DHD];
__device__ float g_k [NG*TT*DHD];
__device__ float g_v [NG*TT*DHD];
__device__ float g_r [NG*TT*DHD];
__device__ float g_s [(size_t)NG*LQ*TT];             // scores -> probs
__device__ float g_av[LQ*BATCH*NH*DHD];
__device__ float g_h [LQ*BATCH*DMODEL];

// ---------------- tf32 mma helpers --------------------------------------------
__device__ __forceinline__ unsigned f2tf(float f){
    unsigned r; asm("cvt.rna.tf32.f32 %0, %1;" : "=r"(r) : "f"(f)); return r;
}
__device__ __forceinline__ void mma_tf32(float c[4],
                                         unsigned a0, unsigned a1, unsigned a2, unsigned a3,
                                         unsigned b0, unsigned b1){
    asm volatile("mma.sync.aligned.m16n8k8.row.col.f32.tf32.tf32.f32 "
        "{%0,%1,%2,%3}, {%4,%5,%6,%7}, {%8,%9}, {%0,%1,%2,%3};"
        : "+f"(c[0]), "+f"(c[1]), "+f"(c[2]), "+f"(c[3])
        : "r"(a0), "r"(a1), "r"(a2), "r"(a3), "r"(b0), "r"(b1));
}

// ---------------- reductions ----------------
__device__ __forceinline__ float blockSum(float v){
    __shared__ float sm[32];
    int lane = threadIdx.x & 31, w = threadIdx.x >> 5;
    #pragma unroll
    for (int o=16;o>0;o>>=1) v += __shfl_xor_sync(0xffffffffu, v, o);
    if (lane==0) sm[w] = v;
    __syncthreads();
    float r = (threadIdx.x < 8) ? sm[threadIdx.x] : 0.f;
    if (w==0){
        #pragma unroll
        for (int o=4;o>0;o>>=1) r += __shfl_xor_sync(0xffffffffu, r, o);
        if (lane==0) sm[0]=r;
    }
    __syncthreads();
    r = sm[0];
    __syncthreads();
    return r;
}
__device__ __forceinline__ float blockMax(float v){
    __shared__ float sm[32];
    int lane = threadIdx.x & 31, w = threadIdx.x >> 5;
    #pragma unroll
    for (int o=16;o>0;o>>=1) v = fmaxf(v, __shfl_xor_sync(0xffffffffu, v, o));
    if (lane==0) sm[w] = v;
    __syncthreads();
    float r = (threadIdx.x < 8) ? sm[threadIdx.x] : -3.4e38f;
    if (w==0){
        #pragma unroll
        for (int o=4;o>0;o>>=1) r = fmaxf(r, __shfl_xor_sync(0xffffffffu, r, o));
        if (lane==0) sm[0]=r;
    }
    __syncthreads();
    r = sm[0];
    __syncthreads();
    return r;
}

// ---------------- QKVR projection GEMM (tf32 MMA, ping-pong pipelined) --------
#define QKVR_SMEM_WORDS (2*128*36 + 2*32*136)
__global__ __launch_bounds__(256) void qkvr_mma(const float* __restrict__ x,
                                                const float* __restrict__ memory,
                                                const float* __restrict__ pos_emb,
                                                const float* __restrict__ Wq,
                                                const float* __restrict__ Wkv,
                                                const float* __restrict__ Wrel)
{
    extern __shared__ unsigned sm_qk[];
    unsigned* AsB = sm_qk;                 // 2 x [128][36]
    unsigned* BsB = sm_qk + 2*128*36;      // 2 x [32][136]

    int bid = blockIdx.x;
    int mode, m0, n0, N;
    const float* W;
    if (bid < 128)      { mode=0; m0=(bid>>3)<<7;  n0=(bid&7)<<7;  N=1024; W=Wq;  }
    else if (bid < 640) { int t=bid-128; mode=1; m0=(t>>4)<<7; n0=(t&15)<<7; N=2048; W=Wkv; }
    else                { int t=bid-640; mode=2; m0=(t>>3)<<7; n0=(t&7)<<7;  N=1024; W=Wrel;}

    const int tid = threadIdx.x;
    const int warp = tid >> 5, lane = tid & 31;
    const int gq = lane >> 2, tq = lane & 3;
    const int wm = (warp >> 2) * 64, wn = (warp & 3) * 32;

    const int a_r = tid >> 1;
    const int a_cb = (tid & 1) * 16;
    const int grow = m0 + a_r;
    const float* arow;
    if (mode==0)      arow = x + (size_t)grow*DMODEL;
    else if (mode==1) arow = (grow < MEMLEN*BATCH) ? memory + (size_t)grow*DMODEL
                                                   : x + (size_t)(grow - MEMLEN*BATCH)*DMODEL;
    else              arow = pos_emb + (size_t)grow*DMODEL;

    const int b_kr = tid >> 3;
    const int b_cb = (tid & 7) * 16;

    float acc[4][4][4];
    #pragma unroll
    for (int mi=0;mi<4;mi++)
        #pragma unroll
        for (int ni=0;ni<4;ni++)
            #pragma unroll
            for (int c=0;c<4;c++) acc[mi][ni][c]=0.f;

    // preload chunk 0 into SMEM buffer 0
    {
        #pragma unroll
        for (int q=0;q<4;q++){
            float4 v = *(const float4*)(arow + a_cb + q*4);
            uint4 u = { f2tf(v.x), f2tf(v.y), f2tf(v.z), f2tf(v.w) };
            *(uint4*)&AsB[a_r*36 + a_cb + q*4] = u;
        }
        const float* brow = W + (size_t)b_kr*N + n0 + b_cb;
        #pragma unroll
        for (int q=0;q<4;q++){
            float4 v = *(const float4*)(brow + q*4);
            uint4 u = { f2tf(v.x), f2tf(v.y), f2tf(v.z), f2tf(v.w) };
            *(uint4*)&BsB[b_kr*136 + b_cb + q*4] = u;
        }
    }
    __syncthreads();

    for (int kc=0;kc<32;kc++){
        unsigned* Ac = AsB + (kc&1)*128*36;
        unsigned* Bc = BsB + (kc&1)*32*136;
        float4 na[4], nb[4];
        if (kc < 31){
            const int k0n = (kc+1)*32;
            #pragma unroll
            for (int q=0;q<4;q++) na[q] = *(const float4*)(arow + k0n + a_cb + q*4);
            const float* brow = W + (size_t)(k0n + b_kr)*N + n0 + b_cb;
            #pragma unroll
            for (int q=0;q<4;q++) nb[q] = *(const float4*)(brow + q*4);
        }
        #pragma unroll
        for (int kk=0;kk<32;kk+=8){
            unsigned a[4][4], b[4][2];
            #pragma unroll
            for (int mi=0;mi<4;mi++){
                int m = wm + mi*16;
                a[mi][0] = Ac[(m+gq  )*36 + kk+tq  ];
                a[mi][1] = Ac[(m+gq+8)*36 + kk+tq  ];
                a[mi][2] = Ac[(m+gq  )*36 + kk+tq+4];
                a[mi][3] = Ac[(m+gq+8)*36 + kk+tq+4];
            }
            #pragma unroll
            for (int ni=0;ni<4;ni++){
                int n = wn + ni*8;
                b[ni][0] = Bc[(kk+tq  )*136 + n+gq];
                b[ni][1] = Bc[(kk+tq+4)*136 + n+gq];
            }
            #pragma unroll
            for (int mi=0;mi<4;mi++)
                #pragma unroll
                for (int ni=0;ni<4;ni++)
                    mma_tf32(acc[mi][ni], a[mi][0],a[mi][1],a[mi][2],a[mi][3], b[ni][0],b[ni][1]);
        }
        if (kc < 31){
            unsigned* An = AsB + ((kc+1)&1)*128*36;
            unsigned* Bn = BsB + ((kc+1)&1)*32*136;
            #pragma unroll
            for (int q=0;q<4;q++){
                uint4 u = { f2tf(na[q].x), f2tf(na[q].y), f2tf(na[q].z), f2tf(na[q].w) };
                *(uint4*)&An[a_r*36 + a_cb + q*4] = u;
                uint4 w = { f2tf(nb[q].x), f2tf(nb[q].y), f2tf(nb[q].z), f2tf(nb[q].w) };
                *(uint4*)&Bn[b_kr*136 + b_cb + q*4] = w;
            }
        }
        __syncthreads();
    }

    #pragma unroll
    for (int mi=0;mi<4;mi++){
        #pragma unroll
        for (int rr=0;rr<2;rr++){
            const int row = m0 + wm + mi*16 + gq + rr*8;
            const int t   = row >> 1, bb = row & 1;
            #pragma unroll
            for (int ni=0;ni<4;ni++){
                const int col = n0 + wn + ni*8 + 2*tq;
                float2 val = { acc[mi][ni][rr*2+0], acc[mi][ni][rr*2+1] };
                if (mode==0){
                    int h = col >> 6, d = col & 63;
                    *(float2*)&g_q[(((size_t)(bb*NH+h)*LQ + t)<<6) + d] = val;
                } else if (mode==1){
                    int c = col; float* dst = g_k;
                    if (c >= NH*DHD){ dst = g_v; c -= NH*DHD; }
                    int h = c >> 6, d = c & 63;
                    *(float2*)&dst[(((size_t)(bb*NH+h)*TT + t)<<6) + d] = val;
                } else {
                    int h = col >> 6, d = col & 63;
                    *(float2*)&g_r[(((size_t)(bb*NH+h)*TT + t)<<6) + d] = val;
                }
            }
        }
    }
}

// ---------------- fused scores: AC + BD (diag-shifted band) in one kernel -----
// scores[i,j] = ( q_i.k_j + u.k_j + q_i.r_p + v.r_p ) * scale,  p = j-i+1023
#define SCORES_SMEM_WORDS (2*128*68 + 64*68 + 128 + 64 + 64 + 64)
__global__ __launch_bounds__(256) void scores_fused_mma(const float* __restrict__ ubias,
                                                        const float* __restrict__ vbias)
{
    const int gg = blockIdx.z, h = gg & (NH-1);
    const int i0 = blockIdx.y << 7;
    const int j0 = blockIdx.x << 7;
    const int delta = j0 - i0;
    if (delta > 1151) return;                 // fully masked tile

    extern __shared__ unsigned sm_sc[];
    unsigned* Qs = sm_sc;                     // [128][68] tf32
    unsigned* Ks = Qs + 128*68;               // [128][68] tf32, later BD stage (float)
    unsigned* Rs = Ks + 128*68;               // [64][68] tf32
    float* BDs = (float*)Ks;
    float* uKs = (float*)(Rs + 64*68);        // [128]
    float* vRs = uKs + 128;                   // [64]
    float* u_s = vRs + 64;                    // [64]
    float* v_s = u_s + 64;                    // [64]

    const int tid = threadIdx.x;
    const int warp = tid >> 5, lane = tid & 31;
    const int gq = lane >> 2, tq = lane & 3;
    const int wm = (warp >> 2) * 64, wn = (warp & 3) * 32;   // AC: 64x32 warp tile
    const int wmb = (warp >> 1) * 32, wnb = (warp & 1) * 32; // BD: 32x32 over 128x64

    // ---- stage Q, K (full K=64) + biases ----
    {
        const int sr = tid >> 1, cb = (tid & 1) * 32;
        const float* qrow = g_q + (((size_t)gg*LQ + i0 + sr) << 6);
        const float* krow = g_k + (((size_t)gg*TT + j0 + sr) << 6);
        #pragma unroll
        for (int q=0;q<8;q++){
            float4 v = *(const float4*)(qrow + cb + q*4);
            uint4 u = { f2tf(v.x), f2tf(v.y), f2tf(v.z), f2tf(v.w) };
            *(uint4*)&Qs[sr*68 + cb + q*4] = u;
            float4 kv = *(const float4*)(krow + cb + q*4);
            uint4 uk = { f2tf(kv.x), f2tf(kv.y), f2tf(kv.z), f2tf(kv.w) };
            *(uint4*)&Ks[sr*68 + cb + q*4] = uk;
        }
        if (tid < 64)       u_s[tid]    = ubias[(h<<6) + tid];
        else if (tid < 128) v_s[tid-64] = vbias[(h<<6) + tid - 64];
    }
    __syncthreads();

    // ---- uK[j] = u . k_j ----
    if (tid < 128){
        float s = 0.f;
        #pragma unroll
        for (int d=0;d<64;d++) s += u_s[d] * __uint_as_float(Ks[tid*68 + d]);
        uKs[tid] = s;
    }

    // ---- AC = Q.K^T ----
    float acc_ac[4][4][4];
    #pragma unroll
    for (int mi=0;mi<4;mi++)
        #pragma unroll
        for (int ni=0;ni<4;ni++)
            #pragma unroll
            for (int c=0;c<4;c++) acc_ac[mi][ni][c]=0.f;

    #pragma unroll
    for (int kk=0;kk<64;kk+=8){
        unsigned a[4][4], b[4][2];
        #pragma unroll
        for (int mi=0;mi<4;mi++){
            int m = wm + mi*16;
            a[mi][0] = Qs[(m+gq  )*68 + kk+tq  ];
            a[mi][1] = Qs[(m+gq+8)*68 + kk+tq  ];
            a[mi][2] = Qs[(m+gq  )*68 + kk+tq+4];
            a[mi][3] = Qs[(m+gq+8)*68 + kk+tq+4];
        }
        #pragma unroll
        for (int ni=0;ni<4;ni++){
            int n = wn + ni*8;
            b[ni][0] = Ks[(n+gq)*68 + kk+tq  ];
            b[ni][1] = Ks[(n+gq)*68 + kk+tq+4];
        }
        #pragma unroll
        for (int mi=0;mi<4;mi++)
            #pragma unroll
            for (int ni=0;ni<4;ni++)
                mma_tf32(acc_ac[mi][ni], a[mi][0],a[mi][1],a[mi][2],a[mi][3], b[ni][0],b[ni][1]);
    }

    // ---- BD band in 4 chunks of 64 p-columns ----
    #pragma unroll 1
    for (int c=0;c<4;c++){
        // stage R chunk
        {
            const int rsr = tid >> 2, rcb = (tid & 3) * 16;
            int rg = delta + 896 + c*64 + rsr;
            rg = min(max(rg, 0), TT-1);
            const float* rrow = g_r + (((size_t)gg*TT + rg) << 6);
            #pragma unroll
            for (int q=0;q<4;q++){
                float4 v = *(const float4*)(rrow + rcb + q*4);
                uint4 u = { f2tf(v.x), f2tf(v.y), f2tf(v.z), f2tf(v.w) };
                *(uint4*)&Rs[rsr*68 + rcb + q*4] = u;
            }
        }
        __syncthreads();   // Rs visible; also guarantees AC mma + prior BDs reads done
        if (tid < 64){
            float s = 0.f;
            #pragma unroll
            for (int d=0;d<64;d++) s += v_s[d] * __uint_as_float(Rs[tid*68 + d]);
            vRs[tid] = s;
        }
        // BD chunk = Q . Rchunk^T (128x64)
        float acc_bd[2][4][4];
        #pragma unroll
        for (int mi=0;mi<2;mi++)
            #pragma unroll
            for (int ni=0;ni<4;ni++)
                #pragma unroll
                for (int e=0;e<4;e++) acc_bd[mi][ni][e]=0.f;
        #pragma unroll
        for (int kk=0;kk<64;kk+=8){
            unsigned a[2][4], b[4][2];
            #pragma unroll
            for (int mi=0;mi<2;mi++){
                int m = wmb + mi*16;
                a[mi][0] = Qs[(m+gq  )*68 + kk+tq  ];
                a[mi][1] = Qs[(m+gq+8)*68 + kk+tq  ];
                a[mi][2] = Qs[(m+gq  )*68 + kk+tq+4];
                a[mi][3] = Qs[(m+gq+8)*68 + kk+tq+4];
            }
            #pragma unroll
            for (int ni=0;ni<4;ni++){
                int n = wnb + ni*8;
                b[ni][0] = Rs[(n+gq)*68 + kk+tq  ];
                b[ni][1] = Rs[(n+gq)*68 + kk+tq+4];
            }
            #pragma unroll
            for (int mi=0;mi<2;mi++)
                #pragma unroll
                for (int ni=0;ni<4;ni++)
                    mma_tf32(acc_bd[mi][ni], a[mi][0],a[mi][1],a[mi][2],a[mi][3], b[ni][0],b[ni][1]);
        }
        __syncthreads();   // vRs visible; safe to overwrite BDs (all prior reads done)
        // stage BD chunk to SMEM
        #pragma unroll
        for (int mi=0;mi<2;mi++)
            #pragma unroll
            for (int rr=0;rr<2;rr++){
                int il = wmb + mi*16 + gq + rr*8;
                #pragma unroll
                for (int ni=0;ni<4;ni++){
                    int pl = wnb + ni*8 + 2*tq;
                    float2 v = { acc_bd[mi][ni][rr*2+0], acc_bd[mi][ni][rr*2+1] };
                    *(float2*)&BDs[il*68 + pl] = v;
                }
            }
        __syncthreads();
        // gather diag-shifted elements into acc_ac
        const int poff = 127 - c*64;
        #pragma unroll
        for (int mi=0;mi<4;mi++)
            #pragma unroll
            for (int rr=0;rr<2;rr++){
                int il = wm + mi*16 + gq + rr*8;
                #pragma unroll
                for (int ni=0;ni<4;ni++){
                    int jl = wn + ni*8 + 2*tq;
                    int pl = jl - il + poff;
                    if (pl >= 0 && pl < 64)
                        acc_ac[mi][ni][rr*2+0] += BDs[il*68 + pl] + vRs[pl];
                    pl++;
                    if (pl >= 0 && pl < 64)
                        acc_ac[mi][ni][rr*2+1] += BDs[il*68 + pl] + vRs[pl];
                }
            }
        __syncthreads();
    }

    // ---- write scores ----
    #pragma unroll
    for (int mi=0;mi<4;mi++)
        #pragma unroll
        for (int rr=0;rr<2;rr++){
            const int i = i0 + wm + mi*16 + gq + rr*8;
            float* srow = g_s + ((size_t)gg*LQ + i)*TT + j0;
            #pragma unroll
            for (int ni=0;ni<4;ni++){
                const int jl = wn + ni*8 + 2*tq;
                float2 val = { (acc_ac[mi][ni][rr*2+0] + uKs[jl  ]) * SCALE_F,
                               (acc_ac[mi][ni][rr*2+1] + uKs[jl+1]) * SCALE_F };
                *(float2*)&srow[jl] = val;
            }
        }
}

// ---------------- softmax: in-place over g_s rows (write-trimmed) -------------
__global__ __launch_bounds__(256) void softmax_kernel()
{
    const int idx = blockIdx.x;            // g*L + i
    const int i   = idx & (LQ-1);
    float* srow = g_s + (size_t)idx*TT;
    const int jmax = i + MEMLEN;
    const int zend = (i & ~127) + 1152;    // pv/attnmat never touch beyond this
    const int tid = threadIdx.x;
    float vals[8];
    float mx = -3.4e38f;
    #pragma unroll
    for (int q=0;q<8;q++){
        int j = q*256 + tid;
        if (j <= jmax){
            float vv = srow[j];
            vals[q] = vv;
            mx = fmaxf(mx, vv);
        } else vals[q] = NEGBIG;
    }
    mx = blockMax(mx);
    float s = 0.f;
    #pragma unroll
    for (int q=0;q<8;q++){
        float e = (vals[q] > -1e29f) ? __expf(vals[q]-mx) : 0.f;
        vals[q] = e; s += e;
    }
    s = blockSum(s);
    const float inv = 1.f / s;
    #pragma unroll
    for (int q=0;q<8;q++){
        int j = q*256 + tid;
        if (j <= jmax)       srow[j] = vals[q] * inv;
        else if (j < zend)   srow[j] = 0.f;
    }
}

// ---------------- attn_matrix = mean over (b,h); masked j emitted as 0 --------
__global__ __launch_bounds__(256) void attnmat_kernel(float* __restrict__ out)
{
    const int i = blockIdx.x;
    const int jmax = i + MEMLEN;
    const int tid = threadIdx.x;
    const float c = 1.f/NG;
    #pragma unroll
    for (int half=0; half<2; half++){
        const int j = half*1024 + tid*4;
        float4 s = {0.f,0.f,0.f,0.f};
        if (j+3 <= jmax){
            #pragma unroll
            for (int g=0; g<NG; g++){
                float4 p = *(const float4*)(g_s + ((size_t)g*LQ + i)*TT + j);
                s.x += p.x; s.y += p.y; s.z += p.z; s.w += p.w;
            }
            s.x*=c; s.y*=c; s.z*=c; s.w*=c;
        } else if (j <= jmax){
            float tmp[4] = {0.f,0.f,0.f,0.f};
            for (int g=0; g<NG; g++){
                const float* row = g_s + ((size_t)g*LQ + i)*TT;
                #pragma unroll
                for (int e=0;e<4;e++) if (j+e <= jmax) tmp[e] += row[j+e];
            }
            s.x=tmp[0]*c; s.y=tmp[1]*c; s.z=tmp[2]*c; s.w=tmp[3]*c;
        }
        *(float4*)(out + (size_t)i*TT + j) = s;
    }
}

// ---------------- PV GEMM (tf32 MMA): av = P @ V ------------------------------
__global__ __launch_bounds__(256) void pv_mma()
{
    const int gg = blockIdx.y, b = gg >> 4, h = gg & (NH-1);
    const int i0 = blockIdx.x << 7;
    const int kmax = min(TT, i0 + 1152);

    __shared__ unsigned As[128][36];
    __shared__ unsigned Vs[32][72];

    const int tid = threadIdx.x;
    const int warp = tid >> 5, lane = tid & 31;
    const int gq = lane >> 2, tq = lane & 3;
    const int wm = (warp >> 1) * 32, wn = (warp & 1) * 32;

    float acc[2][4][4];
    #pragma unroll
    for (int mi=0;mi<2;mi++)
        #pragma unroll
        for (int ni=0;ni<4;ni++)
            #pragma unroll
            for (int c=0;c<4;c++) acc[mi][ni][c]=0.f;

    const int a_r = tid >> 1;
    const int a_cb = (tid & 1) * 16;
    const float* prow = g_s + ((size_t)gg*LQ + i0 + a_r)*TT + a_cb;
    const float* vtile = g_v + ((size_t)gg*TT << 6);
    const int v_jr = tid >> 3;
    const int v_db = (tid & 7) * 8;

    for (int k0=0;k0<kmax;k0+=32){
        #pragma unroll
        for (int q=0;q<4;q++){
            float4 v = *(const float4*)(prow + k0 + q*4);
            uint4 u = { f2tf(v.x), f2tf(v.y), f2tf(v.z), f2tf(v.w) };
            *(uint4*)&As[a_r][a_cb + q*4] = u;
        }
        const float* vr = vtile + (size_t)(k0 + v_jr)*DHD + v_db;
        #pragma unroll
        for (int q=0;q<2;q++){
            float4 v = *(const float4*)(vr + q*4);
            uint4 u = { f2tf(v.x), f2tf(v.y), f2tf(v.z), f2tf(v.w) };
            *(uint4*)&Vs[v_jr][v_db + q*4] = u;
        }
        __syncthreads();
        #pragma unroll
        for (int kk=0;kk<32;kk+=8){
            unsigned a[2][4], b[4][2];
            #pragma unroll
            for (int mi=0;mi<2;mi++){
                int m = wm + mi*16;
                a[mi][0] = As[m+gq  ][kk+tq  ];
                a[mi][1] = As[m+gq+8][kk+tq  ];
                a[mi][2] = As[m+gq  ][kk+tq+4];
                a[mi][3] = As[m+gq+8][kk+tq+4];
            }
            #pragma unroll
            for (int ni=0;ni<4;ni++){
                int n = wn + ni*8;
                b[ni][0] = Vs[kk+tq  ][n+gq];
                b[ni][1] = Vs[kk+tq+4][n+gq];
            }
            #pragma unroll
            for (int mi=0;mi<2;mi++)
                #pragma unroll
                for (int ni=0;ni<4;ni++)
                    mma_tf32(acc[mi][ni], a[mi][0],a[mi][1],a[mi][2],a[mi][3], b[ni][0],b[ni][1]);
        }
        __syncthreads();
    }

    #pragma unroll
    for (int mi=0;mi<2;mi++)
        #pragma unroll
        for (int rr=0;rr<2;rr++){
            const int i = i0 + wm + mi*16 + gq + rr*8;
            float* dst = g_av + (size_t)(i*BATCH + b)*DMODEL + (h<<6);
            #pragma unroll
            for (int ni=0;ni<4;ni++){
                const int d = wn + ni*8 + 2*tq;
                float2 val = { acc[mi][ni][rr*2+0], acc[mi][ni][rr*2+1] };
                *(float2*)&dst[d] = val;
            }
        }
}

// ---------------- Wo GEMM + residual (tf32 MMA): g_h = x + g_av @ Wo ----------
__global__ __launch_bounds__(256) void wo_mma(const float* __restrict__ x,
                                              const float* __restrict__ Wo)
{
    const int m0 = blockIdx.y << 7;
    const int n0 = blockIdx.x << 6;

    __shared__ unsigned As[128][36];
    __shared__ unsigned Bs[32][72];

    const int tid = threadIdx.x;
    const int warp = tid >> 5, lane = tid & 31;
    const int gq = lane >> 2, tq = lane & 3;
    const int wm = (warp >> 1) * 32, wn = (warp & 1) * 32;

    float acc[2][4][4];
    #pragma unroll
    for (int mi=0;mi<2;mi++)
        #pragma unroll
        for (int ni=0;ni<4;ni++)
            #pragma unroll
            for (int c=0;c<4;c++) acc[mi][ni][c]=0.f;

    const int a_r = tid >> 1;
    const int a_cb = (tid & 1) * 16;
    const float* arow = g_av + (size_t)(m0 + a_r)*DMODEL + a_cb;
    const int b_kr = tid >> 3;
    const int b_db = (tid & 7) * 8;

    for (int k0=0;k0<DMODEL;k0+=32){
        #pragma unroll
        for (int q=0;q<4;q++){
            float4 v = *(const float4*)(arow + k0 + q*4);
            uint4 u = { f2tf(v.x), f2tf(v.y), f2tf(v.z), f2tf(v.w) };
            *(uint4*)&As[a_r][a_cb + q*4] = u;
        }
        const float* brow = Wo + (size_t)(k0 + b_kr)*DMODEL + n0 + b_db;
        #pragma unroll
        for (int q=0;q<2;q++){
            float4 v = *(const float4*)(brow + q*4);
            uint4 u = { f2tf(v.x), f2tf(v.y), f2tf(v.z), f2tf(v.w) };
            *(uint4*)&Bs[b_kr][b_db + q*4] = u;
        }
        __syncthreads();
        #pragma unroll
        for (int kk=0;kk<32;kk+=8){
            unsigned a[2][4], b[4][2];
            #pragma unroll
            for (int mi=0;mi<2;mi++){
                int m = wm + mi*16;
                a[mi][0] = As[m+gq  ][kk+tq  ];
                a[mi][1] = As[m+gq+8][kk+tq  ];
                a[mi][2] = As[m+gq  ][kk+tq+4];
                a[mi][3] = As[m+gq+8][kk+tq+4];
            }
            #pragma unroll
            for (int ni=0;ni<4;ni++){
                int n = wn + ni*8;
                b[ni][0] = Bs[kk+tq  ][n+gq];
                b[ni][1] = Bs[kk+tq+4][n+gq];
            }
            #pragma unroll
            for (int mi=0;mi<2;mi++)
                #pragma unroll
                for (int ni=0;ni<4;ni++)
                    mma_tf32(acc[mi][ni], a[mi][0],a[mi][1],a[mi][2],a[mi][3], b[ni][0],b[ni][1]);
        }
        __syncthreads();
    }

    #pragma unroll
    for (int mi=0;mi<2;mi++)
        #pragma unroll
        for (int rr=0;rr<2;rr++){
            const int row = m0 + wm + mi*16 + gq + rr*8;
            #pragma unroll
            for (int ni=0;ni<4;ni++){
                const int col = n0 + wn + ni*8 + 2*tq;
                float2 xv = *(const float2*)&x[(size_t)row*DMODEL + col];
                float2 val = { acc[mi][ni][rr*2+0] + xv.x,
                               acc[mi][ni][rr*2+1] + xv.y };
                *(float2*)&g_h[(size_t)row*DMODEL + col] = val;
            }
        }
}

// ---------------- layernorm ----------------------------------------------------
__global__ __launch_bounds__(256) void ln_kernel(const float* __restrict__ gamma,
                                                 const float* __restrict__ beta,
                                                 float* __restrict__ out)
{
    const int row = blockIdx.x;
    const float* hr = g_h + (size_t)row*DMODEL;
    const int c = threadIdx.x * 4;
    float4 v = *(const float4*)(hr + c);
    float s = v.x+v.y+v.z+v.w;
    s = blockSum(s);
    const float mu = s * (1.f/DMODEL);
    float dx = v.x-mu, dy = v.y-mu, dz = v.z-mu, dw = v.w-mu;
    float sq = dx*dx+dy*dy+dz*dz+dw*dw;
    sq = blockSum(sq);
    const float inv = rsqrtf(sq*(1.f/DMODEL) + 1e-5f);
    float4 gm = *(const float4*)(gamma + c);
    float4 bt = *(const float4*)(beta + c);
    float4 o;
    o.x = dx*inv*gm.x + bt.x;
    o.y = dy*inv*gm.y + bt.y;
    o.z = dz*inv*gm.z + bt.z;
    o.w = dw*inv*gm.w + bt.w;
    *(float4*)(out + (size_t)row*DMODEL + c) = o;
}

// ---------------- launch --------------------------------------------------------
extern "C" void kernel_launch(void* const* d_in, const int* in_sizes, int n_in,
                              void* d_out, int out_size)
{
    const float* x        = (const float*)d_in[0];
    const float* pos_emb  = (const float*)d_in[1];
    const float* memory   = (const float*)d_in[2];
    const float* ubias    = (const float*)d_in[3];
    const float* vbias    = (const float*)d_in[4];
    const float* Wq       = (const float*)d_in[6];
    const float* Wkv      = (const float*)d_in[7];
    const float* Wrel     = (const float*)d_in[8];
    const float* Wo       = (const float*)d_in[9];
    const float* gamma    = (const float*)d_in[10];
    const float* beta     = (const float*)d_in[11];
    float* out    = (float*)d_out;
    float* out_am = out + (size_t)LQ*BATCH*DMODEL;

    const int qkvr_smem   = QKVR_SMEM_WORDS * 4;      // 71680 B
    const int scores_smem = SCORES_SMEM_WORDS * 4;    // 88320 B
    cudaFuncSetAttribute(qkvr_mma, cudaFuncAttributeMaxDynamicSharedMemorySize, qkvr_smem);
    cudaFuncSetAttribute(scores_fused_mma, cudaFuncAttributeMaxDynamicSharedMemorySize, scores_smem);

    qkvr_mma<<<896, 256, qkvr_smem>>>(x, memory, pos_emb, Wq, Wkv, Wrel);
    scores_fused_mma<<<dim3(TT/128, LQ/128, NG), 256, scores_smem>>>(ubias, vbias);
    softmax_kernel<<<NG*LQ, 256>>>();
    attnmat_kernel<<<LQ, 256>>>(out_am);
    pv_mma<<<dim3(LQ/128, NG), 256>>>();
    wo_mma<<<dim3(16,16), 256>>>(x, Wo);
    ln_kernel<<<LQ*BATCH, 256>>>(gamma, beta, out);
}

// round 6
// speedup vs baseline: 3.4092x; 1.4677x over previous
#include <cuda_runtime.h>
#include <cuda_fp16.h>
#include <math.h>

#define LQ      1024
#define BATCH   2
#define DMODEL  1024
#define NH      16
#define DHD     64
#define MEMLEN  1024
#define TT      2048
#define NG      (BATCH*NH)
#define SCALE_F 0.125f
#define NEGBIG  -1e30f

// ---------------- scratch (halves for all MMA operands) ------------------------
__device__ __half g_q [NG*LQ*DHD];
__device__ __half g_k [NG*TT*DHD];
__device__ __half g_v [NG*TT*DHD];
__device__ __half g_r [NG*TT*DHD];
__device__ float  g_s [(size_t)NG*LQ*TT];            // scores -> probs (fp32)
__device__ __half g_av[LQ*BATCH*NH*DHD];
__device__ float  g_h [LQ*BATCH*DMODEL];

// ---------------- fp16 mma helpers --------------------------------------------
__device__ __forceinline__ unsigned pack_h2(float a, float b){
    __half2 h = __floats2half2_rn(a, b);
    return *reinterpret_cast<unsigned*>(&h);
}
__device__ __forceinline__ void mma_f16(float c[4],
                                        unsigned a0, unsigned a1, unsigned a2, unsigned a3,
                                        unsigned b0, unsigned b1){
    asm volatile("mma.sync.aligned.m16n8k16.row.col.f32.f16.f16.f32 "
        "{%0,%1,%2,%3}, {%4,%5,%6,%7}, {%8,%9}, {%0,%1,%2,%3};"
        : "+f"(c[0]), "+f"(c[1]), "+f"(c[2]), "+f"(c[3])
        : "r"(a0), "r"(a1), "r"(a2), "r"(a3), "r"(b0), "r"(b1));
}

// ---------------- reductions ----------------
__device__ __forceinline__ float blockSum(float v){
    __shared__ float sm[32];
    int lane = threadIdx.x & 31, w = threadIdx.x >> 5;
    #pragma unroll
    for (int o=16;o>0;o>>=1) v += __shfl_xor_sync(0xffffffffu, v, o);
    if (lane==0) sm[w] = v;
    __syncthreads();
    float r = (threadIdx.x < 8) ? sm[threadIdx.x] : 0.f;
    if (w==0){
        #pragma unroll
        for (int o=4;o>0;o>>=1) r += __shfl_xor_sync(0xffffffffu, r, o);
        if (lane==0) sm[0]=r;
    }
    __syncthreads();
    r = sm[0];
    __syncthreads();
    return r;
}
__device__ __forceinline__ float blockMax(float v){
    __shared__ float sm[32];
    int lane = threadIdx.x & 31, w = threadIdx.x >> 5;
    #pragma unroll
    for (int o=16;o>0;o>>=1) v = fmaxf(v, __shfl_xor_sync(0xffffffffu, v, o));
    if (lane==0) sm[w] = v;
    __syncthreads();
    float r = (threadIdx.x < 8) ? sm[threadIdx.x] : -3.4e38f;
    if (w==0){
        #pragma unroll
        for (int o=4;o>0;o>>=1) r = fmaxf(r, __shfl_xor_sync(0xffffffffu, r, o));
        if (lane==0) sm[0]=r;
    }
    __syncthreads();
    r = sm[0];
    __syncthreads();
    return r;
}

// ---------------- QKVR projection GEMM (fp16 MMA, ping-pong pipelined) --------
// A staged as half [2][128][40] (k-pairs natural); B staged as half2 [2][16][136]
// holding (W[k][n], W[k+1][n]) pairs.
__global__ __launch_bounds__(256) void qkvr_mma(const float* __restrict__ x,
                                                const float* __restrict__ memory,
                                                const float* __restrict__ pos_emb,
                                                const float* __restrict__ Wq,
                                                const float* __restrict__ Wkv,
                                                const float* __restrict__ Wrel)
{
    __shared__ __half   AsB[2*128*40];
    __shared__ unsigned BsB[2*16*136];

    int bid = blockIdx.x;
    int mode, m0, n0, N;
    const float* W;
    if (bid < 128)      { mode=0; m0=(bid>>3)<<7;  n0=(bid&7)<<7;  N=1024; W=Wq;  }
    else if (bid < 640) { int t=bid-128; mode=1; m0=(t>>4)<<7; n0=(t&15)<<7; N=2048; W=Wkv; }
    else                { int t=bid-640; mode=2; m0=(t>>3)<<7; n0=(t&7)<<7;  N=1024; W=Wrel;}

    const int tid = threadIdx.x;
    const int warp = tid >> 5, lane = tid & 31;
    const int gq = lane >> 2, tq = lane & 3;
    const int wm = (warp >> 2) * 64, wn = (warp & 3) * 32;

    const int a_r = tid >> 1;
    const int a_cb = (tid & 1) * 16;          // halves / floats offset within K=32
    const int grow = m0 + a_r;
    const float* arow;
    if (mode==0)      arow = x + (size_t)grow*DMODEL;
    else if (mode==1) arow = (grow < MEMLEN*BATCH) ? memory + (size_t)grow*DMODEL
                                                   : x + (size_t)(grow - MEMLEN*BATCH)*DMODEL;
    else              arow = pos_emb + (size_t)grow*DMODEL;

    const int b_k2 = tid >> 4;                // 0..15 (k-pair row)
    const int b_cb = (tid & 15) * 8;          // n offset

    float acc[4][4][4];
    #pragma unroll
    for (int mi=0;mi<4;mi++)
        #pragma unroll
        for (int ni=0;ni<4;ni++)
            #pragma unroll
            for (int c=0;c<4;c++) acc[mi][ni][c]=0.f;

    // stage helper (inline): A 16 floats -> 8 half2; B rows k,k+1 x 8 floats -> 8 half2
    {
        float4 va[4], vb[4];
        #pragma unroll
        for (int q=0;q<4;q++) va[q] = *(const float4*)(arow + a_cb + q*4);
        const float* br = W + (size_t)(2*b_k2)*N + n0 + b_cb;
        vb[0] = *(const float4*)(br);     vb[1] = *(const float4*)(br+4);
        vb[2] = *(const float4*)(br+N);   vb[3] = *(const float4*)(br+N+4);
        unsigned u[8];
        #pragma unroll
        for (int q=0;q<4;q++){ u[2*q]=pack_h2(va[q].x,va[q].y); u[2*q+1]=pack_h2(va[q].z,va[q].w); }
        __half* Ad = AsB + a_r*40 + a_cb;
        *(uint4*)Ad     = *(uint4*)&u[0];
        *(uint4*)(Ad+8) = *(uint4*)&u[4];
        float r0[8] = {vb[0].x,vb[0].y,vb[0].z,vb[0].w, vb[1].x,vb[1].y,vb[1].z,vb[1].w};
        float r1[8] = {vb[2].x,vb[2].y,vb[2].z,vb[2].w, vb[3].x,vb[3].y,vb[3].z,vb[3].w};
        unsigned w8[8];
        #pragma unroll
        for (int e=0;e<8;e++) w8[e] = pack_h2(r0[e], r1[e]);
        unsigned* Bd = BsB + b_k2*136 + b_cb;
        *(uint4*)Bd     = *(uint4*)&w8[0];
        *(uint4*)(Bd+4) = *(uint4*)&w8[4];
    }
    __syncthreads();

    for (int kc=0;kc<32;kc++){
        const __half*   Ac = AsB + (kc&1)*128*40;
        const unsigned* Ac2 = (const unsigned*)Ac;          // stride 20
        const unsigned* Bc = BsB + (kc&1)*16*136;
        float4 va[4], vb[4];
        if (kc < 31){
            const int k0n = (kc+1)*32;
            #pragma unroll
            for (int q=0;q<4;q++) va[q] = *(const float4*)(arow + k0n + a_cb + q*4);
            const float* br = W + (size_t)(k0n + 2*b_k2)*N + n0 + b_cb;
            vb[0] = *(const float4*)(br);     vb[1] = *(const float4*)(br+4);
            vb[2] = *(const float4*)(br+N);   vb[3] = *(const float4*)(br+N+4);
        }
        #pragma unroll
        for (int kk=0;kk<32;kk+=16){
            unsigned a[4][4], b[4][2];
            const int k2 = kk >> 1;
            #pragma unroll
            for (int mi=0;mi<4;mi++){
                int m = wm + mi*16;
                a[mi][0] = Ac2[(m+gq  )*20 + k2 + tq  ];
                a[mi][1] = Ac2[(m+gq+8)*20 + k2 + tq  ];
                a[mi][2] = Ac2[(m+gq  )*20 + k2 + tq+4];
                a[mi][3] = Ac2[(m+gq+8)*20 + k2 + tq+4];
            }
            #pragma unroll
            for (int ni=0;ni<4;ni++){
                int n = wn + ni*8 + gq;
                b[ni][0] = Bc[(k2+tq  )*136 + n];
                b[ni][1] = Bc[(k2+tq+4)*136 + n];
            }
            #pragma unroll
            for (int mi=0;mi<4;mi++)
                #pragma unroll
                for (int ni=0;ni<4;ni++)
                    mma_f16(acc[mi][ni], a[mi][0],a[mi][1],a[mi][2],a[mi][3], b[ni][0],b[ni][1]);
        }
        if (kc < 31){
            __half* An = AsB + ((kc+1)&1)*128*40 + a_r*40 + a_cb;
            unsigned u[8];
            #pragma unroll
            for (int q=0;q<4;q++){ u[2*q]=pack_h2(va[q].x,va[q].y); u[2*q+1]=pack_h2(va[q].z,va[q].w); }
            *(uint4*)An     = *(uint4*)&u[0];
            *(uint4*)(An+8) = *(uint4*)&u[4];
            float r0[8] = {vb[0].x,vb[0].y,vb[0].z,vb[0].w, vb[1].x,vb[1].y,vb[1].z,vb[1].w};
            float r1[8] = {vb[2].x,vb[2].y,vb[2].z,vb[2].w, vb[3].x,vb[3].y,vb[3].z,vb[3].w};
            unsigned w8[8];
            #pragma unroll
            for (int e=0;e<8;e++) w8[e] = pack_h2(r0[e], r1[e]);
            unsigned* Bn = BsB + ((kc+1)&1)*16*136 + b_k2*136 + b_cb;
            *(uint4*)Bn     = *(uint4*)&w8[0];
            *(uint4*)(Bn+4) = *(uint4*)&w8[4];
        }
        __syncthreads();
    }

    #pragma unroll
    for (int mi=0;mi<4;mi++){
        #pragma unroll
        for (int rr=0;rr<2;rr++){
            const int row = m0 + wm + mi*16 + gq + rr*8;
            const int t   = row >> 1, bb = row & 1;
            #pragma unroll
            for (int ni=0;ni<4;ni++){
                const int col = n0 + wn + ni*8 + 2*tq;
                unsigned hv = pack_h2(acc[mi][ni][rr*2+0], acc[mi][ni][rr*2+1]);
                if (mode==0){
                    int h = col >> 6, d = col & 63;
                    *reinterpret_cast<unsigned*>(&g_q[(((size_t)(bb*NH+h)*LQ + t)<<6) + d]) = hv;
                } else if (mode==1){
                    int c = col; __half* dst = g_k;
                    if (c >= NH*DHD){ dst = g_v; c -= NH*DHD; }
                    int h = c >> 6, d = c & 63;
                    *reinterpret_cast<unsigned*>(&dst[(((size_t)(bb*NH+h)*TT + t)<<6) + d]) = hv;
                } else {
                    int h = col >> 6, d = col & 63;
                    *reinterpret_cast<unsigned*>(&g_r[(((size_t)(bb*NH+h)*TT + t)<<6) + d]) = hv;
                }
            }
        }
    }
}

// ---------------- fused scores: AC + BD (diag-shifted band), fp16 MMA ---------
// SMEM: Qs half[128][72] | region{ Ks half[128][72] / BDs float[128][68] } |
//       Rs half[64][72] | uKs[128] vRs[64] u_s[64] v_s[64]
#define SC_SMEM_BYTES (128*72*2 + 128*68*4 + 64*72*2 + (128+64+64+64)*4)
__global__ __launch_bounds__(256) void scores_fused_mma(const float* __restrict__ ubias,
                                                        const float* __restrict__ vbias)
{
    const int gg = blockIdx.z, h = gg & (NH-1);
    const int i0 = blockIdx.y << 7;
    const int j0 = blockIdx.x << 7;
    const int delta = j0 - i0;
    if (delta > 1151) return;

    extern __shared__ char sm_raw[];
    __half* Qs = (__half*)sm_raw;                         // [128][72]
    char*   reg2 = sm_raw + 128*72*2;
    __half* Ks = (__half*)reg2;                           // [128][72] (dies after AC)
    float*  BDs = (float*)reg2;                           // [128][68] (aliases Ks)
    __half* Rs = (__half*)(reg2 + 128*68*4);              // [64][72]
    float*  uKs = (float*)(reg2 + 128*68*4 + 64*72*2);    // [128]
    float*  vRs = uKs + 128;                              // [64]
    float*  u_s = vRs + 64;
    float*  v_s = u_s + 64;

    const int tid = threadIdx.x;
    const int warp = tid >> 5, lane = tid & 31;
    const int gq = lane >> 2, tq = lane & 3;
    const int wm = (warp >> 2) * 64, wn = (warp & 3) * 32;
    const int wmb = (warp >> 1) * 32, wnb = (warp & 1) * 32;

    const unsigned* Qs2 = (const unsigned*)Qs;            // stride 36
    const unsigned* Ks2 = (const unsigned*)Ks;
    const unsigned* Rs2 = (const unsigned*)Rs;

    // ---- stage Q, K (direct half copy) + biases ----
    {
        const int sr = tid >> 1, cb = (tid & 1) * 32;     // halves
        const __half* qrow = g_q + (((size_t)gg*LQ + i0 + sr) << 6) + cb;
        const __half* krow = g_k + (((size_t)gg*TT + j0 + sr) << 6) + cb;
        #pragma unroll
        for (int q=0;q<4;q++){
            *(uint4*)&Qs[sr*72 + cb + q*8] = *(const uint4*)(qrow + q*8);
            *(uint4*)&Ks[sr*72 + cb + q*8] = *(const uint4*)(krow + q*8);
        }
        if (tid < 64)       u_s[tid]    = ubias[(h<<6) + tid];
        else if (tid < 128) v_s[tid-64] = vbias[(h<<6) + tid - 64];
    }
    __syncthreads();

    // ---- uK[j] = u . k_j ----
    if (tid < 128){
        float s = 0.f;
        #pragma unroll
        for (int d=0;d<64;d++) s += u_s[d] * __half2float(Ks[tid*72 + d]);
        uKs[tid] = s;
    }

    // ---- AC = Q.K^T ----
    float acc_ac[4][4][4];
    #pragma unroll
    for (int mi=0;mi<4;mi++)
        #pragma unroll
        for (int ni=0;ni<4;ni++)
            #pragma unroll
            for (int c=0;c<4;c++) acc_ac[mi][ni][c]=0.f;

    #pragma unroll
    for (int kk=0;kk<64;kk+=16){
        const int k2 = kk >> 1;
        unsigned a[4][4], b[4][2];
        #pragma unroll
        for (int mi=0;mi<4;mi++){
            int m = wm + mi*16;
            a[mi][0] = Qs2[(m+gq  )*36 + k2 + tq  ];
            a[mi][1] = Qs2[(m+gq+8)*36 + k2 + tq  ];
            a[mi][2] = Qs2[(m+gq  )*36 + k2 + tq+4];
            a[mi][3] = Qs2[(m+gq+8)*36 + k2 + tq+4];
        }
        #pragma unroll
        for (int ni=0;ni<4;ni++){
            int n = wn + ni*8 + gq;
            b[ni][0] = Ks2[n*36 + k2 + tq  ];
            b[ni][1] = Ks2[n*36 + k2 + tq+4];
        }
        #pragma unroll
        for (int mi=0;mi<4;mi++)
            #pragma unroll
            for (int ni=0;ni<4;ni++)
                mma_f16(acc_ac[mi][ni], a[mi][0],a[mi][1],a[mi][2],a[mi][3], b[ni][0],b[ni][1]);
    }

    // ---- BD band in 4 chunks of 64 p-columns ----
    #pragma unroll 1
    for (int c=0;c<4;c++){
        {
            const int rsr = tid >> 2, rcb = (tid & 3) * 16;
            int rg = delta + 896 + c*64 + rsr;
            rg = min(max(rg, 0), TT-1);
            const __half* rrow = g_r + (((size_t)gg*TT + rg) << 6) + rcb;
            *(uint4*)&Rs[rsr*72 + rcb]     = *(const uint4*)(rrow);
            *(uint4*)&Rs[rsr*72 + rcb + 8] = *(const uint4*)(rrow + 8);
        }
        __syncthreads();   // Rs visible; AC reads of Ks complete (c==0) / prior BDs reads done
        if (tid < 64){
            float s = 0.f;
            #pragma unroll
            for (int d=0;d<64;d++) s += v_s[d] * __half2float(Rs[tid*72 + d]);
            vRs[tid] = s;
        }
        float acc_bd[2][4][4];
        #pragma unroll
        for (int mi=0;mi<2;mi++)
            #pragma unroll
            for (int ni=0;ni<4;ni++)
                #pragma unroll
                for (int e=0;e<4;e++) acc_bd[mi][ni][e]=0.f;
        #pragma unroll
        for (int kk=0;kk<64;kk+=16){
            const int k2 = kk >> 1;
            unsigned a[2][4], b[4][2];
            #pragma unroll
            for (int mi=0;mi<2;mi++){
                int m = wmb + mi*16;
                a[mi][0] = Qs2[(m+gq  )*36 + k2 + tq  ];
                a[mi][1] = Qs2[(m+gq+8)*36 + k2 + tq  ];
                a[mi][2] = Qs2[(m+gq  )*36 + k2 + tq+4];
                a[mi][3] = Qs2[(m+gq+8)*36 + k2 + tq+4];
            }
            #pragma unroll
            for (int ni=0;ni<4;ni++){
                int n = wnb + ni*8 + gq;
                b[ni][0] = Rs2[n*36 + k2 + tq  ];
                b[ni][1] = Rs2[n*36 + k2 + tq+4];
            }
            #pragma unroll
            for (int mi=0;mi<2;mi++)
                #pragma unroll
                for (int ni=0;ni<4;ni++)
                    mma_f16(acc_bd[mi][ni], a[mi][0],a[mi][1],a[mi][2],a[mi][3], b[ni][0],b[ni][1]);
        }
        __syncthreads();   // vRs visible; safe to overwrite BDs
        #pragma unroll
        for (int mi=0;mi<2;mi++)
            #pragma unroll
            for (int rr=0;rr<2;rr++){
                int il = wmb + mi*16 + gq + rr*8;
                #pragma unroll
                for (int ni=0;ni<4;ni++){
                    int pl = wnb + ni*8 + 2*tq;
                    float2 v = { acc_bd[mi][ni][rr*2+0], acc_bd[mi][ni][rr*2+1] };
                    *(float2*)&BDs[il*68 + pl] = v;
                }
            }
        __syncthreads();
        const int poff = 127 - c*64;
        #pragma unroll
        for (int mi=0;mi<4;mi++)
            #pragma unroll
            for (int rr=0;rr<2;rr++){
                int il = wm + mi*16 + gq + rr*8;
                #pragma unroll
                for (int ni=0;ni<4;ni++){
                    int jl = wn + ni*8 + 2*tq;
                    int pl = jl - il + poff;
                    if (pl >= 0 && pl < 64)
                        acc_ac[mi][ni][rr*2+0] += BDs[il*68 + pl] + vRs[pl];
                    pl++;
                    if (pl >= 0 && pl < 64)
                        acc_ac[mi][ni][rr*2+1] += BDs[il*68 + pl] + vRs[pl];
                }
            }
        __syncthreads();
    }

    // ---- write scores (fp32) ----
    #pragma unroll
    for (int mi=0;mi<4;mi++)
        #pragma unroll
        for (int rr=0;rr<2;rr++){
            const int i = i0 + wm + mi*16 + gq + rr*8;
            float* srow = g_s + ((size_t)gg*LQ + i)*TT + j0;
            #pragma unroll
            for (int ni=0;ni<4;ni++){
                const int jl = wn + ni*8 + 2*tq;
                float2 val = { (acc_ac[mi][ni][rr*2+0] + uKs[jl  ]) * SCALE_F,
                               (acc_ac[mi][ni][rr*2+1] + uKs[jl+1]) * SCALE_F };
                *(float2*)&srow[jl] = val;
            }
        }
}

// ---------------- softmax: in-place over g_s rows (write-trimmed) -------------
__global__ __launch_bounds__(256) void softmax_kernel()
{
    const int idx = blockIdx.x;
    const int i   = idx & (LQ-1);
    float* srow = g_s + (size_t)idx*TT;
    const int jmax = i + MEMLEN;
    const int zend = (i & ~127) + 1152;
    const int tid = threadIdx.x;
    float vals[8];
    float mx = -3.4e38f;
    #pragma unroll
    for (int q=0;q<8;q++){
        int j = q*256 + tid;
        if (j <= jmax){
            float vv = srow[j];
            vals[q] = vv;
            mx = fmaxf(mx, vv);
        } else vals[q] = NEGBIG;
    }
    mx = blockMax(mx);
    float s = 0.f;
    #pragma unroll
    for (int q=0;q<8;q++){
        float e = (vals[q] > -1e29f) ? __expf(vals[q]-mx) : 0.f;
        vals[q] = e; s += e;
    }
    s = blockSum(s);
    const float inv = 1.f / s;
    #pragma unroll
    for (int q=0;q<8;q++){
        int j = q*256 + tid;
        if (j <= jmax)       srow[j] = vals[q] * inv;
        else if (j < zend)   srow[j] = 0.f;
    }
}

// ---------------- attn_matrix = mean over (b,h); 4-way g-split + SMEM reduce --
__global__ __launch_bounds__(256) void attnmat_kernel(float* __restrict__ out)
{
    const int i  = blockIdx.y;
    const int j0 = blockIdx.x << 8;           // 8 tiles of 256
    const int jmax = i + MEMLEN;
    const int tid = threadIdx.x;
    const int jq = tid & 63;
    const int gsel = tid >> 6;
    const int j = j0 + jq*4;
    __shared__ float4 red[256];

    float4 s = {0.f,0.f,0.f,0.f};
    if (j0 <= jmax){
        #pragma unroll
        for (int gi=0; gi<8; gi++){
            int g = gsel + gi*4;
            float4 p = *(const float4*)(g_s + ((size_t)g*LQ + i)*TT + j);
            s.x+=p.x; s.y+=p.y; s.z+=p.z; s.w+=p.w;
        }
        if (j+0 > jmax) s.x = 0.f;
        if (j+1 > jmax) s.y = 0.f;
        if (j+2 > jmax) s.z = 0.f;
        if (j+3 > jmax) s.w = 0.f;
    }
    red[tid] = s;
    __syncthreads();
    if (tid < 64){
        float4 a=red[tid], b=red[tid+64], c=red[tid+128], d=red[tid+192];
        const float k = 1.f/NG;
        float4 o = { (a.x+b.x+c.x+d.x)*k, (a.y+b.y+c.y+d.y)*k,
                     (a.z+b.z+c.z+d.z)*k, (a.w+b.w+c.w+d.w)*k };
        *(float4*)(out + (size_t)i*TT + j0 + tid*4) = o;
    }
}

// ---------------- PV GEMM (fp16 MMA): av = P @ V ------------------------------
__global__ __launch_bounds__(256) void pv_mma()
{
    const int gg = blockIdx.y, b = gg >> 4, h = gg & (NH-1);
    const int i0 = blockIdx.x << 7;
    const int kmax = min(TT, i0 + 1152);

    __shared__ __half   As[128*40];
    __shared__ unsigned Vs[16*72];      // half2 pairs (V[k][d], V[k+1][d])

    const int tid = threadIdx.x;
    const int warp = tid >> 5, lane = tid & 31;
    const int gq = lane >> 2, tq = lane & 3;
    const int wm = (warp >> 1) * 32, wn = (warp & 1) * 32;
    const unsigned* As2 = (const unsigned*)As;   // stride 20

    float acc[2][4][4];
    #pragma unroll
    for (int mi=0;mi<2;mi++)
        #pragma unroll
        for (int ni=0;ni<4;ni++)
            #pragma unroll
            for (int c=0;c<4;c++) acc[mi][ni][c]=0.f;

    const int a_r = tid >> 1;
    const int a_cb = (tid & 1) * 16;
    const float* prow = g_s + ((size_t)gg*LQ + i0 + a_r)*TT + a_cb;
    const __half* vtile = g_v + ((size_t)gg*TT << 6);
    const int v_k2 = tid >> 4;           // 0..15
    const int v_cb = (tid & 15) * 4;     // d offset

    for (int k0=0;k0<kmax;k0+=32){
        {
            unsigned u[8];
            #pragma unroll
            for (int q=0;q<4;q++){
                float4 v = *(const float4*)(prow + k0 + q*4);
                u[2*q]=pack_h2(v.x,v.y); u[2*q+1]=pack_h2(v.z,v.w);
            }
            __half* Ad = As + a_r*40 + a_cb;
            *(uint4*)Ad     = *(uint4*)&u[0];
            *(uint4*)(Ad+8) = *(uint4*)&u[4];
            const __half* vr0 = vtile + (size_t)(k0 + 2*v_k2)*DHD + v_cb;
            const __half* vr1 = vr0 + DHD;
            unsigned w4[4];
            #pragma unroll
            for (int e=0;e<4;e++){
                __half2 hh = __halves2half2(vr0[e], vr1[e]);
                w4[e] = *reinterpret_cast<unsigned*>(&hh);
            }
            *(uint4*)&Vs[v_k2*72 + v_cb] = *(uint4*)&w4[0];
        }
        __syncthreads();
        #pragma unroll
        for (int kk=0;kk<32;kk+=16){
            const int k2 = kk >> 1;
            unsigned a[2][4], bfr[4][2];
            #pragma unroll
            for (int mi=0;mi<2;mi++){
                int m = wm + mi*16;
                a[mi][0] = As2[(m+gq  )*20 + k2 + tq  ];
                a[mi][1] = As2[(m+gq+8)*20 + k2 + tq  ];
                a[mi][2] = As2[(m+gq  )*20 + k2 + tq+4];
                a[mi][3] = As2[(m+gq+8)*20 + k2 + tq+4];
            }
            #pragma unroll
            for (int ni=0;ni<4;ni++){
                int n = wn + ni*8 + gq;
                bfr[ni][0] = Vs[(k2+tq  )*72 + n];
                bfr[ni][1] = Vs[(k2+tq+4)*72 + n];
            }
            #pragma unroll
            for (int mi=0;mi<2;mi++)
                #pragma unroll
                for (int ni=0;ni<4;ni++)
                    mma_f16(acc[mi][ni], a[mi][0],a[mi][1],a[mi][2],a[mi][3], bfr[ni][0],bfr[ni][1]);
        }
        __syncthreads();
    }

    #pragma unroll
    for (int mi=0;mi<2;mi++)
        #pragma unroll
        for (int rr=0;rr<2;rr++){
            const int i = i0 + wm + mi*16 + gq + rr*8;
            __half* dst = g_av + (size_t)(i*BATCH + b)*DMODEL + (h<<6);
            #pragma unroll
            for (int ni=0;ni<4;ni++){
                const int d = wn + ni*8 + 2*tq;
                unsigned hv = pack_h2(acc[mi][ni][rr*2+0], acc[mi][ni][rr*2+1]);
                *reinterpret_cast<unsigned*>(&dst[d]) = hv;
            }
        }
}

// ---------------- Wo GEMM + residual (fp16 MMA): g_h = x + g_av @ Wo ----------
__global__ __launch_bounds__(256) void wo_mma(const float* __restrict__ x,
                                              const float* __restrict__ Wo)
{
    const int m0 = blockIdx.y << 7;
    const int n0 = blockIdx.x << 6;

    __shared__ __half   As[128*40];
    __shared__ unsigned Bs[16*72];

    const int tid = threadIdx.x;
    const int warp = tid >> 5, lane = tid & 31;
    const int gq = lane >> 2, tq = lane & 3;
    const int wm = (warp >> 1) * 32, wn = (warp & 1) * 32;
    const unsigned* As2 = (const unsigned*)As;

    float acc[2][4][4];
    #pragma unroll
    for (int mi=0;mi<2;mi++)
        #pragma unroll
        for (int ni=0;ni<4;ni++)
            #pragma unroll
            for (int c=0;c<4;c++) acc[mi][ni][c]=0.f;

    const int a_r = tid >> 1;
    const int a_cb = (tid & 1) * 16;
    const __half* arow = g_av + (size_t)(m0 + a_r)*DMODEL + a_cb;
    const int b_k2 = tid >> 4;
    const int b_cb = (tid & 15) * 4;

    for (int k0=0;k0<DMODEL;k0+=32){
        {
            __half* Ad = As + a_r*40 + a_cb;
            *(uint4*)Ad     = *(const uint4*)(arow + k0);
            *(uint4*)(Ad+8) = *(const uint4*)(arow + k0 + 8);
            const float* br0 = Wo + (size_t)(k0 + 2*b_k2)*DMODEL + n0 + b_cb;
            const float* br1 = br0 + DMODEL;
            float4 r0 = *(const float4*)br0;
            float4 r1 = *(const float4*)br1;
            unsigned w4[4] = { pack_h2(r0.x,r1.x), pack_h2(r0.y,r1.y),
                               pack_h2(r0.z,r1.z), pack_h2(r0.w,r1.w) };
            *(uint4*)&Bs[b_k2*72 + b_cb] = *(uint4*)&w4[0];
        }
        __syncthreads();
        #pragma unroll
        for (int kk=0;kk<32;kk+=16){
            const int k2 = kk >> 1;
            unsigned a[2][4], bfr[4][2];
            #pragma unroll
            for (int mi=0;mi<2;mi++){
                int m = wm + mi*16;
                a[mi][0] = As2[(m+gq  )*20 + k2 + tq  ];
                a[mi][1] = As2[(m+gq+8)*20 + k2 + tq  ];
                a[mi][2] = As2[(m+gq  )*20 + k2 + tq+4];
                a[mi][3] = As2[(m+gq+8)*20 + k2 + tq+4];
            }
            #pragma unroll
            for (int ni=0;ni<4;ni++){
                int n = wn + ni*8 + gq;
                bfr[ni][0] = Bs[(k2+tq  )*72 + n];
                bfr[ni][1] = Bs[(k2+tq+4)*72 + n];
            }
            #pragma unroll
            for (int mi=0;mi<2;mi++)
                #pragma unroll
                for (int ni=0;ni<4;ni++)
                    mma_f16(acc[mi][ni], a[mi][0],a[mi][1],a[mi][2],a[mi][3], bfr[ni][0],bfr[ni][1]);
        }
        __syncthreads();
    }

    #pragma unroll
    for (int mi=0;mi<2;mi++)
        #pragma unroll
        for (int rr=0;rr<2;rr++){
            const int row = m0 + wm + mi*16 + gq + rr*8;
            #pragma unroll
            for (int ni=0;ni<4;ni++){
                const int col = n0 + wn + ni*8 + 2*tq;
                float2 xv = *(const float2*)&x[(size_t)row*DMODEL + col];
                float2 val = { acc[mi][ni][rr*2+0] + xv.x,
                               acc[mi][ni][rr*2+1] + xv.y };
                *(float2*)&g_h[(size_t)row*DMODEL + col] = val;
            }
        }
}

// ---------------- layernorm ----------------------------------------------------
__global__ __launch_bounds__(256) void ln_kernel(const float* __restrict__ gamma,
                                                 const float* __restrict__ beta,
                                                 float* __restrict__ out)
{
    const int row = blockIdx.x;
    const float* hr = g_h + (size_t)row*DMODEL;
    const int c = threadIdx.x * 4;
    float4 v = *(const float4*)(hr + c);
    float s = v.x+v.y+v.z+v.w;
    s = blockSum(s);
    const float mu = s * (1.f/DMODEL);
    float dx = v.x-mu, dy = v.y-mu, dz = v.z-mu, dw = v.w-mu;
    float sq = dx*dx+dy*dy+dz*dz+dw*dw;
    sq = blockSum(sq);
    const float inv = rsqrtf(sq*(1.f/DMODEL) + 1e-5f);
    float4 gm = *(const float4*)(gamma + c);
    float4 bt = *(const float4*)(beta + c);
    float4 o;
    o.x = dx*inv*gm.x + bt.x;
    o.y = dy*inv*gm.y + bt.y;
    o.z = dz*inv*gm.z + bt.z;
    o.w = dw*inv*gm.w + bt.w;
    *(float4*)(out + (size_t)row*DMODEL + c) = o;
}

// ---------------- launch --------------------------------------------------------
extern "C" void kernel_launch(void* const* d_in, const int* in_sizes, int n_in,
                              void* d_out, int out_size)
{
    const float* x        = (const float*)d_in[0];
    const float* pos_emb  = (const float*)d_in[1];
    const float* memory   = (const float*)d_in[2];
    const float* ubias    = (const float*)d_in[3];
    const float* vbias    = (const float*)d_in[4];
    const float* Wq       = (const float*)d_in[6];
    const float* Wkv      = (const float*)d_in[7];
    const float* Wrel     = (const float*)d_in[8];
    const float* Wo       = (const float*)d_in[9];
    const float* gamma    = (const float*)d_in[10];
    const float* beta     = (const float*)d_in[11];
    float* out    = (float*)d_out;
    float* out_am = out + (size_t)LQ*BATCH*DMODEL;

    cudaFuncSetAttribute(scores_fused_mma, cudaFuncAttributeMaxDynamicSharedMemorySize, SC_SMEM_BYTES);

    qkvr_mma<<<896, 256>>>(x, memory, pos_emb, Wq, Wkv, Wrel);
    scores_fused_mma<<<dim3(TT/128, LQ/128, NG), 256, SC_SMEM_BYTES>>>(ubias, vbias);
    softmax_kernel<<<NG*LQ, 256>>>();
    attnmat_kernel<<<dim3(8, LQ), 256>>>(out_am);
    pv_mma<<<dim3(LQ/128, NG), 256>>>();
    wo_mma<<<dim3(16,16), 256>>>(x, Wo);
    ln_kernel<<<LQ*BATCH, 256>>>(gamma, beta, out);
}

// round 7
// speedup vs baseline: 3.9985x; 1.1729x over previous
#include <cuda_runtime.h>
#include <cuda_fp16.h>
#include <math.h>

#define LQ      1024
#define BATCH   2
#define DMODEL  1024
#define NH      16
#define DHD     64
#define MEMLEN  1024
#define TT      2048
#define NG      (BATCH*NH)
#define SCALE_F 0.125f
#define NEGBIG  -1e30f

// ---------------- scratch -------------------------------------------------------
__device__ __half g_q [NG*LQ*DHD];
__device__ __half g_k [NG*TT*DHD];
__device__ __half g_v [NG*TT*DHD];
__device__ __half g_r [NG*TT*DHD];
__device__ float  g_s [(size_t)NG*LQ*TT];            // scores (fp32)
__device__ __half g_p [(size_t)NG*LQ*TT];            // probs  (fp16)
__device__ __half g_av[LQ*BATCH*NH*DHD];
__device__ float  g_h [LQ*BATCH*DMODEL];
// fp16 pre-converted inputs / weights
__device__ __half   g_xh  [LQ*BATCH*DMODEL];
__device__ __half   g_memh[MEMLEN*BATCH*DMODEL];
__device__ __half   g_posh[TT*BATCH*DMODEL];
__device__ unsigned g_wqi  [512*1024];               // (W[2k],W[2k+1]) half2 pairs
__device__ unsigned g_wkvi [512*2048];
__device__ unsigned g_wreli[512*1024];
__device__ unsigned g_woi  [512*1024];

// ---------------- fp16 mma helpers ----------------------------------------------
__device__ __forceinline__ unsigned pack_h2(float a, float b){
    __half2 h = __floats2half2_rn(a, b);
    return *reinterpret_cast<unsigned*>(&h);
}
__device__ __forceinline__ void mma_f16(float c[4],
                                        unsigned a0, unsigned a1, unsigned a2, unsigned a3,
                                        unsigned b0, unsigned b1){
    asm volatile("mma.sync.aligned.m16n8k16.row.col.f32.f16.f16.f32 "
        "{%0,%1,%2,%3}, {%4,%5,%6,%7}, {%8,%9}, {%0,%1,%2,%3};"
        : "+f"(c[0]), "+f"(c[1]), "+f"(c[2]), "+f"(c[3])
        : "r"(a0), "r"(a1), "r"(a2), "r"(a3), "r"(b0), "r"(b1));
}

// ---------------- reductions ----------------
__device__ __forceinline__ float blockSum(float v){
    __shared__ float sm[32];
    int lane = threadIdx.x & 31, w = threadIdx.x >> 5;
    #pragma unroll
    for (int o=16;o>0;o>>=1) v += __shfl_xor_sync(0xffffffffu, v, o);
    if (lane==0) sm[w] = v;
    __syncthreads();
    float r = (threadIdx.x < 8) ? sm[threadIdx.x] : 0.f;
    if (w==0){
        #pragma unroll
        for (int o=4;o>0;o>>=1) r += __shfl_xor_sync(0xffffffffu, r, o);
        if (lane==0) sm[0]=r;
    }
    __syncthreads();
    r = sm[0];
    __syncthreads();
    return r;
}
__device__ __forceinline__ float blockMax(float v){
    __shared__ float sm[32];
    int lane = threadIdx.x & 31, w = threadIdx.x >> 5;
    #pragma unroll
    for (int o=16;o>0;o>>=1) v = fmaxf(v, __shfl_xor_sync(0xffffffffu, v, o));
    if (lane==0) sm[w] = v;
    __syncthreads();
    float r = (threadIdx.x < 8) ? sm[threadIdx.x] : -3.4e38f;
    if (w==0){
        #pragma unroll
        for (int o=4;o>0;o>>=1) r = fmaxf(r, __shfl_xor_sync(0xffffffffu, r, o));
        if (lane==0) sm[0]=r;
    }
    __syncthreads();
    r = sm[0];
    __syncthreads();
    return r;
}

// ---------------- fp16 pre-conversion -------------------------------------------
__device__ __forceinline__ void cvt_plain(const float* __restrict__ s, __half* d, int b, int t){
    const int idx = b*2048 + t*8;
    float4 v0 = *(const float4*)(s+idx), v1 = *(const float4*)(s+idx+4);
    unsigned u[4] = { pack_h2(v0.x,v0.y), pack_h2(v0.z,v0.w),
                      pack_h2(v1.x,v1.y), pack_h2(v1.z,v1.w) };
    *(uint4*)&d[idx] = *(uint4*)u;
}
__device__ __forceinline__ void cvt_inter(const float* __restrict__ W, unsigned* d,
                                          int b, int t, int lgN){
    const int p = b*1024 + t*4;
    const int N = 1 << lgN;
    const int k2 = p >> lgN, n = p & (N-1);
    const float* r0 = W + ((size_t)k2*2)*N + n;
    float4 a = *(const float4*)r0;
    float4 c = *(const float4*)(r0 + N);
    unsigned u[4] = { pack_h2(a.x,c.x), pack_h2(a.y,c.y),
                      pack_h2(a.z,c.z), pack_h2(a.w,c.w) };
    *(uint4*)&d[p] = *(uint4*)u;
}
__global__ __launch_bounds__(256) void cvt_all(const float* __restrict__ x,
                                               const float* __restrict__ memory,
                                               const float* __restrict__ pos_emb,
                                               const float* __restrict__ Wq,
                                               const float* __restrict__ Wkv,
                                               const float* __restrict__ Wrel,
                                               const float* __restrict__ Wo)
{
    const int bid = blockIdx.x, tid = threadIdx.x;
    if      (bid < 1024) cvt_plain(x,       g_xh,   bid,        tid);
    else if (bid < 2048) cvt_plain(memory,  g_memh, bid-1024,   tid);
    else if (bid < 4096) cvt_plain(pos_emb, g_posh, bid-2048,   tid);
    else if (bid < 4608) cvt_inter(Wq,   g_wqi,   bid-4096, tid, 10);
    else if (bid < 5632) cvt_inter(Wkv,  g_wkvi,  bid-4608, tid, 11);
    else if (bid < 6144) cvt_inter(Wrel, g_wreli, bid-5632, tid, 10);
    else                 cvt_inter(Wo,   g_woi,   bid-6144, tid, 10);
}

// ---------------- QKVR projection GEMM (fp16 MMA, ping-pong, pure-copy staging) --
__global__ __launch_bounds__(256) void qkvr_mma()
{
    __shared__ __half   AsB[2*128*40];
    __shared__ unsigned BsB[2*16*136];

    int bid = blockIdx.x;
    int mode, m0, n0, N;
    const unsigned* Wi;
    if (bid < 128)      { mode=0; m0=(bid>>3)<<7;  n0=(bid&7)<<7;  N=1024; Wi=g_wqi;  }
    else if (bid < 640) { int t=bid-128; mode=1; m0=(t>>4)<<7; n0=(t&15)<<7; N=2048; Wi=g_wkvi; }
    else                { int t=bid-640; mode=2; m0=(t>>3)<<7; n0=(t&7)<<7;  N=1024; Wi=g_wreli;}

    const int tid = threadIdx.x;
    const int warp = tid >> 5, lane = tid & 31;
    const int gq = lane >> 2, tq = lane & 3;
    const int wm = (warp >> 2) * 64, wn = (warp & 3) * 32;

    const int a_r = tid >> 1;
    const int a_cb = (tid & 1) * 16;          // half offset within K=32 chunk
    const int grow = m0 + a_r;
    const __half* arow;
    if (mode==0)      arow = g_xh + (size_t)grow*DMODEL;
    else if (mode==1) arow = (grow < MEMLEN*BATCH) ? g_memh + (size_t)grow*DMODEL
                                                   : g_xh + (size_t)(grow - MEMLEN*BATCH)*DMODEL;
    else              arow = g_posh + (size_t)grow*DMODEL;

    const int b_k2 = tid >> 4;                // 0..15 (k-pair row within chunk)
    const int b_cb = (tid & 15) * 8;          // unsigned offset (8 per thread)

    float acc[4][4][4];
    #pragma unroll
    for (int mi=0;mi<4;mi++)
        #pragma unroll
        for (int ni=0;ni<4;ni++)
            #pragma unroll
            for (int c=0;c<4;c++) acc[mi][ni][c]=0.f;

    // preload chunk 0
    {
        const __half* asrc = arow + a_cb;
        uint4 u0 = *(const uint4*)asrc, u1 = *(const uint4*)(asrc+8);
        __half* Ad = AsB + a_r*40 + a_cb;
        *(uint4*)Ad = u0; *(uint4*)(Ad+8) = u1;
        const unsigned* bsrc = Wi + (size_t)b_k2*N + n0 + b_cb;
        uint4 w0 = *(const uint4*)bsrc, w1 = *(const uint4*)(bsrc+4);
        unsigned* Bd = BsB + b_k2*136 + b_cb;
        *(uint4*)Bd = w0; *(uint4*)(Bd+4) = w1;
    }
    __syncthreads();

    for (int kc=0;kc<32;kc++){
        const unsigned* Ac2 = (const unsigned*)(AsB + (kc&1)*128*40);   // stride 20
        const unsigned* Bc  = BsB + (kc&1)*16*136;
        uint4 pa0, pa1, pb0, pb1;
        if (kc < 31){
            const __half* asrc = arow + (kc+1)*32 + a_cb;
            pa0 = *(const uint4*)asrc; pa1 = *(const uint4*)(asrc+8);
            const unsigned* bsrc = Wi + (size_t)((kc+1)*16 + b_k2)*N + n0 + b_cb;
            pb0 = *(const uint4*)bsrc; pb1 = *(const uint4*)(bsrc+4);
        }
        #pragma unroll
        for (int kk=0;kk<32;kk+=16){
            unsigned a[4][4], b[4][2];
            const int k2 = kk >> 1;
            #pragma unroll
            for (int mi=0;mi<4;mi++){
                int m = wm + mi*16;
                a[mi][0] = Ac2[(m+gq  )*20 + k2 + tq  ];
                a[mi][1] = Ac2[(m+gq+8)*20 + k2 + tq  ];
                a[mi][2] = Ac2[(m+gq  )*20 + k2 + tq+4];
                a[mi][3] = Ac2[(m+gq+8)*20 + k2 + tq+4];
            }
            #pragma unroll
            for (int ni=0;ni<4;ni++){
                int n = wn + ni*8 + gq;
                b[ni][0] = Bc[(k2+tq  )*136 + n];
                b[ni][1] = Bc[(k2+tq+4)*136 + n];
            }
            #pragma unroll
            for (int mi=0;mi<4;mi++)
                #pragma unroll
                for (int ni=0;ni<4;ni++)
                    mma_f16(acc[mi][ni], a[mi][0],a[mi][1],a[mi][2],a[mi][3], b[ni][0],b[ni][1]);
        }
        if (kc < 31){
            __half* An = AsB + ((kc+1)&1)*128*40 + a_r*40 + a_cb;
            *(uint4*)An = pa0; *(uint4*)(An+8) = pa1;
            unsigned* Bn = BsB + ((kc+1)&1)*16*136 + b_k2*136 + b_cb;
            *(uint4*)Bn = pb0; *(uint4*)(Bn+4) = pb1;
        }
        __syncthreads();
    }

    #pragma unroll
    for (int mi=0;mi<4;mi++){
        #pragma unroll
        for (int rr=0;rr<2;rr++){
            const int row = m0 + wm + mi*16 + gq + rr*8;
            const int t   = row >> 1, bb = row & 1;
            #pragma unroll
            for (int ni=0;ni<4;ni++){
                const int col = n0 + wn + ni*8 + 2*tq;
                unsigned hv = pack_h2(acc[mi][ni][rr*2+0], acc[mi][ni][rr*2+1]);
                if (mode==0){
                    int h = col >> 6, d = col & 63;
                    *reinterpret_cast<unsigned*>(&g_q[(((size_t)(bb*NH+h)*LQ + t)<<6) + d]) = hv;
                } else if (mode==1){
                    int c = col; __half* dst = g_k;
                    if (c >= NH*DHD){ dst = g_v; c -= NH*DHD; }
                    int h = c >> 6, d = c & 63;
                    *reinterpret_cast<unsigned*>(&dst[(((size_t)(bb*NH+h)*TT + t)<<6) + d]) = hv;
                } else {
                    int h = col >> 6, d = col & 63;
                    *reinterpret_cast<unsigned*>(&g_r[(((size_t)(bb*NH+h)*TT + t)<<6) + d]) = hv;
                }
            }
        }
    }
}

// ---------------- fused scores: AC + BD (diag-shifted band), fp16 MMA -----------
#define SC_SMEM_BYTES (128*72*2 + 128*68*4 + 64*72*2 + (128+64+64+64)*4)
__global__ __launch_bounds__(256) void scores_fused_mma(const float* __restrict__ ubias,
                                                        const float* __restrict__ vbias)
{
    const int gg = blockIdx.z, h = gg & (NH-1);
    const int i0 = blockIdx.y << 7;
    const int j0 = blockIdx.x << 7;
    const int delta = j0 - i0;
    if (delta > 1151) return;

    extern __shared__ char sm_raw[];
    __half* Qs = (__half*)sm_raw;                         // [128][72]
    char*   reg2 = sm_raw + 128*72*2;
    __half* Ks = (__half*)reg2;                           // [128][72] (dies after AC)
    float*  BDs = (float*)reg2;                           // [128][68] (aliases Ks)
    __half* Rs = (__half*)(reg2 + 128*68*4);              // [64][72]
    float*  uKs = (float*)(reg2 + 128*68*4 + 64*72*2);    // [128]
    float*  vRs = uKs + 128;                              // [64]
    float*  u_s = vRs + 64;
    float*  v_s = u_s + 64;

    const int tid = threadIdx.x;
    const int warp = tid >> 5, lane = tid & 31;
    const int gq = lane >> 2, tq = lane & 3;
    const int wm = (warp >> 2) * 64, wn = (warp & 3) * 32;
    const int wmb = (warp >> 1) * 32, wnb = (warp & 1) * 32;

    const unsigned* Qs2 = (const unsigned*)Qs;            // stride 36
    const unsigned* Ks2 = (const unsigned*)Ks;
    const unsigned* Rs2 = (const unsigned*)Rs;

    {
        const int sr = tid >> 1, cb = (tid & 1) * 32;
        const __half* qrow = g_q + (((size_t)gg*LQ + i0 + sr) << 6) + cb;
        const __half* krow = g_k + (((size_t)gg*TT + j0 + sr) << 6) + cb;
        #pragma unroll
        for (int q=0;q<4;q++){
            *(uint4*)&Qs[sr*72 + cb + q*8] = *(const uint4*)(qrow + q*8);
            *(uint4*)&Ks[sr*72 + cb + q*8] = *(const uint4*)(krow + q*8);
        }
        if (tid < 64)       u_s[tid]    = ubias[(h<<6) + tid];
        else if (tid < 128) v_s[tid-64] = vbias[(h<<6) + tid - 64];
    }
    __syncthreads();

    if (tid < 128){
        float s = 0.f;
        #pragma unroll
        for (int d=0;d<64;d++) s += u_s[d] * __half2float(Ks[tid*72 + d]);
        uKs[tid] = s;
    }

    float acc_ac[4][4][4];
    #pragma unroll
    for (int mi=0;mi<4;mi++)
        #pragma unroll
        for (int ni=0;ni<4;ni++)
            #pragma unroll
            for (int c=0;c<4;c++) acc_ac[mi][ni][c]=0.f;

    #pragma unroll
    for (int kk=0;kk<64;kk+=16){
        const int k2 = kk >> 1;
        unsigned a[4][4], b[4][2];
        #pragma unroll
        for (int mi=0;mi<4;mi++){
            int m = wm + mi*16;
            a[mi][0] = Qs2[(m+gq  )*36 + k2 + tq  ];
            a[mi][1] = Qs2[(m+gq+8)*36 + k2 + tq  ];
            a[mi][2] = Qs2[(m+gq  )*36 + k2 + tq+4];
            a[mi][3] = Qs2[(m+gq+8)*36 + k2 + tq+4];
        }
        #pragma unroll
        for (int ni=0;ni<4;ni++){
            int n = wn + ni*8 + gq;
            b[ni][0] = Ks2[n*36 + k2 + tq  ];
            b[ni][1] = Ks2[n*36 + k2 + tq+4];
        }
        #pragma unroll
        for (int mi=0;mi<4;mi++)
            #pragma unroll
            for (int ni=0;ni<4;ni++)
                mma_f16(acc_ac[mi][ni], a[mi][0],a[mi][1],a[mi][2],a[mi][3], b[ni][0],b[ni][1]);
    }

    #pragma unroll 1
    for (int c=0;c<4;c++){
        {
            const int rsr = tid >> 2, rcb = (tid & 3) * 16;
            int rg = delta + 896 + c*64 + rsr;
            rg = min(max(rg, 0), TT-1);
            const __half* rrow = g_r + (((size_t)gg*TT + rg) << 6) + rcb;
            *(uint4*)&Rs[rsr*72 + rcb]     = *(const uint4*)(rrow);
            *(uint4*)&Rs[rsr*72 + rcb + 8] = *(const uint4*)(rrow + 8);
        }
        __syncthreads();
        if (tid < 64){
            float s = 0.f;
            #pragma unroll
            for (int d=0;d<64;d++) s += v_s[d] * __half2float(Rs[tid*72 + d]);
            vRs[tid] = s;
        }
        float acc_bd[2][4][4];
        #pragma unroll
        for (int mi=0;mi<2;mi++)
            #pragma unroll
            for (int ni=0;ni<4;ni++)
                #pragma unroll
                for (int e=0;e<4;e++) acc_bd[mi][ni][e]=0.f;
        #pragma unroll
        for (int kk=0;kk<64;kk+=16){
            const int k2 = kk >> 1;
            unsigned a[2][4], b[4][2];
            #pragma unroll
            for (int mi=0;mi<2;mi++){
                int m = wmb + mi*16;
                a[mi][0] = Qs2[(m+gq  )*36 + k2 + tq  ];
                a[mi][1] = Qs2[(m+gq+8)*36 + k2 + tq  ];
                a[mi][2] = Qs2[(m+gq  )*36 + k2 + tq+4];
                a[mi][3] = Qs2[(m+gq+8)*36 + k2 + tq+4];
            }
            #pragma unroll
            for (int ni=0;ni<4;ni++){
                int n = wnb + ni*8 + gq;
                b[ni][0] = Rs2[n*36 + k2 + tq  ];
                b[ni][1] = Rs2[n*36 + k2 + tq+4];
            }
            #pragma unroll
            for (int mi=0;mi<2;mi++)
                #pragma unroll
                for (int ni=0;ni<4;ni++)
                    mma_f16(acc_bd[mi][ni], a[mi][0],a[mi][1],a[mi][2],a[mi][3], b[ni][0],b[ni][1]);
        }
        __syncthreads();
        #pragma unroll
        for (int mi=0;mi<2;mi++)
            #pragma unroll
            for (int rr=0;rr<2;rr++){
                int il = wmb + mi*16 + gq + rr*8;
                #pragma unroll
                for (int ni=0;ni<4;ni++){
                    int pl = wnb + ni*8 + 2*tq;
                    float2 v = { acc_bd[mi][ni][rr*2+0], acc_bd[mi][ni][rr*2+1] };
                    *(float2*)&BDs[il*68 + pl] = v;
                }
            }
        __syncthreads();
        const int poff = 127 - c*64;
        #pragma unroll
        for (int mi=0;mi<4;mi++)
            #pragma unroll
            for (int rr=0;rr<2;rr++){
                int il = wm + mi*16 + gq + rr*8;
                #pragma unroll
                for (int ni=0;ni<4;ni++){
                    int jl = wn + ni*8 + 2*tq;
                    int pl = jl - il + poff;
                    if (pl >= 0 && pl < 64)
                        acc_ac[mi][ni][rr*2+0] += BDs[il*68 + pl] + vRs[pl];
                    pl++;
                    if (pl >= 0 && pl < 64)
                        acc_ac[mi][ni][rr*2+1] += BDs[il*68 + pl] + vRs[pl];
                }
            }
        __syncthreads();
    }

    #pragma unroll
    for (int mi=0;mi<4;mi++)
        #pragma unroll
        for (int rr=0;rr<2;rr++){
            const int i = i0 + wm + mi*16 + gq + rr*8;
            float* srow = g_s + ((size_t)gg*LQ + i)*TT + j0;
            #pragma unroll
            for (int ni=0;ni<4;ni++){
                const int jl = wn + ni*8 + 2*tq;
                float2 val = { (acc_ac[mi][ni][rr*2+0] + uKs[jl  ]) * SCALE_F,
                               (acc_ac[mi][ni][rr*2+1] + uKs[jl+1]) * SCALE_F };
                *(float2*)&srow[jl] = val;
            }
        }
}

// ---------------- softmax: read fp32 scores, write fp16 probs (full rows) -------
__global__ __launch_bounds__(256) void softmax_kernel()
{
    const int idx = blockIdx.x;
    const int i   = idx & (LQ-1);
    const float* srow = g_s + (size_t)idx*TT;
    __half* prow = g_p + (size_t)idx*TT;
    const int jmax = i + MEMLEN;
    const int base = threadIdx.x * 8;
    float vals[8];
    if (base <= jmax){
        float4 v0 = *(const float4*)(srow + base);
        float4 v1 = *(const float4*)(srow + base + 4);
        vals[0]=v0.x; vals[1]=v0.y; vals[2]=v0.z; vals[3]=v0.w;
        vals[4]=v1.x; vals[5]=v1.y; vals[6]=v1.z; vals[7]=v1.w;
        #pragma unroll
        for (int q=0;q<8;q++) if (base+q > jmax) vals[q] = NEGBIG;
    } else {
        #pragma unroll
        for (int q=0;q<8;q++) vals[q] = NEGBIG;
    }
    float mx = vals[0];
    #pragma unroll
    for (int q=1;q<8;q++) mx = fmaxf(mx, vals[q]);
    mx = blockMax(mx);
    float s = 0.f;
    #pragma unroll
    for (int q=0;q<8;q++){
        float e = (vals[q] > -1e29f) ? __expf(vals[q]-mx) : 0.f;
        vals[q] = e; s += e;
    }
    s = blockSum(s);
    const float inv = 1.f / s;
    unsigned u[4] = { pack_h2(vals[0]*inv, vals[1]*inv), pack_h2(vals[2]*inv, vals[3]*inv),
                      pack_h2(vals[4]*inv, vals[5]*inv), pack_h2(vals[6]*inv, vals[7]*inv) };
    *(uint4*)&prow[base] = *(uint4*)u;
}

// ---------------- attn_matrix = mean over (b,h) of fp16 probs -------------------
__global__ __launch_bounds__(256) void attnmat_kernel(float* __restrict__ out)
{
    const int i  = blockIdx.y;
    const int j0 = blockIdx.x << 8;
    const int jmax = i + MEMLEN;
    const int tid = threadIdx.x;
    const int jq = tid & 63;
    const int gsel = tid >> 6;
    const int j = j0 + jq*4;
    __shared__ float4 red[256];

    float4 s = {0.f,0.f,0.f,0.f};
    if (j0 <= jmax){
        #pragma unroll
        for (int gi=0; gi<8; gi++){
            int g = gsel*8 + gi;
            uint2 raw = *(const uint2*)(g_p + ((size_t)g*LQ + i)*TT + j);
            float2 f0 = __half22float2(*reinterpret_cast<__half2*>(&raw.x));
            float2 f1 = __half22float2(*reinterpret_cast<__half2*>(&raw.y));
            s.x+=f0.x; s.y+=f0.y; s.z+=f1.x; s.w+=f1.y;
        }
    }
    red[tid] = s;
    __syncthreads();
    if (tid < 64){
        float4 a=red[tid], b=red[tid+64], c=red[tid+128], d=red[tid+192];
        const float k = 1.f/NG;
        float4 o = { (a.x+b.x+c.x+d.x)*k, (a.y+b.y+c.y+d.y)*k,
                     (a.z+b.z+c.z+d.z)*k, (a.w+b.w+c.w+d.w)*k };
        *(float4*)(out + (size_t)i*TT + j0 + tid*4) = o;
    }
}

// ---------------- PV GEMM (fp16 MMA): av = P @ V --------------------------------
__global__ __launch_bounds__(256) void pv_mma()
{
    const int gg = blockIdx.y, b = gg >> 4, h = gg & (NH-1);
    const int i0 = blockIdx.x << 7;
    const int kmax = min(TT, i0 + 1152);

    __shared__ __half   As[128*40];
    __shared__ unsigned Vs[16*72];

    const int tid = threadIdx.x;
    const int warp = tid >> 5, lane = tid & 31;
    const int gq = lane >> 2, tq = lane & 3;
    const int wm = (warp >> 1) * 32, wn = (warp & 1) * 32;
    const unsigned* As2 = (const unsigned*)As;   // stride 20

    float acc[2][4][4];
    #pragma unroll
    for (int mi=0;mi<2;mi++)
        #pragma unroll
        for (int ni=0;ni<4;ni++)
            #pragma unroll
            for (int c=0;c<4;c++) acc[mi][ni][c]=0.f;

    const int a_r = tid >> 1;
    const int a_cb = (tid & 1) * 16;
    const __half* prow = g_p + ((size_t)gg*LQ + i0 + a_r)*TT + a_cb;
    const __half* vtile = g_v + ((size_t)gg*TT << 6);
    const int v_k2 = tid >> 4;
    const int v_cb = (tid & 15) * 4;

    for (int k0=0;k0<kmax;k0+=32){
        {
            uint4 u0 = *(const uint4*)(prow + k0);
            uint4 u1 = *(const uint4*)(prow + k0 + 8);
            __half* Ad = As + a_r*40 + a_cb;
            *(uint4*)Ad = u0; *(uint4*)(Ad+8) = u1;
            const __half* vr0 = vtile + (size_t)(k0 + 2*v_k2)*DHD + v_cb;
            uint2 x0 = *(const uint2*)vr0;
            uint2 x1 = *(const uint2*)(vr0 + DHD);
            unsigned w4[4] = { __byte_perm(x0.x,x1.x,0x5410), __byte_perm(x0.x,x1.x,0x7632),
                               __byte_perm(x0.y,x1.y,0x5410), __byte_perm(x0.y,x1.y,0x7632) };
            *(uint4*)&Vs[v_k2*72 + v_cb] = *(uint4*)w4;
        }
        __syncthreads();
        #pragma unroll
        for (int kk=0;kk<32;kk+=16){
            const int k2 = kk >> 1;
            unsigned a[2][4], bfr[4][2];
            #pragma unroll
            for (int mi=0;mi<2;mi++){
                int m = wm + mi*16;
                a[mi][0] = As2[(m+gq  )*20 + k2 + tq  ];
                a[mi][1] = As2[(m+gq+8)*20 + k2 + tq  ];
                a[mi][2] = As2[(m+gq  )*20 + k2 + tq+4];
                a[mi][3] = As2[(m+gq+8)*20 + k2 + tq+4];
            }
            #pragma unroll
            for (int ni=0;ni<4;ni++){
                int n = wn + ni*8 + gq;
                bfr[ni][0] = Vs[(k2+tq  )*72 + n];
                bfr[ni][1] = Vs[(k2+tq+4)*72 + n];
            }
            #pragma unroll
            for (int mi=0;mi<2;mi++)
                #pragma unroll
                for (int ni=0;ni<4;ni++)
                    mma_f16(acc[mi][ni], a[mi][0],a[mi][1],a[mi][2],a[mi][3], bfr[ni][0],bfr[ni][1]);
        }
        __syncthreads();
    }

    #pragma unroll
    for (int mi=0;mi<2;mi++)
        #pragma unroll
        for (int rr=0;rr<2;rr++){
            const int i = i0 + wm + mi*16 + gq + rr*8;
            __half* dst = g_av + (size_t)(i*BATCH + b)*DMODEL + (h<<6);
            #pragma unroll
            for (int ni=0;ni<4;ni++){
                const int d = wn + ni*8 + 2*tq;
                unsigned hv = pack_h2(acc[mi][ni][rr*2+0], acc[mi][ni][rr*2+1]);
                *reinterpret_cast<unsigned*>(&dst[d]) = hv;
            }
        }
}

// ---------------- Wo GEMM + residual (fp16 MMA): g_h = x + g_av @ Wo ------------
__global__ __launch_bounds__(256) void wo_mma(const float* __restrict__ x)
{
    const int m0 = blockIdx.y << 7;
    const int n0 = blockIdx.x << 6;

    __shared__ __half   As[128*40];
    __shared__ unsigned Bs[16*72];

    const int tid = threadIdx.x;
    const int warp = tid >> 5, lane = tid & 31;
    const int gq = lane >> 2, tq = lane & 3;
    const int wm = (warp >> 1) * 32, wn = (warp & 1) * 32;
    const unsigned* As2 = (const unsigned*)As;

    float acc[2][4][4];
    #pragma unroll
    for (int mi=0;mi<2;mi++)
        #pragma unroll
        for (int ni=0;ni<4;ni++)
            #pragma unroll
            for (int c=0;c<4;c++) acc[mi][ni][c]=0.f;

    const int a_r = tid >> 1;
    const int a_cb = (tid & 1) * 16;
    const __half* arow = g_av + (size_t)(m0 + a_r)*DMODEL + a_cb;
    const int b_k2 = tid >> 4;
    const int b_cb = (tid & 15) * 4;

    for (int k0=0;k0<DMODEL;k0+=32){
        {
            __half* Ad = As + a_r*40 + a_cb;
            *(uint4*)Ad     = *(const uint4*)(arow + k0);
            *(uint4*)(Ad+8) = *(const uint4*)(arow + k0 + 8);
            const unsigned* bsrc = g_woi + (size_t)((k0>>1) + b_k2)*DMODEL + n0 + b_cb;
            *(uint4*)&Bs[b_k2*72 + b_cb] = *(const uint4*)bsrc;
        }
        __syncthreads();
        #pragma unroll
        for (int kk=0;kk<32;kk+=16){
            const int k2 = kk >> 1;
            unsigned a[2][4], bfr[4][2];
            #pragma unroll
            for (int mi=0;mi<2;mi++){
                int m = wm + mi*16;
                a[mi][0] = As2[(m+gq  )*20 + k2 + tq  ];
                a[mi][1] = As2[(m+gq+8)*20 + k2 + tq  ];
                a[mi][2] = As2[(m+gq  )*20 + k2 + tq+4];
                a[mi][3] = As2[(m+gq+8)*20 + k2 + tq+4];
            }
            #pragma unroll
            for (int ni=0;ni<4;ni++){
                int n = wn + ni*8 + gq;
                bfr[ni][0] = Bs[(k2+tq  )*72 + n];
                bfr[ni][1] = Bs[(k2+tq+4)*72 + n];
            }
            #pragma unroll
            for (int mi=0;mi<2;mi++)
                #pragma unroll
                for (int ni=0;ni<4;ni++)
                    mma_f16(acc[mi][ni], a[mi][0],a[mi][1],a[mi][2],a[mi][3], bfr[ni][0],bfr[ni][1]);
        }
        __syncthreads();
    }

    #pragma unroll
    for (int mi=0;mi<2;mi++)
        #pragma unroll
        for (int rr=0;rr<2;rr++){
            const int row = m0 + wm + mi*16 + gq + rr*8;
            #pragma unroll
            for (int ni=0;ni<4;ni++){
                const int col = n0 + wn + ni*8 + 2*tq;
                float2 xv = *(const float2*)&x[(size_t)row*DMODEL + col];
                float2 val = { acc[mi][ni][rr*2+0] + xv.x,
                               acc[mi][ni][rr*2+1] + xv.y };
                *(float2*)&g_h[(size_t)row*DMODEL + col] = val;
            }
        }
}

// ---------------- layernorm ------------------------------------------------------
__global__ __launch_bounds__(256) void ln_kernel(const float* __restrict__ gamma,
                                                 const float* __restrict__ beta,
                                                 float* __restrict__ out)
{
    const int row = blockIdx.x;
    const float* hr = g_h + (size_t)row*DMODEL;
    const int c = threadIdx.x * 4;
    float4 v = *(const float4*)(hr + c);
    float s = v.x+v.y+v.z+v.w;
    s = blockSum(s);
    const float mu = s * (1.f/DMODEL);
    float dx = v.x-mu, dy = v.y-mu, dz = v.z-mu, dw = v.w-mu;
    float sq = dx*dx+dy*dy+dz*dz+dw*dw;
    sq = blockSum(sq);
    const float inv = rsqrtf(sq*(1.f/DMODEL) + 1e-5f);
    float4 gm = *(const float4*)(gamma + c);
    float4 bt = *(const float4*)(beta + c);
    float4 o;
    o.x = dx*inv*gm.x + bt.x;
    o.y = dy*inv*gm.y + bt.y;
    o.z = dz*inv*gm.z + bt.z;
    o.w = dw*inv*gm.w + bt.w;
    *(float4*)(out + (size_t)row*DMODEL + c) = o;
}

// ---------------- launch ----------------------------------------------------------
extern "C" void kernel_launch(void* const* d_in, const int* in_sizes, int n_in,
                              void* d_out, int out_size)
{
    const float* x        = (const float*)d_in[0];
    const float* pos_emb  = (const float*)d_in[1];
    const float* memory   = (const float*)d_in[2];
    const float* ubias    = (const float*)d_in[3];
    const float* vbias    = (const float*)d_in[4];
    const float* Wq       = (const float*)d_in[6];
    const float* Wkv      = (const float*)d_in[7];
    const float* Wrel     = (const float*)d_in[8];
    const float* Wo       = (const float*)d_in[9];
    const float* gamma    = (const float*)d_in[10];
    const float* beta     = (const float*)d_in[11];
    float* out    = (float*)d_out;
    float* out_am = out + (size_t)LQ*BATCH*DMODEL;

    cudaFuncSetAttribute(scores_fused_mma, cudaFuncAttributeMaxDynamicSharedMemorySize, SC_SMEM_BYTES);

    cvt_all<<<6656, 256>>>(x, memory, pos_emb, Wq, Wkv, Wrel, Wo);
    qkvr_mma<<<896, 256>>>();
    scores_fused_mma<<<dim3(TT/128, LQ/128, NG), 256, SC_SMEM_BYTES>>>(ubias, vbias);
    softmax_kernel<<<NG*LQ, 256>>>();
    attnmat_kernel<<<dim3(8, LQ), 256>>>(out_am);
    pv_mma<<<dim3(LQ/128, NG), 256>>>();
    wo_mma<<<dim3(16,16), 256>>>(x);
    ln_kernel<<<LQ*BATCH, 256>>>(gamma, beta, out);
}

// round 8
// speedup vs baseline: 4.2430x; 1.0611x over previous
#include <cuda_runtime.h>
#include <cuda_fp16.h>
#include <math.h>

#define LQ      1024
#define BATCH   2
#define DMODEL  1024
#define NH      16
#define DHD     64
#define MEMLEN  1024
#define TT      2048
#define NG      (BATCH*NH)
#define SCALE_F 0.125f
#define EXPC    8.0f

// ---------------- scratch -------------------------------------------------------
__device__ __half g_q [NG*LQ*DHD];
__device__ __half g_k [NG*TT*DHD];
__device__ __half g_v [NG*TT*DHD];
__device__ __half g_r [NG*TT*DHD];
__device__ __half g_p [(size_t)NG*LQ*TT];            // unnormalized e^(s-8) (fp16)
__device__ float  g_rs[NG*LQ];                       // row sums of e^(s-8)
__device__ __half g_av[LQ*BATCH*NH*DHD];
__device__ float  g_h [LQ*BATCH*DMODEL];
// fp16 pre-converted inputs / weights
__device__ __half   g_xh  [LQ*BATCH*DMODEL];
__device__ __half   g_memh[MEMLEN*BATCH*DMODEL];
__device__ __half   g_posh[TT*BATCH*DMODEL];
__device__ unsigned g_wqi  [512*1024];               // (W[2k],W[2k+1]) half2 pairs
__device__ unsigned g_wkvi [512*2048];
__device__ unsigned g_wreli[512*1024];
__device__ unsigned g_woi  [512*1024];

// ---------------- fp16 mma helpers ----------------------------------------------
__device__ __forceinline__ unsigned pack_h2(float a, float b){
    __half2 h = __floats2half2_rn(a, b);
    return *reinterpret_cast<unsigned*>(&h);
}
__device__ __forceinline__ void mma_f16(float c[4],
                                        unsigned a0, unsigned a1, unsigned a2, unsigned a3,
                                        unsigned b0, unsigned b1){
    asm volatile("mma.sync.aligned.m16n8k16.row.col.f32.f16.f16.f32 "
        "{%0,%1,%2,%3}, {%4,%5,%6,%7}, {%8,%9}, {%0,%1,%2,%3};"
        : "+f"(c[0]), "+f"(c[1]), "+f"(c[2]), "+f"(c[3])
        : "r"(a0), "r"(a1), "r"(a2), "r"(a3), "r"(b0), "r"(b1));
}

// ---------------- reductions ----------------
__device__ __forceinline__ float blockSum(float v){
    __shared__ float sm[32];
    int lane = threadIdx.x & 31, w = threadIdx.x >> 5;
    #pragma unroll
    for (int o=16;o>0;o>>=1) v += __shfl_xor_sync(0xffffffffu, v, o);
    if (lane==0) sm[w] = v;
    __syncthreads();
    float r = (threadIdx.x < 8) ? sm[threadIdx.x] : 0.f;
    if (w==0){
        #pragma unroll
        for (int o=4;o>0;o>>=1) r += __shfl_xor_sync(0xffffffffu, r, o);
        if (lane==0) sm[0]=r;
    }
    __syncthreads();
    r = sm[0];
    __syncthreads();
    return r;
}

// ---------------- fp16 pre-conversion -------------------------------------------
__device__ __forceinline__ void cvt_plain(const float* __restrict__ s, __half* d, int b, int t){
    const int idx = b*2048 + t*8;
    float4 v0 = *(const float4*)(s+idx), v1 = *(const float4*)(s+idx+4);
    unsigned u[4] = { pack_h2(v0.x,v0.y), pack_h2(v0.z,v0.w),
                      pack_h2(v1.x,v1.y), pack_h2(v1.z,v1.w) };
    *(uint4*)&d[idx] = *(uint4*)u;
}
__device__ __forceinline__ void cvt_inter(const float* __restrict__ W, unsigned* d,
                                          int b, int t, int lgN){
    const int p = b*1024 + t*4;
    const int N = 1 << lgN;
    const int k2 = p >> lgN, n = p & (N-1);
    const float* r0 = W + ((size_t)k2*2)*N + n;
    float4 a = *(const float4*)r0;
    float4 c = *(const float4*)(r0 + N);
    unsigned u[4] = { pack_h2(a.x,c.x), pack_h2(a.y,c.y),
                      pack_h2(a.z,c.z), pack_h2(a.w,c.w) };
    *(uint4*)&d[p] = *(uint4*)u;
}
__global__ __launch_bounds__(256) void cvt_all(const float* __restrict__ x,
                                               const float* __restrict__ memory,
                                               const float* __restrict__ pos_emb,
                                               const float* __restrict__ Wq,
                                               const float* __restrict__ Wkv,
                                               const float* __restrict__ Wrel,
                                               const float* __restrict__ Wo)
{
    const int bid = blockIdx.x, tid = threadIdx.x;
    if      (bid < 1024) cvt_plain(x,       g_xh,   bid,        tid);
    else if (bid < 2048) cvt_plain(memory,  g_memh, bid-1024,   tid);
    else if (bid < 4096) cvt_plain(pos_emb, g_posh, bid-2048,   tid);
    else if (bid < 4608) cvt_inter(Wq,   g_wqi,   bid-4096, tid, 10);
    else if (bid < 5632) cvt_inter(Wkv,  g_wkvi,  bid-4608, tid, 11);
    else if (bid < 6144) cvt_inter(Wrel, g_wreli, bid-5632, tid, 10);
    else                 cvt_inter(Wo,   g_woi,   bid-6144, tid, 10);
}

// ---------------- QKVR projection GEMM (fp16 MMA, ping-pong, pure-copy staging) --
__global__ __launch_bounds__(256) void qkvr_mma()
{
    __shared__ __half   AsB[2*128*40];
    __shared__ unsigned BsB[2*16*136];

    int bid = blockIdx.x;
    int mode, m0, n0, N;
    const unsigned* Wi;
    if (bid < 128)      { mode=0; m0=(bid>>3)<<7;  n0=(bid&7)<<7;  N=1024; Wi=g_wqi;  }
    else if (bid < 640) { int t=bid-128; mode=1; m0=(t>>4)<<7; n0=(t&15)<<7; N=2048; Wi=g_wkvi; }
    else                { int t=bid-640; mode=2; m0=(t>>3)<<7; n0=(t&7)<<7;  N=1024; Wi=g_wreli;}

    const int tid = threadIdx.x;
    const int warp = tid >> 5, lane = tid & 31;
    const int gq = lane >> 2, tq = lane & 3;
    const int wm = (warp >> 2) * 64, wn = (warp & 3) * 32;

    const int a_r = tid >> 1;
    const int a_cb = (tid & 1) * 16;
    const int grow = m0 + a_r;
    const __half* arow;
    if (mode==0)      arow = g_xh + (size_t)grow*DMODEL;
    else if (mode==1) arow = (grow < MEMLEN*BATCH) ? g_memh + (size_t)grow*DMODEL
                                                   : g_xh + (size_t)(grow - MEMLEN*BATCH)*DMODEL;
    else              arow = g_posh + (size_t)grow*DMODEL;

    const int b_k2 = tid >> 4;
    const int b_cb = (tid & 15) * 8;

    float acc[4][4][4];
    #pragma unroll
    for (int mi=0;mi<4;mi++)
        #pragma unroll
        for (int ni=0;ni<4;ni++)
            #pragma unroll
            for (int c=0;c<4;c++) acc[mi][ni][c]=0.f;

    {
        const __half* asrc = arow + a_cb;
        uint4 u0 = *(const uint4*)asrc, u1 = *(const uint4*)(asrc+8);
        __half* Ad = AsB + a_r*40 + a_cb;
        *(uint4*)Ad = u0; *(uint4*)(Ad+8) = u1;
        const unsigned* bsrc = Wi + (size_t)b_k2*N + n0 + b_cb;
        uint4 w0 = *(const uint4*)bsrc, w1 = *(const uint4*)(bsrc+4);
        unsigned* Bd = BsB + b_k2*136 + b_cb;
        *(uint4*)Bd = w0; *(uint4*)(Bd+4) = w1;
    }
    __syncthreads();

    for (int kc=0;kc<32;kc++){
        const unsigned* Ac2 = (const unsigned*)(AsB + (kc&1)*128*40);
        const unsigned* Bc  = BsB + (kc&1)*16*136;
        uint4 pa0, pa1, pb0, pb1;
        if (kc < 31){
            const __half* asrc = arow + (kc+1)*32 + a_cb;
            pa0 = *(const uint4*)asrc; pa1 = *(const uint4*)(asrc+8);
            const unsigned* bsrc = Wi + (size_t)((kc+1)*16 + b_k2)*N + n0 + b_cb;
            pb0 = *(const uint4*)bsrc; pb1 = *(const uint4*)(bsrc+4);
        }
        #pragma unroll
        for (int kk=0;kk<32;kk+=16){
            unsigned a[4][4], b[4][2];
            const int k2 = kk >> 1;
            #pragma unroll
            for (int mi=0;mi<4;mi++){
                int m = wm + mi*16;
                a[mi][0] = Ac2[(m+gq  )*20 + k2 + tq  ];
                a[mi][1] = Ac2[(m+gq+8)*20 + k2 + tq  ];
                a[mi][2] = Ac2[(m+gq  )*20 + k2 + tq+4];
                a[mi][3] = Ac2[(m+gq+8)*20 + k2 + tq+4];
            }
            #pragma unroll
            for (int ni=0;ni<4;ni++){
                int n = wn + ni*8 + gq;
                b[ni][0] = Bc[(k2+tq  )*136 + n];
                b[ni][1] = Bc[(k2+tq+4)*136 + n];
            }
            #pragma unroll
            for (int mi=0;mi<4;mi++)
                #pragma unroll
                for (int ni=0;ni<4;ni++)
                    mma_f16(acc[mi][ni], a[mi][0],a[mi][1],a[mi][2],a[mi][3], b[ni][0],b[ni][1]);
        }
        if (kc < 31){
            __half* An = AsB + ((kc+1)&1)*128*40 + a_r*40 + a_cb;
            *(uint4*)An = pa0; *(uint4*)(An+8) = pa1;
            unsigned* Bn = BsB + ((kc+1)&1)*16*136 + b_k2*136 + b_cb;
            *(uint4*)Bn = pb0; *(uint4*)(Bn+4) = pb1;
        }
        __syncthreads();
    }

    #pragma unroll
    for (int mi=0;mi<4;mi++){
        #pragma unroll
        for (int rr=0;rr<2;rr++){
            const int row = m0 + wm + mi*16 + gq + rr*8;
            const int t   = row >> 1, bb = row & 1;
            #pragma unroll
            for (int ni=0;ni<4;ni++){
                const int col = n0 + wn + ni*8 + 2*tq;
                unsigned hv = pack_h2(acc[mi][ni][rr*2+0], acc[mi][ni][rr*2+1]);
                if (mode==0){
                    int h = col >> 6, d = col & 63;
                    *reinterpret_cast<unsigned*>(&g_q[(((size_t)(bb*NH+h)*LQ + t)<<6) + d]) = hv;
                } else if (mode==1){
                    int c = col; __half* dst = g_k;
                    if (c >= NH*DHD){ dst = g_v; c -= NH*DHD; }
                    int h = c >> 6, d = c & 63;
                    *reinterpret_cast<unsigned*>(&dst[(((size_t)(bb*NH+h)*TT + t)<<6) + d]) = hv;
                } else {
                    int h = col >> 6, d = col & 63;
                    *reinterpret_cast<unsigned*>(&g_r[(((size_t)(bb*NH+h)*TT + t)<<6) + d]) = hv;
                }
            }
        }
    }
}

// ---------------- flash: scores (AC+BD) + exp + PV fused -------------------------
// SMEM layout (bytes):
//  Qs   half[128][72]  @ 0       (18432)
//  Ks   half[128][72]  @ 18432   (aliased by BDs float[128][68] = 34816)
//  Rs   half[64][72]   @ 53248   (9216)
//  Vs   uns [64][72]   @ 62464   (18432)
//  uKs f[128] @80896, vRs f[64] @81408, u_s f[64] @81664, v_s f[64] @81920
#define FL_SMEM_BYTES 82176
__global__ __launch_bounds__(256) void flash_mma(const float* __restrict__ ubias,
                                                 const float* __restrict__ vbias)
{
    const int gg = blockIdx.y, h = gg & (NH-1);
    const int bi = 7 - blockIdx.x;            // heavy CTAs first
    const int i0 = bi << 7;

    extern __shared__ char smr[];
    __half*   Qs  = (__half*)smr;
    __half*   Ks  = (__half*)(smr + 18432);
    float*    BDs = (float*) (smr + 18432);
    __half*   Rs  = (__half*)(smr + 53248);
    unsigned* Vs  = (unsigned*)(smr + 62464);
    float*    uKs = (float*)(smr + 80896);
    float*    vRs = uKs + 128;
    float*    u_s = vRs + 64;
    float*    v_s = u_s + 64;

    const int tid = threadIdx.x;
    const int warp = tid >> 5, lane = tid & 31;
    const int gq = lane >> 2, tq = lane & 3;
    const int wm = warp << 4;                  // 16 rows per warp
    const int wmb = (warp >> 1) * 32, wnb = (warp & 1) * 32;   // BD tiling

    const unsigned* Qs2 = (const unsigned*)Qs;  // stride 36
    const unsigned* Ks2 = (const unsigned*)Ks;
    const unsigned* Rs2 = (const unsigned*)Rs;

    // stage Q once + biases
    {
        const int sr = tid >> 1, cb = (tid & 1) * 32;
        const __half* qrow = g_q + (((size_t)gg*LQ + i0 + sr) << 6) + cb;
        #pragma unroll
        for (int q=0;q<4;q++)
            *(uint4*)&Qs[sr*72 + cb + q*8] = *(const uint4*)(qrow + q*8);
        if (tid < 64)       u_s[tid]    = ubias[(h<<6) + tid];
        else if (tid < 128) v_s[tid-64] = vbias[(h<<6) + tid - 64];
    }

    float acc_pv[8][4];
    #pragma unroll
    for (int ni=0;ni<8;ni++)
        #pragma unroll
        for (int c=0;c<4;c++) acc_pv[ni][c]=0.f;
    float rs0 = 0.f, rs1 = 0.f;

    const int jt_max = bi + 8;
    for (int jt=0; jt<=jt_max; jt++){
        const int j0 = jt << 7;
        const int delta = j0 - i0;
        __syncthreads();                       // protect Ks/Vs reuse (and Q stage at jt=0)
        // stage K tile
        {
            const int sr = tid >> 1, cb = (tid & 1) * 32;
            const __half* krow = g_k + (((size_t)gg*TT + j0 + sr) << 6) + cb;
            #pragma unroll
            for (int q=0;q<4;q++)
                *(uint4*)&Ks[sr*72 + cb + q*8] = *(const uint4*)(krow + q*8);
        }
        // stage V tile (interleaved k-pairs)
        {
            const int r = tid >> 2, cb2 = (tid & 3) * 16;
            const __half* vr0 = g_v + (((size_t)gg*TT + j0 + 2*r) << 6) + cb2;
            const __half* vr1 = vr0 + DHD;
            #pragma unroll
            for (int q=0;q<4;q++){
                uint2 x0 = *(const uint2*)(vr0 + q*4);
                uint2 x1 = *(const uint2*)(vr1 + q*4);
                unsigned w4[4] = { __byte_perm(x0.x,x1.x,0x5410), __byte_perm(x0.x,x1.x,0x7632),
                                   __byte_perm(x0.y,x1.y,0x5410), __byte_perm(x0.y,x1.y,0x7632) };
                *(uint4*)&Vs[r*72 + cb2 + q*4] = *(uint4*)w4;
            }
        }
        __syncthreads();
        // uK[j] = u . k_j
        if (tid < 128){
            float s = 0.f;
            #pragma unroll
            for (int d=0;d<64;d++) s += u_s[d] * __half2float(Ks[tid*72 + d]);
            uKs[tid] = s;
        }
        // AC = Q.K^T  (warp tile 16x128)
        float acc[16][4];
        #pragma unroll
        for (int ni=0;ni<16;ni++)
            #pragma unroll
            for (int c=0;c<4;c++) acc[ni][c]=0.f;
        #pragma unroll
        for (int kk=0;kk<64;kk+=16){
            const int k2 = kk >> 1;
            unsigned a0 = Qs2[(wm+gq  )*36 + k2 + tq  ];
            unsigned a1 = Qs2[(wm+gq+8)*36 + k2 + tq  ];
            unsigned a2 = Qs2[(wm+gq  )*36 + k2 + tq+4];
            unsigned a3 = Qs2[(wm+gq+8)*36 + k2 + tq+4];
            #pragma unroll
            for (int ni=0;ni<16;ni++){
                int n = ni*8 + gq;
                unsigned b0 = Ks2[n*36 + k2 + tq  ];
                unsigned b1 = Ks2[n*36 + k2 + tq+4];
                mma_f16(acc[ni], a0,a1,a2,a3, b0,b1);
            }
        }
        // BD band in 4 chunks of 64 p-columns
        #pragma unroll 1
        for (int c=0;c<4;c++){
            {
                const int rsr = tid >> 2, rcb = (tid & 3) * 16;
                int rg = delta + 896 + c*64 + rsr;
                rg = min(max(rg, 0), TT-1);
                const __half* rrow = g_r + (((size_t)gg*TT + rg) << 6) + rcb;
                *(uint4*)&Rs[rsr*72 + rcb]     = *(const uint4*)(rrow);
                *(uint4*)&Rs[rsr*72 + rcb + 8] = *(const uint4*)(rrow + 8);
            }
            __syncthreads();
            if (tid < 64){
                float s = 0.f;
                #pragma unroll
                for (int d=0;d<64;d++) s += v_s[d] * __half2float(Rs[tid*72 + d]);
                vRs[tid] = s;
            }
            float abd[2][4][4];
            #pragma unroll
            for (int mi=0;mi<2;mi++)
                #pragma unroll
                for (int ni=0;ni<4;ni++)
                    #pragma unroll
                    for (int e=0;e<4;e++) abd[mi][ni][e]=0.f;
            #pragma unroll
            for (int kk=0;kk<64;kk+=16){
                const int k2 = kk >> 1;
                unsigned a[2][4], b[4][2];
                #pragma unroll
                for (int mi=0;mi<2;mi++){
                    int m = wmb + mi*16;
                    a[mi][0] = Qs2[(m+gq  )*36 + k2 + tq  ];
                    a[mi][1] = Qs2[(m+gq+8)*36 + k2 + tq  ];
                    a[mi][2] = Qs2[(m+gq  )*36 + k2 + tq+4];
                    a[mi][3] = Qs2[(m+gq+8)*36 + k2 + tq+4];
                }
                #pragma unroll
                for (int ni=0;ni<4;ni++){
                    int n = wnb + ni*8 + gq;
                    b[ni][0] = Rs2[n*36 + k2 + tq  ];
                    b[ni][1] = Rs2[n*36 + k2 + tq+4];
                }
                #pragma unroll
                for (int mi=0;mi<2;mi++)
                    #pragma unroll
                    for (int ni=0;ni<4;ni++)
                        mma_f16(abd[mi][ni], a[mi][0],a[mi][1],a[mi][2],a[mi][3], b[ni][0],b[ni][1]);
            }
            __syncthreads();
            #pragma unroll
            for (int mi=0;mi<2;mi++)
                #pragma unroll
                for (int rr=0;rr<2;rr++){
                    int il = wmb + mi*16 + gq + rr*8;
                    #pragma unroll
                    for (int ni=0;ni<4;ni++){
                        int pl = wnb + ni*8 + 2*tq;
                        float2 v = { abd[mi][ni][rr*2+0], abd[mi][ni][rr*2+1] };
                        *(float2*)&BDs[il*68 + pl] = v;
                    }
                }
            __syncthreads();
            const int poff = 127 - c*64;
            const int il0 = wm + gq, il1 = wm + gq + 8;
            #pragma unroll
            for (int ni=0;ni<16;ni++){
                int jl = ni*8 + 2*tq;
                int p0 = jl - il0 + poff;
                if (p0 >= 0 && p0 < 64) acc[ni][0] += BDs[il0*68 + p0] + vRs[p0];
                if (p0+1 >= 0 && p0+1 < 64) acc[ni][1] += BDs[il0*68 + p0+1] + vRs[p0+1];
                int p2 = jl - il1 + poff;
                if (p2 >= 0 && p2 < 64) acc[ni][2] += BDs[il1*68 + p2] + vRs[p2];
                if (p2+1 >= 0 && p2+1 < 64) acc[ni][3] += BDs[il1*68 + p2+1] + vRs[p2+1];
            }
        }
        // exp + pack + write p + row sums
        const bool isDiag = (delta == 1024);
        const int il0 = wm + gq, il1 = wm + gq + 8;
        unsigned pfrag[16][2];
        __half* prow0 = g_p + ((size_t)gg*LQ + i0 + il0)*TT + j0;
        __half* prow1 = g_p + ((size_t)gg*LQ + i0 + il1)*TT + j0;
        #pragma unroll
        for (int ni=0;ni<16;ni++){
            const int jl = ni*8 + 2*tq;
            float u0 = uKs[jl], u1 = uKs[jl+1];
            float p0 = __expf((acc[ni][0] + u0)*SCALE_F - EXPC);
            float p1 = __expf((acc[ni][1] + u1)*SCALE_F - EXPC);
            float p2 = __expf((acc[ni][2] + u0)*SCALE_F - EXPC);
            float p3 = __expf((acc[ni][3] + u1)*SCALE_F - EXPC);
            if (isDiag){
                if (jl   > il0) p0 = 0.f;
                if (jl+1 > il0) p1 = 0.f;
                if (jl   > il1) p2 = 0.f;
                if (jl+1 > il1) p3 = 0.f;
            }
            rs0 += p0 + p1;
            rs1 += p2 + p3;
            unsigned lo = pack_h2(p0, p1), hi = pack_h2(p2, p3);
            *reinterpret_cast<unsigned*>(prow0 + jl) = lo;
            *reinterpret_cast<unsigned*>(prow1 + jl) = hi;
            pfrag[ni][0] = lo;
            pfrag[ni][1] = hi;
        }
        // PV: acc_pv += P(tile) @ V(tile)
        #pragma unroll
        for (int s=0;s<8;s++){
            unsigned a0 = pfrag[2*s][0], a1 = pfrag[2*s][1];
            unsigned a2 = pfrag[2*s+1][0], a3 = pfrag[2*s+1][1];
            const int kb = s*8;
            #pragma unroll
            for (int ni=0;ni<8;ni++){
                int n = ni*8 + gq;
                unsigned b0 = Vs[(kb+tq  )*72 + n];
                unsigned b1 = Vs[(kb+tq+4)*72 + n];
                mma_f16(acc_pv[ni], a0,a1,a2,a3, b0,b1);
            }
        }
    }

    // epilogue: row sums, normalize, write av
    rs0 += __shfl_xor_sync(0xffffffffu, rs0, 1);
    rs0 += __shfl_xor_sync(0xffffffffu, rs0, 2);
    rs1 += __shfl_xor_sync(0xffffffffu, rs1, 1);
    rs1 += __shfl_xor_sync(0xffffffffu, rs1, 2);
    const int row0 = i0 + wm + gq, row1 = row0 + 8;
    if (tq == 0){
        g_rs[gg*LQ + row0] = rs0;
        g_rs[gg*LQ + row1] = rs1;
    }
    const float inv0 = 1.f / rs0, inv1 = 1.f / rs1;
    const int b = gg >> 4;
    __half* dst0 = g_av + (size_t)(row0*BATCH + b)*DMODEL + (h<<6);
    __half* dst1 = g_av + (size_t)(row1*BATCH + b)*DMODEL + (h<<6);
    #pragma unroll
    for (int ni=0;ni<8;ni++){
        const int d = ni*8 + 2*tq;
        *reinterpret_cast<unsigned*>(dst0 + d) = pack_h2(acc_pv[ni][0]*inv0, acc_pv[ni][1]*inv0);
        *reinterpret_cast<unsigned*>(dst1 + d) = pack_h2(acc_pv[ni][2]*inv1, acc_pv[ni][3]*inv1);
    }
}

// ---------------- attn_matrix = mean over (b,h) of p/rs --------------------------
__global__ __launch_bounds__(256) void attnmat_kernel(float* __restrict__ out)
{
    const int i  = blockIdx.y;
    const int j0 = blockIdx.x << 8;
    const int jmax = i + MEMLEN;
    const int tid = threadIdx.x;
    const int jq = tid & 63;
    const int gsel = tid >> 6;
    const int j = j0 + jq*4;
    __shared__ float4 red[256];

    float4 s = {0.f,0.f,0.f,0.f};
    if (j0 <= jmax){
        const bool edge = (j + 3 > jmax);
        #pragma unroll
        for (int gi=0; gi<8; gi++){
            int g = gsel*8 + gi;
            float inv = 1.f / g_rs[g*LQ + i];
            uint2 raw = *(const uint2*)(g_p + ((size_t)g*LQ + i)*TT + j);
            float2 f0 = __half22float2(*reinterpret_cast<__half2*>(&raw.x));
            float2 f1 = __half22float2(*reinterpret_cast<__half2*>(&raw.y));
            if (edge){
                if (j+0 > jmax) f0.x = 0.f;
                if (j+1 > jmax) f0.y = 0.f;
                if (j+2 > jmax) f1.x = 0.f;
                if (j+3 > jmax) f1.y = 0.f;
            }
            s.x += f0.x*inv; s.y += f0.y*inv; s.z += f1.x*inv; s.w += f1.y*inv;
        }
    }
    red[tid] = s;
    __syncthreads();
    if (tid < 64){
        float4 a=red[tid], b=red[tid+64], c=red[tid+128], d=red[tid+192];
        const float k = 1.f/NG;
        float4 o = { (a.x+b.x+c.x+d.x)*k, (a.y+b.y+c.y+d.y)*k,
                     (a.z+b.z+c.z+d.z)*k, (a.w+b.w+c.w+d.w)*k };
        *(float4*)(out + (size_t)i*TT + j0 + tid*4) = o;
    }
}

// ---------------- Wo GEMM + residual (fp16 MMA): g_h = x + g_av @ Wo ------------
__global__ __launch_bounds__(256) void wo_mma(const float* __restrict__ x)
{
    const int m0 = blockIdx.y << 7;
    const int n0 = blockIdx.x << 6;

    __shared__ __half   As[128*40];
    __shared__ unsigned Bs[16*72];

    const int tid = threadIdx.x;
    const int warp = tid >> 5, lane = tid & 31;
    const int gq = lane >> 2, tq = lane & 3;
    const int wm = (warp >> 1) * 32, wn = (warp & 1) * 32;
    const unsigned* As2 = (const unsigned*)As;

    float acc[2][4][4];
    #pragma unroll
    for (int mi=0;mi<2;mi++)
        #pragma unroll
        for (int ni=0;ni<4;ni++)
            #pragma unroll
            for (int c=0;c<4;c++) acc[mi][ni][c]=0.f;

    const int a_r = tid >> 1;
    const int a_cb = (tid & 1) * 16;
    const __half* arow = g_av + (size_t)(m0 + a_r)*DMODEL + a_cb;
    const int b_k2 = tid >> 4;
    const int b_cb = (tid & 15) * 4;

    for (int k0=0;k0<DMODEL;k0+=32){
        {
            __half* Ad = As + a_r*40 + a_cb;
            *(uint4*)Ad     = *(const uint4*)(arow + k0);
            *(uint4*)(Ad+8) = *(const uint4*)(arow + k0 + 8);
            const unsigned* bsrc = g_woi + (size_t)((k0>>1) + b_k2)*DMODEL + n0 + b_cb;
            *(uint4*)&Bs[b_k2*72 + b_cb] = *(const uint4*)bsrc;
        }
        __syncthreads();
        #pragma unroll
        for (int kk=0;kk<32;kk+=16){
            const int k2 = kk >> 1;
            unsigned a[2][4], bfr[4][2];
            #pragma unroll
            for (int mi=0;mi<2;mi++){
                int m = wm + mi*16;
                a[mi][0] = As2[(m+gq  )*20 + k2 + tq  ];
                a[mi][1] = As2[(m+gq+8)*20 + k2 + tq  ];
                a[mi][2] = As2[(m+gq  )*20 + k2 + tq+4];
                a[mi][3] = As2[(m+gq+8)*20 + k2 + tq+4];
            }
            #pragma unroll
            for (int ni=0;ni<4;ni++){
                int n = wn + ni*8 + gq;
                bfr[ni][0] = Bs[(k2+tq  )*72 + n];
                bfr[ni][1] = Bs[(k2+tq+4)*72 + n];
            }
            #pragma unroll
            for (int mi=0;mi<2;mi++)
                #pragma unroll
                for (int ni=0;ni<4;ni++)
                    mma_f16(acc[mi][ni], a[mi][0],a[mi][1],a[mi][2],a[mi][3], bfr[ni][0],bfr[ni][1]);
        }
        __syncthreads();
    }

    #pragma unroll
    for (int mi=0;mi<2;mi++)
        #pragma unroll
        for (int rr=0;rr<2;rr++){
            const int row = m0 + wm + mi*16 + gq + rr*8;
            #pragma unroll
            for (int ni=0;ni<4;ni++){
                const int col = n0 + wn + ni*8 + 2*tq;
                float2 xv = *(const float2*)&x[(size_t)row*DMODEL + col];
                float2 val = { acc[mi][ni][rr*2+0] + xv.x,
                               acc[mi][ni][rr*2+1] + xv.y };
                *(float2*)&g_h[(size_t)row*DMODEL + col] = val;
            }
        }
}

// ---------------- layernorm ------------------------------------------------------
__global__ __launch_bounds__(256) void ln_kernel(const float* __restrict__ gamma,
                                                 const float* __restrict__ beta,
                                                 float* __restrict__ out)
{
    const int row = blockIdx.x;
    const float* hr = g_h + (size_t)row*DMODEL;
    const int c = threadIdx.x * 4;
    float4 v = *(const float4*)(hr + c);
    float s = v.x+v.y+v.z+v.w;
    s = blockSum(s);
    const float mu = s * (1.f/DMODEL);
    float dx = v.x-mu, dy = v.y-mu, dz = v.z-mu, dw = v.w-mu;
    float sq = dx*dx+dy*dy+dz*dz+dw*dw;
    sq = blockSum(sq);
    const float inv = rsqrtf(sq*(1.f/DMODEL) + 1e-5f);
    float4 gm = *(const float4*)(gamma + c);
    float4 bt = *(const float4*)(beta + c);
    float4 o;
    o.x = dx*inv*gm.x + bt.x;
    o.y = dy*inv*gm.y + bt.y;
    o.z = dz*inv*gm.z + bt.z;
    o.w = dw*inv*gm.w + bt.w;
    *(float4*)(out + (size_t)row*DMODEL + c) = o;
}

// ---------------- launch ----------------------------------------------------------
extern "C" void kernel_launch(void* const* d_in, const int* in_sizes, int n_in,
                              void* d_out, int out_size)
{
    const float* x        = (const float*)d_in[0];
    const float* pos_emb  = (const float*)d_in[1];
    const float* memory   = (const float*)d_in[2];
    const float* ubias    = (const float*)d_in[3];
    const float* vbias    = (const float*)d_in[4];
    const float* Wq       = (const float*)d_in[6];
    const float* Wkv      = (const float*)d_in[7];
    const float* Wrel     = (const float*)d_in[8];
    const float* Wo       = (const float*)d_in[9];
    const float* gamma    = (const float*)d_in[10];
    const float* beta     = (const float*)d_in[11];
    float* out    = (float*)d_out;
    float* out_am = out + (size_t)LQ*BATCH*DMODEL;

    cudaFuncSetAttribute(flash_mma, cudaFuncAttributeMaxDynamicSharedMemorySize, FL_SMEM_BYTES);

    cvt_all<<<6656, 256>>>(x, memory, pos_emb, Wq, Wkv, Wrel, Wo);
    qkvr_mma<<<896, 256>>>();
    flash_mma<<<dim3(8, NG), 256, FL_SMEM_BYTES>>>(ubias, vbias);
    attnmat_kernel<<<dim3(8, LQ), 256>>>(out_am);
    wo_mma<<<dim3(16,16), 256>>>(x);
    ln_kernel<<<LQ*BATCH, 256>>>(gamma, beta, out);
}

// round 9
// speedup vs baseline: 5.0933x; 1.2004x over previous
#include <cuda_runtime.h>
#include <cuda_fp16.h>
#include <math.h>

#define LQ      1024
#define BATCH   2
#define DMODEL  1024
#define NH      16
#define DHD     64
#define MEMLEN  1024
#define TT      2048
#define NG      (BATCH*NH)
#define SCALE_F 0.125f
#define EXPC    8.0f
#define SROW    72          // halves per staged row
#define SROWB   144         // bytes per staged row
#define BDS     132         // floats per BD strip row

// ---------------- scratch -------------------------------------------------------
__device__ __half g_q [NG*LQ*DHD];
__device__ __half g_k [NG*TT*DHD];
__device__ __half g_v [NG*TT*DHD];
__device__ __half g_r [NG*TT*DHD];
__device__ __half g_p [(size_t)NG*LQ*TT];            // unnormalized e^(s-8) (fp16)
__device__ float  g_rs[NG*LQ];                       // row sums of e^(s-8)
__device__ __half g_av[LQ*BATCH*NH*DHD];
__device__ float  g_h [LQ*BATCH*DMODEL];
// fp16 pre-converted inputs / weights
__device__ __half   g_xh  [LQ*BATCH*DMODEL];
__device__ __half   g_memh[MEMLEN*BATCH*DMODEL];
__device__ __half   g_posh[TT*BATCH*DMODEL];
__device__ unsigned g_wqi  [512*1024];               // (W[2k],W[2k+1]) half2 pairs
__device__ unsigned g_wkvi [512*2048];
__device__ unsigned g_wreli[512*1024];
__device__ unsigned g_woi  [512*1024];

// ---------------- helpers ---------------------------------------------------------
__device__ __forceinline__ unsigned pack_h2(float a, float b){
    __half2 h = __floats2half2_rn(a, b);
    return *reinterpret_cast<unsigned*>(&h);
}
__device__ __forceinline__ void mma_f16(float c[4],
                                        unsigned a0, unsigned a1, unsigned a2, unsigned a3,
                                        unsigned b0, unsigned b1){
    asm volatile("mma.sync.aligned.m16n8k16.row.col.f32.f16.f16.f32 "
        "{%0,%1,%2,%3}, {%4,%5,%6,%7}, {%8,%9}, {%0,%1,%2,%3};"
        : "+f"(c[0]), "+f"(c[1]), "+f"(c[2]), "+f"(c[3])
        : "r"(a0), "r"(a1), "r"(a2), "r"(a3), "r"(b0), "r"(b1));
}
__device__ __forceinline__ unsigned smem_u32(const void* p){
    return (unsigned)__cvta_generic_to_shared(p);
}
__device__ __forceinline__ void ldsm4(unsigned &r0, unsigned &r1, unsigned &r2, unsigned &r3, unsigned a){
    asm volatile("ldmatrix.sync.aligned.m8n8.x4.shared.b16 {%0,%1,%2,%3}, [%4];"
        : "=r"(r0),"=r"(r1),"=r"(r2),"=r"(r3) : "r"(a));
}
__device__ __forceinline__ void ldsm4t(unsigned &r0, unsigned &r1, unsigned &r2, unsigned &r3, unsigned a){
    asm volatile("ldmatrix.sync.aligned.m8n8.x4.trans.shared.b16 {%0,%1,%2,%3}, [%4];"
        : "=r"(r0),"=r"(r1),"=r"(r2),"=r"(r3) : "r"(a));
}

__device__ __forceinline__ float blockSum(float v){
    __shared__ float sm[32];
    int lane = threadIdx.x & 31, w = threadIdx.x >> 5;
    #pragma unroll
    for (int o=16;o>0;o>>=1) v += __shfl_xor_sync(0xffffffffu, v, o);
    if (lane==0) sm[w] = v;
    __syncthreads();
    float r = (threadIdx.x < 8) ? sm[threadIdx.x] : 0.f;
    if (w==0){
        #pragma unroll
        for (int o=4;o>0;o>>=1) r += __shfl_xor_sync(0xffffffffu, r, o);
        if (lane==0) sm[0]=r;
    }
    __syncthreads();
    r = sm[0];
    __syncthreads();
    return r;
}

// ---------------- fp16 pre-conversion -------------------------------------------
__device__ __forceinline__ void cvt_plain(const float* __restrict__ s, __half* d, int b, int t){
    const int idx = b*2048 + t*8;
    float4 v0 = *(const float4*)(s+idx), v1 = *(const float4*)(s+idx+4);
    unsigned u[4] = { pack_h2(v0.x,v0.y), pack_h2(v0.z,v0.w),
                      pack_h2(v1.x,v1.y), pack_h2(v1.z,v1.w) };
    *(uint4*)&d[idx] = *(uint4*)u;
}
__device__ __forceinline__ void cvt_inter(const float* __restrict__ W, unsigned* d,
                                          int b, int t, int lgN){
    const int p = b*1024 + t*4;
    const int N = 1 << lgN;
    const int k2 = p >> lgN, n = p & (N-1);
    const float* r0 = W + ((size_t)k2*2)*N + n;
    float4 a = *(const float4*)r0;
    float4 c = *(const float4*)(r0 + N);
    unsigned u[4] = { pack_h2(a.x,c.x), pack_h2(a.y,c.y),
                      pack_h2(a.z,c.z), pack_h2(a.w,c.w) };
    *(uint4*)&d[p] = *(uint4*)u;
}
__global__ __launch_bounds__(256) void cvt_all(const float* __restrict__ x,
                                               const float* __restrict__ memory,
                                               const float* __restrict__ pos_emb,
                                               const float* __restrict__ Wq,
                                               const float* __restrict__ Wkv,
                                               const float* __restrict__ Wrel,
                                               const float* __restrict__ Wo)
{
    const int bid = blockIdx.x, tid = threadIdx.x;
    if      (bid < 1024) cvt_plain(x,       g_xh,   bid,        tid);
    else if (bid < 2048) cvt_plain(memory,  g_memh, bid-1024,   tid);
    else if (bid < 4096) cvt_plain(pos_emb, g_posh, bid-2048,   tid);
    else if (bid < 4608) cvt_inter(Wq,   g_wqi,   bid-4096, tid, 10);
    else if (bid < 5632) cvt_inter(Wkv,  g_wkvi,  bid-4608, tid, 11);
    else if (bid < 6144) cvt_inter(Wrel, g_wreli, bid-5632, tid, 10);
    else                 cvt_inter(Wo,   g_woi,   bid-6144, tid, 10);
}

// ---------------- QKVR projection GEMM (fp16 MMA, ping-pong, ldmatrix A) --------
__global__ __launch_bounds__(256) void qkvr_mma()
{
    __shared__ __half   AsB[2*128*40];
    __shared__ unsigned BsB[2*16*136];

    int bid = blockIdx.x;
    int mode, m0, n0, N;
    const unsigned* Wi;
    if (bid < 128)      { mode=0; m0=(bid>>3)<<7;  n0=(bid&7)<<7;  N=1024; Wi=g_wqi;  }
    else if (bid < 640) { int t=bid-128; mode=1; m0=(t>>4)<<7; n0=(t&15)<<7; N=2048; Wi=g_wkvi; }
    else                { int t=bid-640; mode=2; m0=(t>>3)<<7; n0=(t&7)<<7;  N=1024; Wi=g_wreli;}

    const int tid = threadIdx.x;
    const int warp = tid >> 5, lane = tid & 31;
    const int gq = lane >> 2, tq = lane & 3;
    const int sel = lane >> 3, l7 = lane & 7;
    const int wm = (warp >> 2) * 64, wn = (warp & 3) * 32;

    const unsigned as_u32 = smem_u32(AsB);
    const unsigned a_off  = (((sel&1)*8 + l7)*40 + (sel>>1)*8)*2;

    const int a_r = tid >> 1;
    const int a_cb = (tid & 1) * 16;
    const int grow = m0 + a_r;
    const __half* arow;
    if (mode==0)      arow = g_xh + (size_t)grow*DMODEL;
    else if (mode==1) arow = (grow < MEMLEN*BATCH) ? g_memh + (size_t)grow*DMODEL
                                                   : g_xh + (size_t)(grow - MEMLEN*BATCH)*DMODEL;
    else              arow = g_posh + (size_t)grow*DMODEL;

    const int b_k2 = tid >> 4;
    const int b_cb = (tid & 15) * 8;

    float acc[4][4][4];
    #pragma unroll
    for (int mi=0;mi<4;mi++)
        #pragma unroll
        for (int ni=0;ni<4;ni++)
            #pragma unroll
            for (int c=0;c<4;c++) acc[mi][ni][c]=0.f;

    {
        const __half* asrc = arow + a_cb;
        uint4 u0 = *(const uint4*)asrc, u1 = *(const uint4*)(asrc+8);
        __half* Ad = AsB + a_r*40 + a_cb;
        *(uint4*)Ad = u0; *(uint4*)(Ad+8) = u1;
        const unsigned* bsrc = Wi + (size_t)b_k2*N + n0 + b_cb;
        uint4 w0 = *(const uint4*)bsrc, w1 = *(const uint4*)(bsrc+4);
        unsigned* Bd = BsB + b_k2*136 + b_cb;
        *(uint4*)Bd = w0; *(uint4*)(Bd+4) = w1;
    }
    __syncthreads();

    for (int kc=0;kc<32;kc++){
        const unsigned abuf = as_u32 + (kc&1)*10240;
        const unsigned* Bc  = BsB + (kc&1)*16*136;
        uint4 pa0, pa1, pb0, pb1;
        if (kc < 31){
            const __half* asrc = arow + (kc+1)*32 + a_cb;
            pa0 = *(const uint4*)asrc; pa1 = *(const uint4*)(asrc+8);
            const unsigned* bsrc = Wi + (size_t)((kc+1)*16 + b_k2)*N + n0 + b_cb;
            pb0 = *(const uint4*)bsrc; pb1 = *(const uint4*)(bsrc+4);
        }
        #pragma unroll
        for (int kk=0;kk<32;kk+=16){
            unsigned a[4][4], b[4][2];
            const int k2 = kk >> 1;
            #pragma unroll
            for (int mi=0;mi<4;mi++)
                ldsm4(a[mi][0],a[mi][1],a[mi][2],a[mi][3],
                      abuf + (wm + mi*16)*80 + a_off + kk*2);
            #pragma unroll
            for (int ni=0;ni<4;ni++){
                int n = wn + ni*8 + gq;
                b[ni][0] = Bc[(k2+tq  )*136 + n];
                b[ni][1] = Bc[(k2+tq+4)*136 + n];
            }
            #pragma unroll
            for (int mi=0;mi<4;mi++)
                #pragma unroll
                for (int ni=0;ni<4;ni++)
                    mma_f16(acc[mi][ni], a[mi][0],a[mi][1],a[mi][2],a[mi][3], b[ni][0],b[ni][1]);
        }
        if (kc < 31){
            __half* An = AsB + ((kc+1)&1)*128*40 + a_r*40 + a_cb;
            *(uint4*)An = pa0; *(uint4*)(An+8) = pa1;
            unsigned* Bn = BsB + ((kc+1)&1)*16*136 + b_k2*136 + b_cb;
            *(uint4*)Bn = pb0; *(uint4*)(Bn+4) = pb1;
        }
        __syncthreads();
    }

    #pragma unroll
    for (int mi=0;mi<4;mi++){
        #pragma unroll
        for (int rr=0;rr<2;rr++){
            const int row = m0 + wm + mi*16 + gq + rr*8;
            const int t   = row >> 1, bb = row & 1;
            #pragma unroll
            for (int ni=0;ni<4;ni++){
                const int col = n0 + wn + ni*8 + 2*tq;
                unsigned hv = pack_h2(acc[mi][ni][rr*2+0], acc[mi][ni][rr*2+1]);
                if (mode==0){
                    int h = col >> 6, d = col & 63;
                    *reinterpret_cast<unsigned*>(&g_q[(((size_t)(bb*NH+h)*LQ + t)<<6) + d]) = hv;
                } else if (mode==1){
                    int c = col; __half* dst = g_k;
                    if (c >= NH*DHD){ dst = g_v; c -= NH*DHD; }
                    int h = c >> 6, d = c & 63;
                    *reinterpret_cast<unsigned*>(&dst[(((size_t)(bb*NH+h)*TT + t)<<6) + d]) = hv;
                } else {
                    int h = col >> 6, d = col & 63;
                    *reinterpret_cast<unsigned*>(&g_r[(((size_t)(bb*NH+h)*TT + t)<<6) + d]) = hv;
                }
            }
        }
    }
}

// ---------------- BD strip compute: BDslot[128][132] = Q(128x64) . Rs(128x64)^T --
__device__ __forceinline__ void compute_strip(unsigned qs_u32, unsigned rs_u32,
                                              float* BDslot, int warp, int lane)
{
    const int sel = lane >> 3, l7 = lane & 7;
    const int gq = lane >> 2, tq = lane & 3;
    const int wmb = (warp >> 1) * 32, wnb = (warp & 1) * 64;
    const unsigned offA = (((sel&1)*8 + l7)*SROW + (sel>>1)*8)*2;
    const unsigned offB = (((sel>>1)*8 + l7)*SROW + (sel&1)*8)*2;

    #pragma unroll
    for (int pass=0; pass<2; pass++){
        float abd[2][4][4];
        #pragma unroll
        for (int mi=0;mi<2;mi++)
            #pragma unroll
            for (int ni=0;ni<4;ni++)
                #pragma unroll
                for (int e=0;e<4;e++) abd[mi][ni][e]=0.f;
        #pragma unroll
        for (int kk=0;kk<64;kk+=16){
            unsigned am[2][4];
            #pragma unroll
            for (int mi=0;mi<2;mi++)
                ldsm4(am[mi][0],am[mi][1],am[mi][2],am[mi][3],
                      qs_u32 + (wmb + mi*16)*SROWB + offA + kk*2);
            #pragma unroll
            for (int q=0;q<2;q++){
                unsigned b0,b1,b2,b3;
                ldsm4(b0,b1,b2,b3,
                      rs_u32 + (wnb + pass*32 + 16*q)*SROWB + offB + kk*2);
                mma_f16(abd[0][2*q  ], am[0][0],am[0][1],am[0][2],am[0][3], b0,b1);
                mma_f16(abd[0][2*q+1], am[0][0],am[0][1],am[0][2],am[0][3], b2,b3);
                mma_f16(abd[1][2*q  ], am[1][0],am[1][1],am[1][2],am[1][3], b0,b1);
                mma_f16(abd[1][2*q+1], am[1][0],am[1][1],am[1][2],am[1][3], b2,b3);
            }
        }
        #pragma unroll
        for (int mi=0;mi<2;mi++)
            #pragma unroll
            for (int rr=0;rr<2;rr++){
                const int il = wmb + mi*16 + gq + rr*8;
                #pragma unroll
                for (int ni=0;ni<4;ni++){
                    const int pl = wnb + pass*32 + ni*8 + 2*tq;
                    float2 v = { abd[mi][ni][rr*2+0], abd[mi][ni][rr*2+1] };
                    *(float2*)&BDslot[il*BDS + pl] = v;
                }
            }
    }
}

// ---------------- flash: scores (AC + strip-shared BD) + exp + PV ----------------
#define FL_SMEM_BYTES 210944
__global__ __launch_bounds__(256) void flash_mma(const float* __restrict__ ubias,
                                                 const float* __restrict__ vbias)
{
    const int gg = blockIdx.y, h = gg & (NH-1);
    const int bi = 7 - blockIdx.x;            // heavy CTAs first
    const int i0 = bi << 7;

    extern __shared__ char smr[];
    __half* Qs = (__half*)smr;                 // [128][72]
    __half* Ks = (__half*)(smr + 18432);       // [128][72]
    __half* Rs = (__half*)(smr + 36864);       // [128][72]
    __half* Vs = (__half*)(smr + 55296);       // [128 t][72 d]
    float*  BD0 = (float*)(smr + 73728);       // [128][132]
    float*  BD1 = (float*)(smr + 141312);
    float*  uKs = (float*)(smr + 208896);      // [128]
    float*  vR0 = (float*)(smr + 209408);      // [128]
    float*  vR1 = (float*)(smr + 209920);
    float*  u_s = (float*)(smr + 210432);      // [64]
    float*  v_s = (float*)(smr + 210688);

    const int tid = threadIdx.x;
    const int warp = tid >> 5, lane = tid & 31;
    const int gq = lane >> 2, tq = lane & 3;
    const int sel = lane >> 3, l7 = lane & 7;
    const int wm = warp << 4;                  // 16 AC rows per warp

    const unsigned qs_u32 = smem_u32(Qs);
    const unsigned ks_u32 = smem_u32(Ks);
    const unsigned rs_u32 = smem_u32(Rs);
    const unsigned vs_u32 = smem_u32(Vs);
    const unsigned offA = (((sel&1)*8 + l7)*SROW + (sel>>1)*8)*2;
    const unsigned offB = (((sel>>1)*8 + l7)*SROW + (sel&1)*8)*2;
    const unsigned qsA = qs_u32 + wm*SROWB + offA;
    const unsigned ksB = ks_u32 + offB;
    const unsigned vsB = vs_u32 + offA;

    const int sr = tid >> 1, cb = (tid & 1) * 32;

    // ---- prologue: stage Q, biases, strip 0 ----
    {
        const __half* qrow = g_q + (((size_t)gg*LQ + i0 + sr) << 6) + cb;
        #pragma unroll
        for (int q=0;q<4;q++)
            *(uint4*)&Qs[sr*SROW + cb + q*8] = *(const uint4*)(qrow + q*8);
        if (tid < 64)       u_s[tid]    = ubias[(h<<6) + tid];
        else if (tid < 128) v_s[tid-64] = vbias[(h<<6) + tid - 64];
        const int ps0 = (7 - bi) << 7;
        const __half* rrow = g_r + (((size_t)gg*TT + ps0 + sr) << 6) + cb;
        #pragma unroll
        for (int q=0;q<4;q++)
            *(uint4*)&Rs[sr*SROW + cb + q*8] = *(const uint4*)(rrow + q*8);
    }
    __syncthreads();
    if (tid >= 128){
        const int c = tid - 128;
        float s = 0.f;
        #pragma unroll
        for (int d=0;d<64;d++) s += v_s[d] * __half2float(Rs[c*SROW + d]);
        vR0[c] = s;
    }
    compute_strip(qs_u32, rs_u32, BD0, warp, lane);

    float acc_pv[8][4];
    #pragma unroll
    for (int ni=0;ni<8;ni++)
        #pragma unroll
        for (int c=0;c<4;c++) acc_pv[ni][c]=0.f;
    float rs_0 = 0.f, rs_1 = 0.f;

    const int jt_max = bi + 8;
    for (int jt=0; jt<=jt_max; jt++){
        const int j0 = jt << 7;
        const bool doStrip = (jt < jt_max);
        __syncthreads();                       // S1
        // stage K, V (and R for strip jt+1)
        {
            const __half* krow = g_k + (((size_t)gg*TT + j0 + sr) << 6) + cb;
            const __half* vrow = g_v + (((size_t)gg*TT + j0 + sr) << 6) + cb;
            #pragma unroll
            for (int q=0;q<4;q++){
                *(uint4*)&Ks[sr*SROW + cb + q*8] = *(const uint4*)(krow + q*8);
                *(uint4*)&Vs[sr*SROW + cb + q*8] = *(const uint4*)(vrow + q*8);
            }
            if (doStrip){
                const int ps = (jt + 1 - bi + 7) << 7;
                const __half* rrow = g_r + (((size_t)gg*TT + ps + sr) << 6) + cb;
                #pragma unroll
                for (int q=0;q<4;q++)
                    *(uint4*)&Rs[sr*SROW + cb + q*8] = *(const uint4*)(rrow + q*8);
            }
        }
        __syncthreads();                       // S2
        if (tid < 128){
            float s = 0.f;
            #pragma unroll
            for (int d=0;d<64;d++) s += u_s[d] * __half2float(Ks[tid*SROW + d]);
            uKs[tid] = s;
        } else if (doStrip){
            const int c = tid - 128;
            float s = 0.f;
            #pragma unroll
            for (int d=0;d<64;d++) s += v_s[d] * __half2float(Rs[c*SROW + d]);
            (((jt+1)&1) ? vR1 : vR0)[c] = s;
        }
        // AC = Q.K^T (warp tile 16x128) via ldmatrix
        float acc[16][4];
        #pragma unroll
        for (int ni=0;ni<16;ni++)
            #pragma unroll
            for (int c=0;c<4;c++) acc[ni][c]=0.f;
        #pragma unroll
        for (int kk=0;kk<64;kk+=16){
            unsigned a0,a1,a2,a3;
            ldsm4(a0,a1,a2,a3, qsA + kk*2);
            #pragma unroll
            for (int q=0;q<8;q++){
                unsigned b0,b1,b2,b3;
                ldsm4(b0,b1,b2,b3, ksB + q*2304 + kk*2);
                mma_f16(acc[2*q  ], a0,a1,a2,a3, b0,b1);
                mma_f16(acc[2*q+1], a0,a1,a2,a3, b2,b3);
            }
        }
        if (doStrip)
            compute_strip(qs_u32, rs_u32, ((jt+1)&1) ? BD1 : BD0, warp, lane);
        __syncthreads();                       // S3
        // gather + exp + mask + write p + row sums
        const bool isDiag = (jt == jt_max);
        const float* BDa = (jt & 1) ? BD1 : BD0;
        const float* BDb = (jt & 1) ? BD0 : BD1;
        const float* vRa = (jt & 1) ? vR1 : vR0;
        const float* vRb = (jt & 1) ? vR0 : vR1;
        const int il0 = wm + gq, il1 = il0 + 8;
        unsigned pfrag[16][2];
        __half* prow0 = g_p + ((size_t)gg*LQ + i0 + il0)*TT + j0;
        __half* prow1 = g_p + ((size_t)gg*LQ + i0 + il1)*TT + j0;
        #pragma unroll
        for (int ni=0;ni<16;ni++){
            const int jl = ni*8 + 2*tq;
            const int o00 = jl - il0 + 127;
            const int o10 = jl - il1 + 127;
            float bd00 = (o00   < 128) ? BDa[il0*BDS + o00    ] + vRa[o00    ] : BDb[il0*BDS + o00-128] + vRb[o00-128];
            float bd01 = (o00+1 < 128) ? BDa[il0*BDS + o00 + 1] + vRa[o00 + 1] : BDb[il0*BDS + o00-127] + vRb[o00-127];
            float bd10 = (o10   < 128) ? BDa[il1*BDS + o10    ] + vRa[o10    ] : BDb[il1*BDS + o10-128] + vRb[o10-128];
            float bd11 = (o10+1 < 128) ? BDa[il1*BDS + o10 + 1] + vRa[o10 + 1] : BDb[il1*BDS + o10-127] + vRb[o10-127];
            const float u0 = uKs[jl], u1 = uKs[jl+1];
            float p0 = __expf((acc[ni][0] + bd00 + u0)*SCALE_F - EXPC);
            float p1 = __expf((acc[ni][1] + bd01 + u1)*SCALE_F - EXPC);
            float p2 = __expf((acc[ni][2] + bd10 + u0)*SCALE_F - EXPC);
            float p3 = __expf((acc[ni][3] + bd11 + u1)*SCALE_F - EXPC);
            if (isDiag){
                if (jl   > il0) p0 = 0.f;
                if (jl+1 > il0) p1 = 0.f;
                if (jl   > il1) p2 = 0.f;
                if (jl+1 > il1) p3 = 0.f;
            }
            rs_0 += p0 + p1;
            rs_1 += p2 + p3;
            unsigned lo = pack_h2(p0, p1), hi = pack_h2(p2, p3);
            *reinterpret_cast<unsigned*>(prow0 + jl) = lo;
            *reinterpret_cast<unsigned*>(prow1 + jl) = hi;
            pfrag[ni][0] = lo;
            pfrag[ni][1] = hi;
        }
        // PV: acc_pv += P(tile) @ V(tile), V frags via ldmatrix.trans
        #pragma unroll
        for (int s=0;s<8;s++){
            unsigned a0 = pfrag[2*s][0], a1 = pfrag[2*s][1];
            unsigned a2 = pfrag[2*s+1][0], a3 = pfrag[2*s+1][1];
            #pragma unroll
            for (int q=0;q<4;q++){
                unsigned b0,b1,b2,b3;
                ldsm4t(b0,b1,b2,b3, vsB + s*2304 + q*32);
                mma_f16(acc_pv[2*q  ], a0,a1,a2,a3, b0,b1);
                mma_f16(acc_pv[2*q+1], a0,a1,a2,a3, b2,b3);
            }
        }
    }

    // epilogue: row sums, normalize, write av
    rs_0 += __shfl_xor_sync(0xffffffffu, rs_0, 1);
    rs_0 += __shfl_xor_sync(0xffffffffu, rs_0, 2);
    rs_1 += __shfl_xor_sync(0xffffffffu, rs_1, 1);
    rs_1 += __shfl_xor_sync(0xffffffffu, rs_1, 2);
    const int row0 = i0 + wm + gq, row1 = row0 + 8;
    if (tq == 0){
        g_rs[gg*LQ + row0] = rs_0;
        g_rs[gg*LQ + row1] = rs_1;
    }
    const float inv0 = 1.f / rs_0, inv1 = 1.f / rs_1;
    const int b = gg >> 4;
    __half* dst0 = g_av + (size_t)(row0*BATCH + b)*DMODEL + (h<<6);
    __half* dst1 = g_av + (size_t)(row1*BATCH + b)*DMODEL + (h<<6);
    #pragma unroll
    for (int ni=0;ni<8;ni++){
        const int d = ni*8 + 2*tq;
        *reinterpret_cast<unsigned*>(dst0 + d) = pack_h2(acc_pv[ni][0]*inv0, acc_pv[ni][1]*inv0);
        *reinterpret_cast<unsigned*>(dst1 + d) = pack_h2(acc_pv[ni][2]*inv1, acc_pv[ni][3]*inv1);
    }
}

// ---------------- attn_matrix = mean over (b,h) of p/rs --------------------------
__global__ __launch_bounds__(256) void attnmat_kernel(float* __restrict__ out)
{
    const int i  = blockIdx.y;
    const int j0 = blockIdx.x << 9;            // 4 tiles of 512
    const int jmax = i + MEMLEN;
    const int tid = threadIdx.x;
    const int jq = tid & 63;
    const int gsel = tid >> 6;
    const int j = j0 + jq*8;
    __shared__ float red[256][9];

    float a[8] = {0.f,0.f,0.f,0.f,0.f,0.f,0.f,0.f};
    if (j0 <= jmax){
        #pragma unroll
        for (int gi=0; gi<8; gi++){
            int g = gsel*8 + gi;
            float inv = 1.f / g_rs[g*LQ + i];
            uint4 raw = *(const uint4*)(g_p + ((size_t)g*LQ + i)*TT + j);
            const __half2* hp = (const __half2*)&raw;
            #pragma unroll
            for (int e=0;e<4;e++){
                float2 f = __half22float2(hp[e]);
                a[2*e]   += f.x * inv;
                a[2*e+1] += f.y * inv;
            }
        }
        #pragma unroll
        for (int e=0;e<8;e++) if (j+e > jmax) a[e] = 0.f;
    }
    #pragma unroll
    for (int e=0;e<8;e++) red[tid][e] = a[e];
    __syncthreads();
    if (tid < 64){
        const float k = 1.f/NG;
        float o[8];
        #pragma unroll
        for (int e=0;e<8;e++)
            o[e] = (red[tid][e] + red[tid+64][e] + red[tid+128][e] + red[tid+192][e]) * k;
        float* dst = out + (size_t)i*TT + j0 + tid*8;
        *(float4*)dst     = make_float4(o[0],o[1],o[2],o[3]);
        *(float4*)(dst+4) = make_float4(o[4],o[5],o[6],o[7]);
    }
}

// ---------------- Wo GEMM + residual (fp16 MMA): g_h = x + g_av @ Wo ------------
__global__ __launch_bounds__(256) void wo_mma(const float* __restrict__ x)
{
    const int m0 = blockIdx.y << 7;
    const int n0 = blockIdx.x << 6;

    __shared__ __half   As[128*40];
    __shared__ unsigned Bs[16*72];

    const int tid = threadIdx.x;
    const int warp = tid >> 5, lane = tid & 31;
    const int gq = lane >> 2, tq = lane & 3;
    const int wm = (warp >> 1) * 32, wn = (warp & 1) * 32;
    const unsigned* As2 = (const unsigned*)As;

    float acc[2][4][4];
    #pragma unroll
    for (int mi=0;mi<2;mi++)
        #pragma unroll
        for (int ni=0;ni<4;ni++)
            #pragma unroll
            for (int c=0;c<4;c++) acc[mi][ni][c]=0.f;

    const int a_r = tid >> 1;
    const int a_cb = (tid & 1) * 16;
    const __half* arow = g_av + (size_t)(m0 + a_r)*DMODEL + a_cb;
    const int b_k2 = tid >> 4;
    const int b_cb = (tid & 15) * 4;

    for (int k0=0;k0<DMODEL;k0+=32){
        {
            __half* Ad = As + a_r*40 + a_cb;
            *(uint4*)Ad     = *(const uint4*)(arow + k0);
            *(uint4*)(Ad+8) = *(const uint4*)(arow + k0 + 8);
            const unsigned* bsrc = g_woi + (size_t)((k0>>1) + b_k2)*DMODEL + n0 + b_cb;
            *(uint4*)&Bs[b_k2*72 + b_cb] = *(const uint4*)bsrc;
        }
        __syncthreads();
        #pragma unroll
        for (int kk=0;kk<32;kk+=16){
            const int k2 = kk >> 1;
            unsigned a[2][4], bfr[4][2];
            #pragma unroll
            for (int mi=0;mi<2;mi++){
                int m = wm + mi*16;
                a[mi][0] = As2[(m+gq  )*20 + k2 + tq  ];
                a[mi][1] = As2[(m+gq+8)*20 + k2 + tq  ];
                a[mi][2] = As2[(m+gq  )*20 + k2 + tq+4];
                a[mi][3] = As2[(m+gq+8)*20 + k2 + tq+4];
            }
            #pragma unroll
            for (int ni=0;ni<4;ni++){
                int n = wn + ni*8 + gq;
                bfr[ni][0] = Bs[(k2+tq  )*72 + n];
                bfr[ni][1] = Bs[(k2+tq+4)*72 + n];
            }
            #pragma unroll
            for (int mi=0;mi<2;mi++)
                #pragma unroll
                for (int ni=0;ni<4;ni++)
                    mma_f16(acc[mi][ni], a[mi][0],a[mi][1],a[mi][2],a[mi][3], bfr[ni][0],bfr[ni][1]);
        }
        __syncthreads();
    }

    #pragma unroll
    for (int mi=0;mi<2;mi++)
        #pragma unroll
        for (int rr=0;rr<2;rr++){
            const int row = m0 + wm + mi*16 + gq + rr*8;
            #pragma unroll
            for (int ni=0;ni<4;ni++){
                const int col = n0 + wn + ni*8 + 2*tq;
                float2 xv = *(const float2*)&x[(size_t)row*DMODEL + col];
                float2 val = { acc[mi][ni][rr*2+0] + xv.x,
                               acc[mi][ni][rr*2+1] + xv.y };
                *(float2*)&g_h[(size_t)row*DMODEL + col] = val;
            }
        }
}

// ---------------- layernorm ------------------------------------------------------
__global__ __launch_bounds__(256) void ln_kernel(const float* __restrict__ gamma,
                                                 const float* __restrict__ beta,
                                                 float* __restrict__ out)
{
    const int row = blockIdx.x;
    const float* hr = g_h + (size_t)row*DMODEL;
    const int c = threadIdx.x * 4;
    float4 v = *(const float4*)(hr + c);
    float s = v.x+v.y+v.z+v.w;
    s = blockSum(s);
    const float mu = s * (1.f/DMODEL);
    float dx = v.x-mu, dy = v.y-mu, dz = v.z-mu, dw = v.w-mu;
    float sq = dx*dx+dy*dy+dz*dz+dw*dw;
    sq = blockSum(sq);
    const float inv = rsqrtf(sq*(1.f/DMODEL) + 1e-5f);
    float4 gm = *(const float4*)(gamma + c);
    float4 bt = *(const float4*)(beta + c);
    float4 o;
    o.x = dx*inv*gm.x + bt.x;
    o.y = dy*inv*gm.y + bt.y;
    o.z = dz*inv*gm.z + bt.z;
    o.w = dw*inv*gm.w + bt.w;
    *(float4*)(out + (size_t)row*DMODEL + c) = o;
}

// ---------------- launch ----------------------------------------------------------
extern "C" void kernel_launch(void* const* d_in, const int* in_sizes, int n_in,
                              void* d_out, int out_size)
{
    const float* x        = (const float*)d_in[0];
    const float* pos_emb  = (const float*)d_in[1];
    const float* memory   = (const float*)d_in[2];
    const float* ubias    = (const float*)d_in[3];
    const float* vbias    = (const float*)d_in[4];
    const float* Wq       = (const float*)d_in[6];
    const float* Wkv      = (const float*)d_in[7];
    const float* Wrel     = (const float*)d_in[8];
    const float* Wo       = (const float*)d_in[9];
    const float* gamma    = (const float*)d_in[10];
    const float* beta     = (const float*)d_in[11];
    float* out    = (float*)d_out;
    float* out_am = out + (size_t)LQ*BATCH*DMODEL;

    cudaFuncSetAttribute(flash_mma, cudaFuncAttributeMaxDynamicSharedMemorySize, FL_SMEM_BYTES);

    cvt_all<<<6656, 256>>>(x, memory, pos_emb, Wq, Wkv, Wrel, Wo);
    qkvr_mma<<<896, 256>>>();
    flash_mma<<<dim3(8, NG), 256, FL_SMEM_BYTES>>>(ubias, vbias);
    attnmat_kernel<<<dim3(4, LQ), 256>>>(out_am);
    wo_mma<<<dim3(16,16), 256>>>(x);
    ln_kernel<<<LQ*BATCH, 256>>>(gamma, beta, out);
}

// round 12
// speedup vs baseline: 5.1773x; 1.0165x over previous
#include <cuda_runtime.h>
#include <cuda_fp16.h>
#include <math.h>
#include <stdint.h>

#define LQ      1024
#define BATCH   2
#define DMODEL  1024
#define NH      16
#define DHD     64
#define MEMLEN  1024
#define TT      2048
#define NG      (BATCH*NH)
#define SCALE_F 0.125f
#define EXPC    8.0f
#define SROW    72          // halves per staged row
#define SROWB   144         // bytes per staged row
#define BDS     132         // floats per BD strip row

// ---------------- scratch -------------------------------------------------------
__device__ __half g_q [NG*LQ*DHD];
__device__ __half g_k [NG*TT*DHD];
__device__ __half g_v [NG*TT*DHD];
__device__ __half g_r [NG*TT*DHD];
__device__ __half g_p [(size_t)NG*LQ*TT];            // unnormalized e^(s-8) (fp16)
__device__ float  g_rs[NG*LQ];                       // row sums of e^(s-8)
__device__ __half g_av[LQ*BATCH*NH*DHD];
__device__ float  g_h [LQ*BATCH*DMODEL];
// fp16 pre-converted inputs / weights
__device__ __half   g_xh   [LQ*BATCH*DMODEL];
__device__ __half   g_memh [MEMLEN*BATCH*DMODEL];
__device__ __half   g_posh [TT*BATCH*DMODEL];
__device__ __half   g_wqt  [1024*1024];              // W^T [n][k] fp16
__device__ __half   g_wkvt [2048*1024];
__device__ __half   g_wrelt[1024*1024];
__device__ unsigned g_woi  [512*1024];               // (W[2k],W[2k+1]) half2 pairs (wo)

// ---------------- helpers ---------------------------------------------------------
__device__ __forceinline__ unsigned pack_h2(float a, float b){
    __half2 h = __floats2half2_rn(a, b);
    return *reinterpret_cast<unsigned*>(&h);
}
__device__ __forceinline__ void mma_f16(float c[4],
                                        unsigned a0, unsigned a1, unsigned a2, unsigned a3,
                                        unsigned b0, unsigned b1){
    asm volatile("mma.sync.aligned.m16n8k16.row.col.f32.f16.f16.f32 "
        "{%0,%1,%2,%3}, {%4,%5,%6,%7}, {%8,%9}, {%0,%1,%2,%3};"
        : "+f"(c[0]), "+f"(c[1]), "+f"(c[2]), "+f"(c[3])
        : "r"(a0), "r"(a1), "r"(a2), "r"(a3), "r"(b0), "r"(b1));
}
__device__ __forceinline__ unsigned smem_u32(const void* p){
    return (unsigned)__cvta_generic_to_shared(p);
}
__device__ __forceinline__ void ldsm4(unsigned &r0, unsigned &r1, unsigned &r2, unsigned &r3, unsigned a){
    asm volatile("ldmatrix.sync.aligned.m8n8.x4.shared.b16 {%0,%1,%2,%3}, [%4];"
        : "=r"(r0),"=r"(r1),"=r"(r2),"=r"(r3) : "r"(a));
}
__device__ __forceinline__ void ldsm4t(unsigned &r0, unsigned &r1, unsigned &r2, unsigned &r3, unsigned a){
    asm volatile("ldmatrix.sync.aligned.m8n8.x4.trans.shared.b16 {%0,%1,%2,%3}, [%4];"
        : "=r"(r0),"=r"(r1),"=r"(r2),"=r"(r3) : "r"(a));
}

__device__ __forceinline__ float blockSum(float v){
    __shared__ float sm[32];
    int lane = threadIdx.x & 31, w = threadIdx.x >> 5;
    #pragma unroll
    for (int o=16;o>0;o>>=1) v += __shfl_xor_sync(0xffffffffu, v, o);
    if (lane==0) sm[w] = v;
    __syncthreads();
    float r = (threadIdx.x < 8) ? sm[threadIdx.x] : 0.f;
    if (w==0){
        #pragma unroll
        for (int o=4;o>0;o>>=1) r += __shfl_xor_sync(0xffffffffu, r, o);
        if (lane==0) sm[0]=r;
    }
    __syncthreads();
    r = sm[0];
    __syncthreads();
    return r;
}

// ---------------- fp16 pre-conversion -------------------------------------------
__device__ __forceinline__ void cvt_plain(const float* __restrict__ s, __half* d, int b, int t){
    const int idx = b*2048 + t*8;
    float4 v0 = *(const float4*)(s+idx), v1 = *(const float4*)(s+idx+4);
    unsigned u[4] = { pack_h2(v0.x,v0.y), pack_h2(v0.z,v0.w),
                      pack_h2(v1.x,v1.y), pack_h2(v1.z,v1.w) };
    *(uint4*)&d[idx] = *(uint4*)u;
}
__device__ __forceinline__ void cvt_inter(const float* __restrict__ W, unsigned* d,
                                          int b, int t, int lgN){
    const int p = b*1024 + t*4;
    const int N = 1 << lgN;
    const int k2 = p >> lgN, n = p & (N-1);
    const float* r0 = W + ((size_t)k2*2)*N + n;
    float4 a = *(const float4*)r0;
    float4 c = *(const float4*)(r0 + N);
    unsigned u[4] = { pack_h2(a.x,c.x), pack_h2(a.y,c.y),
                      pack_h2(a.z,c.z), pack_h2(a.w,c.w) };
    *(uint4*)&d[p] = *(uint4*)u;
}
// transpose 64x64 tile of W[1024][N] fp32 -> Wt[N][1024] fp16
__device__ void cvt_wt_tile(const float* __restrict__ W, __half* Wt, int N,
                            int ky, int nx, int tid){
    __shared__ float buf[64][65];
    const int k0 = ky*64, n0c = nx*64;
    const int kr = tid>>2, nc = (tid&3)*16;
    #pragma unroll
    for (int q=0;q<4;q++){
        float4 w = *(const float4*)(W + (size_t)(k0+kr)*N + n0c + nc + q*4);
        buf[kr][nc+q*4+0]=w.x; buf[kr][nc+q*4+1]=w.y;
        buf[kr][nc+q*4+2]=w.z; buf[kr][nc+q*4+3]=w.w;
    }
    __syncthreads();
    const int nr = tid>>2, kc = (tid&3)*16;
    unsigned u[8];
    #pragma unroll
    for (int e=0;e<8;e++)
        u[e] = pack_h2(buf[kc+2*e][nr], buf[kc+2*e+1][nr]);
    __half* dst = Wt + (size_t)(n0c+nr)*1024 + k0 + kc;
    *(uint4*)dst     = *(uint4*)&u[0];
    *(uint4*)(dst+8) = *(uint4*)&u[4];
}
__global__ __launch_bounds__(256) void cvt_all(const float* __restrict__ x,
                                               const float* __restrict__ memory,
                                               const float* __restrict__ pos_emb,
                                               const float* __restrict__ Wq,
                                               const float* __restrict__ Wkv,
                                               const float* __restrict__ Wrel,
                                               const float* __restrict__ Wo)
{
    const int bid = blockIdx.x, tid = threadIdx.x;
    if      (bid < 1024) cvt_plain(x,       g_xh,   bid,        tid);
    else if (bid < 2048) cvt_plain(memory,  g_memh, bid-1024,   tid);
    else if (bid < 4096) cvt_plain(pos_emb, g_posh, bid-2048,   tid);
    else if (bid < 4608) cvt_inter(Wo, g_woi, bid-4096, tid, 10);
    else {
        int t = bid - 4608;
        if (t < 256)      cvt_wt_tile(Wq,   g_wqt,   1024, t>>4,        t&15,        tid);
        else if (t < 768) cvt_wt_tile(Wkv,  g_wkvt,  2048, (t-256)>>5,  (t-256)&31,  tid);
        else              cvt_wt_tile(Wrel, g_wrelt, 1024, (t-768)>>4,  (t-768)&15,  tid);
    }
}

// ---------------- QKVR projection GEMM (fp16 MMA, all-ldmatrix, K-major B) -------
// C[m][n] = A[m][k] . Wt[n][k] ; tile 128x128, 16 K-chunks of 64, warp = 16 rows.
__device__ __forceinline__ void qkvr_store(int mode, int row, int col, unsigned hv){
    const int t = row >> 1, bb = row & 1;
    if (mode==0){
        int h = col >> 6, d = col & 63;
        *reinterpret_cast<unsigned*>(&g_q[(((size_t)(bb*NH+h)*LQ + t)<<6) + d]) = hv;
    } else if (mode==1){
        int c2 = col; __half* dst = g_k;
        if (c2 >= NH*DHD){ dst = g_v; c2 -= NH*DHD; }
        int h = c2 >> 6, d = c2 & 63;
        *reinterpret_cast<unsigned*>(&dst[(((size_t)(bb*NH+h)*TT + t)<<6) + d]) = hv;
    } else {
        int h = col >> 6, d = col & 63;
        *reinterpret_cast<unsigned*>(&g_r[(((size_t)(bb*NH+h)*TT + t)<<6) + d]) = hv;
    }
}

__global__ __launch_bounds__(256) void qkvr_mma()
{
    __shared__ __half As[128*SROW];
    __shared__ __half Bs[128*SROW];

    int bid = blockIdx.x;
    int mode, m0, n0;
    const __half* Wt;
    if (bid < 128)      { mode=0; m0=(bid>>3)<<7;  n0=(bid&7)<<7;  Wt=g_wqt;  }
    else if (bid < 640) { int t=bid-128; mode=1; m0=(t>>4)<<7; n0=(t&15)<<7; Wt=g_wkvt; }
    else                { int t=bid-640; mode=2; m0=(t>>3)<<7; n0=(t&7)<<7;  Wt=g_wrelt;}

    const int tid = threadIdx.x;
    const int warp = tid >> 5, lane = tid & 31;
    const int gq = lane >> 2, tq = lane & 3;
    const int sel = lane >> 3, l7 = lane & 7;
    const int wm = warp << 4;

    const unsigned offA = (((sel&1)*8 + l7)*SROW + (sel>>1)*8)*2;
    const unsigned offB = (((sel>>1)*8 + l7)*SROW + (sel&1)*8)*2;
    const unsigned asA = smem_u32(As) + wm*SROWB + offA;
    const unsigned bsB = smem_u32(Bs) + offB;

    const int sr = tid >> 1, cb = (tid & 1) * 32;
    const __half* arow;
    {
        int grow = m0 + sr;
        if (mode==0)      arow = g_xh + (size_t)grow*DMODEL;
        else if (mode==1) arow = (grow < MEMLEN*BATCH) ? g_memh + (size_t)grow*DMODEL
                                                       : g_xh + (size_t)(grow - MEMLEN*BATCH)*DMODEL;
        else              arow = g_posh + (size_t)grow*DMODEL;
    }
    const __half* brow = Wt + (size_t)(n0 + sr)*DMODEL;

    float acc[16][4];
    #pragma unroll
    for (int ni=0;ni<16;ni++)
        #pragma unroll
        for (int c=0;c<4;c++) acc[ni][c]=0.f;

    for (int c=0;c<16;c++){
        __syncthreads();
        #pragma unroll
        for (int q=0;q<4;q++){
            *(uint4*)&As[sr*SROW + cb + q*8] = *(const uint4*)(arow + c*64 + cb + q*8);
            *(uint4*)&Bs[sr*SROW + cb + q*8] = *(const uint4*)(brow + c*64 + cb + q*8);
        }
        __syncthreads();
        #pragma unroll
        for (int kk=0;kk<64;kk+=16){
            unsigned a0,a1,a2,a3;
            ldsm4(a0,a1,a2,a3, asA + kk*2);
            #pragma unroll
            for (int q=0;q<8;q++){
                unsigned b0,b1,b2,b3;
                ldsm4(b0,b1,b2,b3, bsB + q*2304 + kk*2);
                mma_f16(acc[2*q  ], a0,a1,a2,a3, b0,b1);
                mma_f16(acc[2*q+1], a0,a1,a2,a3, b2,b3);
            }
        }
    }

    const int row0 = m0 + wm + gq, row1 = row0 + 8;
    #pragma unroll
    for (int ni=0;ni<16;ni++){
        const int col = n0 + ni*8 + 2*tq;
        qkvr_store(mode, row0, col, pack_h2(acc[ni][0], acc[ni][1]));
        qkvr_store(mode, row1, col, pack_h2(acc[ni][2], acc[ni][3]));
    }
}

// ---------------- BD strip: BDslot[128][132] = Q . Rs^T + vR (folded) ------------
__device__ __forceinline__ void compute_strip(unsigned qs_u32, unsigned rs_u32,
                                              float* BDslot, const float* vRslot,
                                              int warp, int lane)
{
    const int sel = lane >> 3, l7 = lane & 7;
    const int gq = lane >> 2, tq = lane & 3;
    const int wmb = (warp >> 1) * 32, wnb = (warp & 1) * 64;
    const unsigned offA = (((sel&1)*8 + l7)*SROW + (sel>>1)*8)*2;
    const unsigned offB = (((sel>>1)*8 + l7)*SROW + (sel&1)*8)*2;

    float abd[2][2][4][4];
    #pragma unroll
    for (int pass=0; pass<2; pass++){
        #pragma unroll
        for (int mi=0;mi<2;mi++)
            #pragma unroll
            for (int ni=0;ni<4;ni++)
                #pragma unroll
                for (int e=0;e<4;e++) abd[pass][mi][ni][e]=0.f;
        #pragma unroll
        for (int kk=0;kk<64;kk+=16){
            unsigned am[2][4];
            #pragma unroll
            for (int mi=0;mi<2;mi++)
                ldsm4(am[mi][0],am[mi][1],am[mi][2],am[mi][3],
                      qs_u32 + (wmb + mi*16)*SROWB + offA + kk*2);
            #pragma unroll
            for (int q=0;q<2;q++){
                unsigned b0,b1,b2,b3;
                ldsm4(b0,b1,b2,b3,
                      rs_u32 + (wnb + pass*32 + 16*q)*SROWB + offB + kk*2);
                mma_f16(abd[pass][0][2*q  ], am[0][0],am[0][1],am[0][2],am[0][3], b0,b1);
                mma_f16(abd[pass][0][2*q+1], am[0][0],am[0][1],am[0][2],am[0][3], b2,b3);
                mma_f16(abd[pass][1][2*q  ], am[1][0],am[1][1],am[1][2],am[1][3], b0,b1);
                mma_f16(abd[pass][1][2*q+1], am[1][0],am[1][1],am[1][2],am[1][3], b2,b3);
            }
        }
    }
    __syncthreads();   // vRslot writes (pre-call, program order) visible to all
    #pragma unroll
    for (int pass=0; pass<2; pass++)
        #pragma unroll
        for (int mi=0;mi<2;mi++)
            #pragma unroll
            for (int rr=0;rr<2;rr++){
                const int il = wmb + mi*16 + gq + rr*8;
                #pragma unroll
                for (int ni=0;ni<4;ni++){
                    const int pl = wnb + pass*32 + ni*8 + 2*tq;
                    float2 v = { abd[pass][mi][ni][rr*2+0] + vRslot[pl],
                                 abd[pass][mi][ni][rr*2+1] + vRslot[pl+1] };
                    *(float2*)&BDslot[il*BDS + pl] = v;
                }
            }
}

// ---------------- flash: scores (AC + strip-shared BD) + exp + PV ----------------
#define FL_SMEM_BYTES 210944
__global__ __launch_bounds__(256) void flash_mma(const float* __restrict__ ubias,
                                                 const float* __restrict__ vbias)
{
    const int gg = blockIdx.y, h = gg & (NH-1);
    const int bi = 7 - blockIdx.x;            // heavy CTAs first
    const int i0 = bi << 7;

    extern __shared__ char smr[];
    __half* Qs = (__half*)smr;                 // [128][72]
    __half* Ks = (__half*)(smr + 18432);       // [128][72]
    __half* Rs = (__half*)(smr + 36864);       // [128][72]
    __half* Vs = (__half*)(smr + 55296);       // [128 t][72 d]
    float*  BD0 = (float*)(smr + 73728);       // [128][132]
    float*  BD1 = (float*)(smr + 141312);
    float*  uKs = (float*)(smr + 208896);      // [128]
    float*  vR0 = (float*)(smr + 209408);      // [128]
    float*  vR1 = (float*)(smr + 209920);
    float*  u_s = (float*)(smr + 210432);      // [64]
    float*  v_s = (float*)(smr + 210688);

    const int tid = threadIdx.x;
    const int warp = tid >> 5, lane = tid & 31;
    const int gq = lane >> 2, tq = lane & 3;
    const int sel = lane >> 3, l7 = lane & 7;
    const int wm = warp << 4;                  // 16 AC rows per warp

    const unsigned qs_u32 = smem_u32(Qs);
    const unsigned ks_u32 = smem_u32(Ks);
    const unsigned rs_u32 = smem_u32(Rs);
    const unsigned vs_u32 = smem_u32(Vs);
    const unsigned offA = (((sel&1)*8 + l7)*SROW + (sel>>1)*8)*2;
    const unsigned offB = (((sel>>1)*8 + l7)*SROW + (sel&1)*8)*2;
    const unsigned qsA = qs_u32 + wm*SROWB + offA;
    const unsigned ksB = ks_u32 + offB;
    const unsigned vsB = vs_u32 + offA;

    const int sr = tid >> 1, cb = (tid & 1) * 32;

    // ---- prologue: stage Q, biases, strip 0 ----
    {
        const __half* qrow = g_q + (((size_t)gg*LQ + i0 + sr) << 6) + cb;
        #pragma unroll
        for (int q=0;q<4;q++)
            *(uint4*)&Qs[sr*SROW + cb + q*8] = *(const uint4*)(qrow + q*8);
        if (tid < 64)       u_s[tid]    = ubias[(h<<6) + tid];
        else if (tid < 128) v_s[tid-64] = vbias[(h<<6) + tid - 64];
        const int ps0 = (7 - bi) << 7;
        const __half* rrow = g_r + (((size_t)gg*TT + ps0 + sr) << 6) + cb;
        #pragma unroll
        for (int q=0;q<4;q++)
            *(uint4*)&Rs[sr*SROW + cb + q*8] = *(const uint4*)(rrow + q*8);
    }
    __syncthreads();
    if (tid >= 128){
        const int c = tid - 128;
        float s = 0.f;
        #pragma unroll
        for (int d=0;d<64;d++) s += v_s[d] * __half2float(Rs[c*SROW + d]);
        vR0[c] = s;
    }
    compute_strip(qs_u32, rs_u32, BD0, vR0, warp, lane);

    float acc_pv[8][4];
    #pragma unroll
    for (int ni=0;ni<8;ni++)
        #pragma unroll
        for (int c=0;c<4;c++) acc_pv[ni][c]=0.f;
    float rs_0 = 0.f, rs_1 = 0.f;

    const int jt_max = bi + 8;
    for (int jt=0; jt<=jt_max; jt++){
        const int j0 = jt << 7;
        const bool doStrip = (jt < jt_max);
        __syncthreads();                       // S1
        // stage K, V (and R for strip jt+1)
        {
            const __half* krow = g_k + (((size_t)gg*TT + j0 + sr) << 6) + cb;
            const __half* vrow = g_v + (((size_t)gg*TT + j0 + sr) << 6) + cb;
            #pragma unroll
            for (int q=0;q<4;q++){
                *(uint4*)&Ks[sr*SROW + cb + q*8] = *(const uint4*)(krow + q*8);
                *(uint4*)&Vs[sr*SROW + cb + q*8] = *(const uint4*)(vrow + q*8);
            }
            if (doStrip){
                const int ps = (jt + 1 - bi + 7) << 7;
                const __half* rrow = g_r + (((size_t)gg*TT + ps + sr) << 6) + cb;
                #pragma unroll
                for (int q=0;q<4;q++)
                    *(uint4*)&Rs[sr*SROW + cb + q*8] = *(const uint4*)(rrow + q*8);
            }
        }
        __syncthreads();                       // S2
        if (tid < 128){
            float s = 0.f;
            #pragma unroll
            for (int d=0;d<64;d++) s += u_s[d] * __half2float(Ks[tid*SROW + d]);
            uKs[tid] = s;
        } else if (doStrip){
            const int c = tid - 128;
            float s = 0.f;
            #pragma unroll
            for (int d=0;d<64;d++) s += v_s[d] * __half2float(Rs[c*SROW + d]);
            (((jt+1)&1) ? vR1 : vR0)[c] = s;
        }
        // AC = Q.K^T (warp tile 16x128) via ldmatrix
        float acc[16][4];
        #pragma unroll
        for (int ni=0;ni<16;ni++)
            #pragma unroll
            for (int c=0;c<4;c++) acc[ni][c]=0.f;
        #pragma unroll
        for (int kk=0;kk<64;kk+=16){
            unsigned a0,a1,a2,a3;
            ldsm4(a0,a1,a2,a3, qsA + kk*2);
            #pragma unroll
            for (int q=0;q<8;q++){
                unsigned b0,b1,b2,b3;
                ldsm4(b0,b1,b2,b3, ksB + q*2304 + kk*2);
                mma_f16(acc[2*q  ], a0,a1,a2,a3, b0,b1);
                mma_f16(acc[2*q+1], a0,a1,a2,a3, b2,b3);
            }
        }
        if (doStrip)
            compute_strip(qs_u32, rs_u32, ((jt+1)&1) ? BD1 : BD0,
                          ((jt+1)&1) ? vR1 : vR0, warp, lane);
        __syncthreads();                       // S3
        // gather + exp + mask + write p + row sums
        const bool isDiag = (jt == jt_max);
        const float* BDa = (jt & 1) ? BD1 : BD0;
        const float* BDb = (jt & 1) ? BD0 : BD1;
        const int il0 = wm + gq, il1 = il0 + 8;
        unsigned pfrag[16][2];
        __half* prow0 = g_p + ((size_t)gg*LQ + i0 + il0)*TT + j0;
        __half* prow1 = g_p + ((size_t)gg*LQ + i0 + il1)*TT + j0;
        #pragma unroll
        for (int ni=0;ni<16;ni++){
            const int jl = ni*8 + 2*tq;
            const int o00 = jl - il0 + 127;
            const int o10 = jl - il1 + 127;
            float bd00 = (o00   < 128) ? BDa[il0*BDS + o00    ] : BDb[il0*BDS + o00-128];
            float bd01 = (o00+1 < 128) ? BDa[il0*BDS + o00 + 1] : BDb[il0*BDS + o00-127];
            float bd10 = (o10   < 128) ? BDa[il1*BDS + o10    ] : BDb[il1*BDS + o10-128];
            float bd11 = (o10+1 < 128) ? BDa[il1*BDS + o10 + 1] : BDb[il1*BDS + o10-127];
            const float u0 = uKs[jl], u1 = uKs[jl+1];
            float p0 = __expf((acc[ni][0] + bd00 + u0)*SCALE_F - EXPC);
            float p1 = __expf((acc[ni][1] + bd01 + u1)*SCALE_F - EXPC);
            float p2 = __expf((acc[ni][2] + bd10 + u0)*SCALE_F - EXPC);
            float p3 = __expf((acc[ni][3] + bd11 + u1)*SCALE_F - EXPC);
            if (isDiag){
                if (jl   > il0) p0 = 0.f;
                if (jl+1 > il0) p1 = 0.f;
                if (jl   > il1) p2 = 0.f;
                if (jl+1 > il1) p3 = 0.f;
            }
            rs_0 += p0 + p1;
            rs_1 += p2 + p3;
            unsigned lo = pack_h2(p0, p1), hi = pack_h2(p2, p3);
            *reinterpret_cast<unsigned*>(prow0 + jl) = lo;
            *reinterpret_cast<unsigned*>(prow1 + jl) = hi;
            pfrag[ni][0] = lo;
            pfrag[ni][1] = hi;
        }
        // PV: acc_pv += P(tile) @ V(tile), V frags via ldmatrix.trans
        #pragma unroll
        for (int s=0;s<8;s++){
            unsigned a0 = pfrag[2*s][0], a1 = pfrag[2*s][1];
            unsigned a2 = pfrag[2*s+1][0], a3 = pfrag[2*s+1][1];
            #pragma unroll
            for (int q=0;q<4;q++){
                unsigned b0,b1,b2,b3;
                ldsm4t(b0,b1,b2,b3, vsB + s*2304 + q*32);
                mma_f16(acc_pv[2*q  ], a0,a1,a2,a3, b0,b1);
                mma_f16(acc_pv[2*q+1], a0,a1,a2,a3, b2,b3);
            }
        }
    }

    // epilogue: row sums, normalize, write av
    rs_0 += __shfl_xor_sync(0xffffffffu, rs_0, 1);
    rs_0 += __shfl_xor_sync(0xffffffffu, rs_0, 2);
    rs_1 += __shfl_xor_sync(0xffffffffu, rs_1, 1);
    rs_1 += __shfl_xor_sync(0xffffffffu, rs_1, 2);
    const int row0 = i0 + wm + gq, row1 = row0 + 8;
    if (tq == 0){
        g_rs[gg*LQ + row0] = rs_0;
        g_rs[gg*LQ + row1] = rs_1;
    }
    const float inv0 = 1.f / rs_0, inv1 = 1.f / rs_1;
    const int b = gg >> 4;
    __half* dst0 = g_av + (size_t)(row0*BATCH + b)*DMODEL + (h<<6);
    __half* dst1 = g_av + (size_t)(row1*BATCH + b)*DMODEL + (h<<6);
    #pragma unroll
    for (int ni=0;ni<8;ni++){
        const int d = ni*8 + 2*tq;
        *reinterpret_cast<unsigned*>(dst0 + d) = pack_h2(acc_pv[ni][0]*inv0, acc_pv[ni][1]*inv0);
        *reinterpret_cast<unsigned*>(dst1 + d) = pack_h2(acc_pv[ni][2]*inv1, acc_pv[ni][3]*inv1);
    }
}

// ---------------- attn_matrix = mean over (b,h) of p/rs --------------------------
__global__ __launch_bounds__(256) void attnmat_kernel(float* __restrict__ out)
{
    const int i  = blockIdx.y;
    const int j0 = blockIdx.x << 9;            // 4 tiles of 512
    const int jmax = i + MEMLEN;
    const int tid = threadIdx.x;
    const int jq = tid & 63;
    const int gsel = tid >> 6;
    const int j = j0 + jq*8;
    __shared__ float red[256][9];

    float a[8] = {0.f,0.f,0.f,0.f,0.f,0.f,0.f,0.f};
    if (j0 <= jmax){
        #pragma unroll
        for (int gi=0; gi<8; gi++){
            int g = gsel*8 + gi;
            float inv = 1.f / g_rs[g*LQ + i];
            uint4 raw = *(const uint4*)(g_p + ((size_t)g*LQ + i)*TT + j);
            const __half2* hp = (const __half2*)&raw;
            #pragma unroll
            for (int e=0;e<4;e++){
                float2 f = __half22float2(hp[e]);
                a[2*e]   += f.x * inv;
                a[2*e+1] += f.y * inv;
            }
        }
        #pragma unroll
        for (int e=0;e<8;e++) if (j+e > jmax) a[e] = 0.f;
    }
    #pragma unroll
    for (int e=0;e<8;e++) red[tid][e] = a[e];
    __syncthreads();
    if (tid < 64){
        const float k = 1.f/NG;
        float o[8];
        #pragma unroll
        for (int e=0;e<8;e++)
            o[e] = (red[tid][e] + red[tid+64][e] + red[tid+128][e] + red[tid+192][e]) * k;
        float* dst = out + (size_t)i*TT + j0 + tid*8;
        *(float4*)dst     = make_float4(o[0],o[1],o[2],o[3]);
        *(float4*)(dst+4) = make_float4(o[4],o[5],o[6],o[7]);
    }
}

// ---------------- Wo GEMM + residual (fp16 MMA): g_h = x + g_av @ Wo ------------
__global__ __launch_bounds__(256) void wo_mma(const float* __restrict__ x)
{
    const int m0 = blockIdx.y << 7;
    const int n0 = blockIdx.x << 6;

    __shared__ __half   As[128*40];
    __shared__ unsigned Bs[16*72];

    const int tid = threadIdx.x;
    const int warp = tid >> 5, lane = tid & 31;
    const int gq = lane >> 2, tq = lane & 3;
    const int wm = (warp >> 1) * 32, wn = (warp & 1) * 32;
    const unsigned* As2 = (const unsigned*)As;

    float acc[2][4][4];
    #pragma unroll
    for (int mi=0;mi<2;mi++)
        #pragma unroll
        for (int ni=0;ni<4;ni++)
            #pragma unroll
            for (int c=0;c<4;c++) acc[mi][ni][c]=0.f;

    const int a_r = tid >> 1;
    const int a_cb = (tid & 1) * 16;
    const __half* arow = g_av + (size_t)(m0 + a_r)*DMODEL + a_cb;
    const int b_k2 = tid >> 4;
    const int b_cb = (tid & 15) * 4;

    for (int k0=0;k0<DMODEL;k0+=32){
        {
            __half* Ad = As + a_r*40 + a_cb;
            *(uint4*)Ad     = *(const uint4*)(arow + k0);
            *(uint4*)(Ad+8) = *(const uint4*)(arow + k0 + 8);
            const unsigned* bsrc = g_woi + (size_t)((k0>>1) + b_k2)*DMODEL + n0 + b_cb;
            *(uint4*)&Bs[b_k2*72 + b_cb] = *(const uint4*)bsrc;
        }
        __syncthreads();
        #pragma unroll
        for (int kk=0;kk<32;kk+=16){
            const int k2 = kk >> 1;
            unsigned a[2][4], bfr[4][2];
            #pragma unroll
            for (int mi=0;mi<2;mi++){
                int m = wm + mi*16;
                a[mi][0] = As2[(m+gq  )*20 + k2 + tq  ];
                a[mi][1] = As2[(m+gq+8)*20 + k2 + tq  ];
                a[mi][2] = As2[(m+gq  )*20 + k2 + tq+4];
                a[mi][3] = As2[(m+gq+8)*20 + k2 + tq+4];
            }
            #pragma unroll
            for (int ni=0;ni<4;ni++){
                int n = wn + ni*8 + gq;
                bfr[ni][0] = Bs[(k2+tq  )*72 + n];
                bfr[ni][1] = Bs[(k2+tq+4)*72 + n];
            }
            #pragma unroll
            for (int mi=0;mi<2;mi++)
                #pragma unroll
                for (int ni=0;ni<4;ni++)
                    mma_f16(acc[mi][ni], a[mi][0],a[mi][1],a[mi][2],a[mi][3], bfr[ni][0],bfr[ni][1]);
        }
        __syncthreads();
    }

    #pragma unroll
    for (int mi=0;mi<2;mi++)
        #pragma unroll
        for (int rr=0;rr<2;rr++){
            const int row = m0 + wm + mi*16 + gq + rr*8;
            #pragma unroll
            for (int ni=0;ni<4;ni++){
                const int col = n0 + wn + ni*8 + 2*tq;
                float2 xv = *(const float2*)&x[(size_t)row*DMODEL + col];
                float2 val = { acc[mi][ni][rr*2+0] + xv.x,
                               acc[mi][ni][rr*2+1] + xv.y };
                *(float2*)&g_h[(size_t)row*DMODEL + col] = val;
            }
        }
}

// ---------------- layernorm ------------------------------------------------------
__global__ __launch_bounds__(256) void ln_kernel(const float* __restrict__ gamma,
                                                 const float* __restrict__ beta,
                                                 float* __restrict__ out)
{
    const int row = blockIdx.x;
    const float* hr = g_h + (size_t)row*DMODEL;
    const int c = threadIdx.x * 4;
    float4 v = *(const float4*)(hr + c);
    float s = v.x+v.y+v.z+v.w;
    s = blockSum(s);
    const float mu = s * (1.f/DMODEL);
    float dx = v.x-mu, dy = v.y-mu, dz = v.z-mu, dw = v.w-mu;
    float sq = dx*dx+dy*dy+dz*dz+dw*dw;
    sq = blockSum(sq);
    const float inv = rsqrtf(sq*(1.f/DMODEL) + 1e-5f);
    float4 gm = *(const float4*)(gamma + c);
    float4 bt = *(const float4*)(beta + c);
    float4 o;
    o.x = dx*inv*gm.x + bt.x;
    o.y = dy*inv*gm.y + bt.y;
    o.z = dz*inv*gm.z + bt.z;
    o.w = dw*inv*gm.w + bt.w;
    *(float4*)(out + (size_t)row*DMODEL + c) = o;
}

// ---------------- launch ----------------------------------------------------------
extern "C" void kernel_launch(void* const* d_in, const int* in_sizes, int n_in,
                              void* d_out, int out_size)
{
    const float* x        = (const float*)d_in[0];
    const float* pos_emb  = (const float*)d_in[1];
    const float* memory   = (const float*)d_in[2];
    const float* ubias    = (const float*)d_in[3];
    const float* vbias    = (const float*)d_in[4];
    const float* Wq       = (const float*)d_in[6];
    const float* Wkv      = (const float*)d_in[7];
    const float* Wrel     = (const float*)d_in[8];
    const float* Wo       = (const float*)d_in[9];
    const float* gamma    = (const float*)d_in[10];
    const float* beta     = (const float*)d_in[11];
    float* out    = (float*)d_out;
    float* out_am = out + (size_t)LQ*BATCH*DMODEL;

    cudaFuncSetAttribute(flash_mma, cudaFuncAttributeMaxDynamicSharedMemorySize, FL_SMEM_BYTES);

    cvt_all<<<5632, 256>>>(x, memory, pos_emb, Wq, Wkv, Wrel, Wo);
    qkvr_mma<<<896, 256>>>();
    flash_mma<<<dim3(8, NG), 256, FL_SMEM_BYTES>>>(ubias, vbias);
    attnmat_kernel<<<dim3(4, LQ), 256>>>(out_am);
    wo_mma<<<dim3(16,16), 256>>>(x);
    ln_kernel<<<LQ*BATCH, 256>>>(gamma, beta, out);
}